// round 1
// baseline (speedup 1.0000x reference)
#include <cuda_runtime.h>

#define TT 200
#define BB 256
#define XPD (TT*BB*1024)

// ---------------- scratch (device globals: allocation-free) ----------------
__device__ float d_char_x[TT*BB*30];        // [t][b][30]
__device__ float d_word_x[TT*BB*128];       // [w][b][128]
__device__ float d_xpre[4][TT*BB*1024];     // per-dir input gate pre-activations
__device__ float d_gates[4][BB*1024];       // per-step gate buffer
__device__ float d_state[4*2*BB*256];       // h,c per dir
__device__ float d_char_h[BB*TT*512];       // [b][t][512]
__device__ float d_word_h[BB*TT*512];       // [b][w][512]
__device__ float d_xcat[BB*TT*712];         // concat(char_map, word_map)
__device__ float d_buf1[BB*TT*512];
__device__ float d_buf2[BB*TT*256];
__device__ float d_logits[BB*TT*12];
__device__ float d_crf[2*BB];               // [0:256) fwd totals, [256:512) real scores

__device__ __forceinline__ float sp_(float x) { return fmaxf(x, 0.f) + log1pf(expf(-fabsf(x))); }
__device__ __forceinline__ float sg_(float x) { return 1.f / (1.f + expf(-x)); }

struct RecPtrs {
    const float* Whh[4];
    const float* Xpre[4];
    float* h[4];
    float* c[4];
    float* gates[4];
    const int* len_char;
    const int* len_word;
    float* outc;
    float* outw;
};

// ---------------- small utility kernels ----------------
__global__ void k_zero(float* p, int n) {
    int i = blockIdx.x * blockDim.x + threadIdx.x;
    if (i < n) p[i] = 0.f;
}

__global__ void k_gather_char(const int* __restrict__ chars, const float* __restrict__ emb,
                              float* __restrict__ out) {
    int i = blockIdx.x * blockDim.x + threadIdx.x;
    if (i >= TT * BB * 30) return;
    int k = i % 30, tb = i / 30;
    int b = tb % BB, t = tb / BB;
    out[i] = emb[chars[b * TT + t] * 30 + k];
}

__global__ void k_transpose_word(const float* __restrict__ words, float* __restrict__ out) {
    int i = blockIdx.x * blockDim.x + threadIdx.x;
    if (i >= TT * BB * 128) return;
    int k = i & 127, wb = i >> 7;
    int b = wb % BB, w = wb / BB;
    out[i] = words[((size_t)b * TT + w) * 128 + k];
}

// ---------------- generic fp32 GEMM: C[m,n] = act(A[M,K] @ W[N,K]^T + bias) ----------------
__global__ void k_gemm(const float* __restrict__ A, const float* __restrict__ W,
                       const float* __restrict__ bias, float* __restrict__ C,
                       int M, int N, int K, int ldc, int act) {
    __shared__ float As[32][65];
    __shared__ float Bs[32][65];
    int tid = threadIdx.x;
    int bm = blockIdx.y * 64, bn = blockIdx.x * 64;
    int lk = tid & 31, lr = tid >> 5;
    int tx = tid & 15, ty = tid >> 4;
    float acc[4][4];
#pragma unroll
    for (int i = 0; i < 4; i++)
#pragma unroll
        for (int j = 0; j < 4; j++) acc[i][j] = 0.f;

    for (int k0 = 0; k0 < K; k0 += 32) {
        int kk = k0 + lk;
#pragma unroll
        for (int r = 0; r < 64; r += 8) {
            int m = bm + lr + r;
            As[lk][lr + r] = (m < M && kk < K) ? A[(size_t)m * K + kk] : 0.f;
            int n = bn + lr + r;
            Bs[lk][lr + r] = (n < N && kk < K) ? W[(size_t)n * K + kk] : 0.f;
        }
        __syncthreads();
#pragma unroll
        for (int k = 0; k < 32; k++) {
            float a[4], bv[4];
#pragma unroll
            for (int i = 0; i < 4; i++) a[i] = As[k][ty * 4 + i];
#pragma unroll
            for (int j = 0; j < 4; j++) bv[j] = Bs[k][tx * 4 + j];
#pragma unroll
            for (int i = 0; i < 4; i++)
#pragma unroll
                for (int j = 0; j < 4; j++) acc[i][j] = fmaf(a[i], bv[j], acc[i][j]);
        }
        __syncthreads();
    }
#pragma unroll
    for (int i = 0; i < 4; i++) {
        int m = bm + ty * 4 + i;
        if (m >= M) continue;
#pragma unroll
        for (int j = 0; j < 4; j++) {
            int n = bn + tx * 4 + j;
            if (n >= N) continue;
            float v = acc[i][j];
            if (bias) v += bias[n];
            if (act) v = sp_(v);
            C[(size_t)m * ldc + n] = v;
        }
    }
}

// ---------------- recurrent step: gates[dir] = Xpre[dir][tr] + h[dir] @ Whh[dir]^T ----------------
__global__ void k_rec_gemm(RecPtrs p, int t) {
    int dir = blockIdx.z;
    const float* __restrict__ A = p.h[dir];     // [256,256]
    const float* __restrict__ W = p.Whh[dir];   // [1024,256]
    int tr = (dir & 1) ? (TT - 1 - t) : t;
    const float* __restrict__ add = p.Xpre[dir] + (size_t)tr * BB * 1024;
    float* __restrict__ C = p.gates[dir];

    __shared__ float As[32][65];
    __shared__ float Bs[32][65];
    int tid = threadIdx.x;
    int bm = blockIdx.y * 64, bn = blockIdx.x * 64;
    int lk = tid & 31, lr = tid >> 5;
    int tx = tid & 15, ty = tid >> 4;
    float acc[4][4];
#pragma unroll
    for (int i = 0; i < 4; i++)
#pragma unroll
        for (int j = 0; j < 4; j++) acc[i][j] = 0.f;

    for (int k0 = 0; k0 < 256; k0 += 32) {
        int kk = k0 + lk;
#pragma unroll
        for (int r = 0; r < 64; r += 8) {
            As[lk][lr + r] = A[(bm + lr + r) * 256 + kk];
            Bs[lk][lr + r] = W[(size_t)(bn + lr + r) * 256 + kk];
        }
        __syncthreads();
#pragma unroll
        for (int k = 0; k < 32; k++) {
            float a[4], bv[4];
#pragma unroll
            for (int i = 0; i < 4; i++) a[i] = As[k][ty * 4 + i];
#pragma unroll
            for (int j = 0; j < 4; j++) bv[j] = Bs[k][tx * 4 + j];
#pragma unroll
            for (int i = 0; i < 4; i++)
#pragma unroll
                for (int j = 0; j < 4; j++) acc[i][j] = fmaf(a[i], bv[j], acc[i][j]);
        }
        __syncthreads();
    }
#pragma unroll
    for (int i = 0; i < 4; i++) {
        int m = bm + ty * 4 + i;
#pragma unroll
        for (int j = 0; j < 4; j++) {
            int n = bn + tx * 4 + j;
            C[m * 1024 + n] = acc[i][j] + add[m * 1024 + n];
        }
    }
}

// ---------------- LSTM cell with packed-sequence mask semantics ----------------
__global__ void k_rec_cell(RecPtrs p, int t) {
    int dir = blockIdx.y;
    int idx = blockIdx.x * blockDim.x + threadIdx.x;  // 0..65535
    int b = idx >> 8, u = idx & 255;
    int tr = (dir & 1) ? (TT - 1 - t) : t;
    int len = (dir < 2 ? p.len_char : p.len_word)[b];
    const float* g = p.gates[dir] + b * 1024;
    float gi = g[u], gf = g[256 + u], gc = g[512 + u], go = g[768 + u];
    float c_old = p.c[dir][idx];
    float cn = sg_(gf) * c_old + sg_(gi) * tanhf(gc);
    float hn = sg_(go) * tanhf(cn);
    bool valid = tr < len;
    if (valid) { p.c[dir][idx] = cn; p.h[dir][idx] = hn; }
    float* outp = (dir < 2) ? p.outc : p.outw;
    int half = (dir & 1) ? 256 : 0;
    outp[((size_t)b * TT + tr) * 512 + half + u] = valid ? hn : 0.f;
}

// ---------------- CRF: real path score (one thread per batch) ----------------
__global__ void k_crf_real(const float* __restrict__ logits, const int* __restrict__ tags,
                           const int* __restrict__ lens, const float* __restrict__ trans,
                           float* __restrict__ rl) {
    int b = threadIdx.x;
    int len = lens[b];
    float s = 0.f;
    int prev = 10;  // START
    for (int t = 0; t < len; t++) {
        int tg = tags[b * TT + t];
        s += logits[((size_t)b * TT + t) * 12 + tg] + trans[prev * 12 + tg];
        prev = tg;
    }
    s += trans[prev * 12 + 11];  // STOP
    rl[b] = s;
}

// ---------------- CRF forward algorithm: one warp per batch ----------------
__global__ void k_crf_fwd(const float* __restrict__ logits, const int* __restrict__ lens,
                          const float* __restrict__ trans, float* __restrict__ tot) {
    __shared__ float st[144];
    int tid = threadIdx.x;
    if (tid < 144) st[tid] = trans[tid];
    __syncthreads();
    int warp = tid >> 5, lane = tid & 31;
    int b = blockIdx.x * 8 + warp;
    int len = lens[b];
    float alpha = 0.f;
    for (int t = 0; t < TT; t++) {
        float lt = (lane < 12) ? logits[((size_t)b * TT + t) * 12 + lane] : 0.f;
        float sc[12];
        float mx = -1e30f;
#pragma unroll
        for (int i = 0; i < 12; i++) {
            float ai = __shfl_sync(0xffffffffu, alpha, i);
            float s = ai + ((lane < 12) ? st[i * 12 + lane] : 0.f);
            sc[i] = s;
            mx = fmaxf(mx, s);
        }
        float sm = 0.f;
#pragma unroll
        for (int i = 0; i < 12; i++) sm += expf(sc[i] - mx);
        float an = mx + logf(sm) + lt;
        if (t < len) alpha = an;
    }
    float v = (lane < 12) ? alpha + st[lane * 12 + 11] : -1e30f;
    float mx = v;
#pragma unroll
    for (int o = 16; o > 0; o >>= 1) mx = fmaxf(mx, __shfl_xor_sync(0xffffffffu, mx, o));
    float e = expf(v - mx);
#pragma unroll
    for (int o = 16; o > 0; o >>= 1) e += __shfl_xor_sync(0xffffffffu, e, o);
    if (lane == 0) tot[b] = mx + logf(e);
}

// ---------------- deterministic final reduce ----------------
__global__ void k_crf_reduce(const float* __restrict__ crf, float* __restrict__ out) {
    __shared__ float s[256];
    int t = threadIdx.x;
    s[t] = crf[t] - crf[256 + t];
    __syncthreads();
    for (int o = 128; o > 0; o >>= 1) {
        if (t < o) s[t] += s[t + o];
        __syncthreads();
    }
    if (t == 0) out[0] = s[0];
}

// ---------------- launch ----------------
extern "C" void kernel_launch(void* const* d_in, const int* in_sizes, int n_in,
                              void* d_out, int out_size) {
    const int*   characters = (const int*)d_in[0];
    const float* words      = (const float*)d_in[1];
    const int*   tags       = (const int*)d_in[2];
    const int*   len_char   = (const int*)d_in[3];
    const int*   len_word   = (const int*)d_in[4];
    const float* char_emb   = (const float*)d_in[5];
    const float* cWihf = (const float*)d_in[6];
    const float* cWhhf = (const float*)d_in[7];
    const float* cbf   = (const float*)d_in[8];
    const float* cWihb = (const float*)d_in[9];
    const float* cWhhb = (const float*)d_in[10];
    const float* cbb   = (const float*)d_in[11];
    const float* clinW = (const float*)d_in[12];
    const float* clinb = (const float*)d_in[13];
    const float* wWihf = (const float*)d_in[14];
    const float* wWhhf = (const float*)d_in[15];
    const float* wbf   = (const float*)d_in[16];
    const float* wWihb = (const float*)d_in[17];
    const float* wWhhb = (const float*)d_in[18];
    const float* wbb   = (const float*)d_in[19];
    const float* wlinW = (const float*)d_in[20];
    const float* wlinb = (const float*)d_in[21];
    const float* l1W   = (const float*)d_in[22];
    const float* l1b   = (const float*)d_in[23];
    const float* l2W   = (const float*)d_in[24];
    const float* l2b   = (const float*)d_in[25];
    const float* tW    = (const float*)d_in[26];
    const float* tb    = (const float*)d_in[27];
    const float* trans = (const float*)d_in[28];
    float* out = (float*)d_out;

    float *char_x, *word_x, *xpre, *gates, *state, *char_h, *word_h, *xcat, *buf1, *buf2, *logits, *crfb;
    cudaGetSymbolAddress((void**)&char_x, d_char_x);
    cudaGetSymbolAddress((void**)&word_x, d_word_x);
    cudaGetSymbolAddress((void**)&xpre,   d_xpre);
    cudaGetSymbolAddress((void**)&gates,  d_gates);
    cudaGetSymbolAddress((void**)&state,  d_state);
    cudaGetSymbolAddress((void**)&char_h, d_char_h);
    cudaGetSymbolAddress((void**)&word_h, d_word_h);
    cudaGetSymbolAddress((void**)&xcat,   d_xcat);
    cudaGetSymbolAddress((void**)&buf1,   d_buf1);
    cudaGetSymbolAddress((void**)&buf2,   d_buf2);
    cudaGetSymbolAddress((void**)&logits, d_logits);
    cudaGetSymbolAddress((void**)&crfb,   d_crf);

    // zero LSTM states
    int nstate = 4 * 2 * BB * 256;
    k_zero<<<(nstate + 255) / 256, 256>>>(state, nstate);

    // stage inputs
    k_gather_char<<<(TT * BB * 30 + 255) / 256, 256>>>(characters, char_emb, char_x);
    k_transpose_word<<<(TT * BB * 128 + 255) / 256, 256>>>(words, word_x);

    int Mbt = BB * TT;  // 51200
    auto grid = [](int M, int N) { return dim3((unsigned)((N + 63) / 64), (unsigned)((M + 63) / 64)); };

    // input projections (time-parallel)
    k_gemm<<<grid(Mbt, 1024), 256>>>(char_x, cWihf, cbf, xpre + 0 * (size_t)XPD, Mbt, 1024, 30, 1024, 0);
    k_gemm<<<grid(Mbt, 1024), 256>>>(char_x, cWihb, cbb, xpre + 1 * (size_t)XPD, Mbt, 1024, 30, 1024, 0);
    k_gemm<<<grid(Mbt, 1024), 256>>>(word_x, wWihf, wbf, xpre + 2 * (size_t)XPD, Mbt, 1024, 128, 1024, 0);
    k_gemm<<<grid(Mbt, 1024), 256>>>(word_x, wWihb, wbb, xpre + 3 * (size_t)XPD, Mbt, 1024, 128, 1024, 0);

    // recurrence: 4 directions fused per step
    RecPtrs rp;
    rp.Whh[0] = cWhhf; rp.Whh[1] = cWhhb; rp.Whh[2] = wWhhf; rp.Whh[3] = wWhhb;
    for (int d = 0; d < 4; d++) {
        rp.Xpre[d]  = xpre + (size_t)d * XPD;
        rp.h[d]     = state + d * 2 * BB * 256;
        rp.c[d]     = rp.h[d] + BB * 256;
        rp.gates[d] = gates + (size_t)d * BB * 1024;
    }
    rp.len_char = len_char;
    rp.len_word = len_word;
    rp.outc = char_h;
    rp.outw = word_h;

    for (int t = 0; t < TT; t++) {
        k_rec_gemm<<<dim3(16, 4, 4), 256>>>(rp, t);
        k_rec_cell<<<dim3(256, 4), 256>>>(rp, t);
    }

    // dense stack (softplus fused); word_map reshape is a contiguous identity
    k_gemm<<<grid(Mbt, 512), 256>>>(char_h, clinW, clinb, xcat,       Mbt, 512, 512, 712, 1);
    k_gemm<<<grid(Mbt, 200), 256>>>(word_h, wlinW, wlinb, xcat + 512, Mbt, 200, 512, 712, 1);
    k_gemm<<<grid(Mbt, 512), 256>>>(xcat, l1W, l1b, buf1,   Mbt, 512, 712, 512, 1);
    k_gemm<<<grid(Mbt, 256), 256>>>(buf1, l2W, l2b, buf2,   Mbt, 256, 512, 256, 1);
    k_gemm<<<grid(Mbt, 12),  256>>>(buf2, tW,  tb,  logits, Mbt, 12,  256, 12,  1);

    // CRF
    k_crf_real<<<1, 256>>>(logits, tags, len_char, trans, crfb + BB);
    k_crf_fwd<<<32, 256>>>(logits, len_char, trans, crfb);
    k_crf_reduce<<<1, 256>>>(crfb, out);
}

// round 2
// speedup vs baseline: 1.1924x; 1.1924x over previous
#include <cuda_runtime.h>

#define TT 200
#define BB 256
#define XPD (TT*BB*1024)
#define NBLK 256

// ---------------- scratch (device globals: allocation-free) ----------------
__device__ float d_char_x[TT*BB*30];        // [t][b][30]
__device__ float d_word_x[TT*BB*128];       // [w][b][128]
__device__ float d_xpre[4][TT*BB*1024];     // per-dir input preact, gate-interleaved cols
__device__ float d_whhp[4][1024*256];       // permuted (unit-interleaved) Whh
__device__ float d_cihp[2][1024*30];        // permuted char Wih
__device__ float d_wihp[2][1024*128];       // permuted word Wih
__device__ float d_bp[4][1024];             // permuted biases
__device__ float d_hbuf[4*2*BB*256];        // ping-pong h per dir
__device__ float d_char_h[BB*TT*512];       // [b][t][512]
__device__ float d_word_h[BB*TT*512];       // [b][w][512]
__device__ float d_xcat[BB*TT*712];         // concat(char_map, word_map)
__device__ float d_buf1[BB*TT*512];
__device__ float d_buf2[BB*TT*256];
__device__ float d_logits[BB*TT*12];
__device__ float d_crf[2*BB];

__device__ unsigned g_arr;
__device__ volatile unsigned g_gen;

__device__ __forceinline__ float sp_(float x) { return fmaxf(x, 0.f) + log1pf(expf(-fabsf(x))); }
__device__ __forceinline__ float sg_(float x) { return 1.f / (1.f + expf(-x)); }

// ---------------- small utility kernels ----------------
__global__ void k_init(float* hbuf) {
    int i = blockIdx.x * blockDim.x + threadIdx.x;
    if (i == 0) { g_arr = 0; g_gen = 0; }
    if (i < 4 * 2 * BB * 256) hbuf[i] = 0.f;
}

__global__ void k_gather_char(const int* __restrict__ chars, const float* __restrict__ emb,
                              float* __restrict__ out) {
    int i = blockIdx.x * blockDim.x + threadIdx.x;
    if (i >= TT * BB * 30) return;
    int k = i % 30, tb = i / 30;
    int b = tb % BB, t = tb / BB;
    out[i] = emb[chars[b * TT + t] * 30 + k];
}

__global__ void k_transpose_word(const float* __restrict__ words, float* __restrict__ out) {
    int i = blockIdx.x * blockDim.x + threadIdx.x;
    if (i >= TT * BB * 128) return;
    int k = i & 127, wb = i >> 7;
    int b = wb % BB, w = wb / BB;
    out[i] = words[((size_t)b * TT + w) * 128 + k];
}

// permute gate-major rows (g*256+u) -> unit-interleaved rows (u*4+g)
__global__ void k_perm_w(const float* __restrict__ src, float* __restrict__ dst, int K) {
    int i = blockIdx.x * blockDim.x + threadIdx.x;
    if (i >= 1024 * K) return;
    int k = i % K, r = i / K;
    int u = r >> 2, g = r & 3;
    dst[(size_t)r * K + k] = src[(size_t)(g * 256 + u) * K + k];
}

__global__ void k_perm_b(const float* __restrict__ src, float* __restrict__ dst) {
    int r = blockIdx.x * blockDim.x + threadIdx.x;
    if (r >= 1024) return;
    int u = r >> 2, g = r & 3;
    dst[r] = src[g * 256 + u];
}

// ---------------- generic fp32 GEMM: C[m,n] = act(A[M,K] @ W[N,K]^T + bias) ----------------
__global__ void k_gemm(const float* __restrict__ A, const float* __restrict__ W,
                       const float* __restrict__ bias, float* __restrict__ C,
                       int M, int N, int K, int ldc, int act) {
    __shared__ float As[32][65];
    __shared__ float Bs[32][65];
    int tid = threadIdx.x;
    int bm = blockIdx.y * 64, bn = blockIdx.x * 64;
    int lk = tid & 31, lr = tid >> 5;
    int tx = tid & 15, ty = tid >> 4;
    float acc[4][4];
#pragma unroll
    for (int i = 0; i < 4; i++)
#pragma unroll
        for (int j = 0; j < 4; j++) acc[i][j] = 0.f;

    for (int k0 = 0; k0 < K; k0 += 32) {
        int kk = k0 + lk;
#pragma unroll
        for (int r = 0; r < 64; r += 8) {
            int m = bm + lr + r;
            As[lk][lr + r] = (m < M && kk < K) ? A[(size_t)m * K + kk] : 0.f;
            int n = bn + lr + r;
            Bs[lk][lr + r] = (n < N && kk < K) ? W[(size_t)n * K + kk] : 0.f;
        }
        __syncthreads();
#pragma unroll
        for (int k = 0; k < 32; k++) {
            float a[4], bv[4];
#pragma unroll
            for (int i = 0; i < 4; i++) a[i] = As[k][ty * 4 + i];
#pragma unroll
            for (int j = 0; j < 4; j++) bv[j] = Bs[k][tx * 4 + j];
#pragma unroll
            for (int i = 0; i < 4; i++)
#pragma unroll
                for (int j = 0; j < 4; j++) acc[i][j] = fmaf(a[i], bv[j], acc[i][j]);
        }
        __syncthreads();
    }
#pragma unroll
    for (int i = 0; i < 4; i++) {
        int m = bm + ty * 4 + i;
        if (m >= M) continue;
#pragma unroll
        for (int j = 0; j < 4; j++) {
            int n = bn + tx * 4 + j;
            if (n >= N) continue;
            float v = acc[i][j];
            if (bias) v += bias[n];
            if (act) v = sp_(v);
            C[(size_t)m * ldc + n] = v;
        }
    }
}

// ---------------- persistent recurrence ----------------
struct RP {
    const float* whhp;      // [4][1024*256] interleaved rows
    const float* xpre;      // [4][XPD] interleaved cols
    float* hbuf;            // [4][2][256*256]
    const int* len_char;
    const int* len_word;
    float* outc;
    float* outw;
};

__device__ __forceinline__ void grid_bar(unsigned target) {
    __threadfence();
    __syncthreads();
    if (threadIdx.x == 0) {
        if (atomicAdd(&g_arr, 1u) == NBLK - 1) {
            g_arr = 0;
            __threadfence();
            g_gen = target;
        } else {
            while (g_gen < target) __nanosleep(64);
        }
    }
    __syncthreads();
}

__global__ void __launch_bounds__(256, 2) k_rec_persist(RP p) {
    extern __shared__ float sm[];
    float* Ws = sm;                 // [256][68]
    float* As = sm + 256 * 68;      // [32][68]

    int bx = blockIdx.x;
    int dir = bx >> 6, mb = (bx >> 4) & 3, nb = bx & 15;
    int tid = threadIdx.x;
    int tx = tid & 15, ty = tid >> 4;
    unsigned lk = tid & 31, lr = tid >> 5;

    const float* W = p.whhp + (size_t)dir * 1024 * 256;
    // load W tile [nb*64 .. +64) rows, transposed into Ws[k][n]
    for (int idx = tid; idx < 64 * 256; idx += 256) {
        int k = idx & 255, n = idx >> 8;
        Ws[k * 68 + n] = W[(size_t)(nb * 64 + n) * 256 + k];
    }

    float hreg[4], creg[4];
#pragma unroll
    for (int i = 0; i < 4; i++) { hreg[i] = 0.f; creg[i] = 0.f; }

    int u = nb * 16 + tx;           // unit owned by this thread
    int bm = mb * 64;
    const int* lens = (dir < 2) ? p.len_char : p.len_word;
    int lenv[4];
#pragma unroll
    for (int i = 0; i < 4; i++) lenv[i] = lens[bm + ty * 4 + i];

    float* hb0 = p.hbuf + (size_t)dir * 2 * 65536;
    float* hb1 = hb0 + 65536;
    const float* xp = p.xpre + (size_t)dir * XPD;
    float* outp = (dir < 2) ? p.outc : p.outw;
    int half = (dir & 1) ? 256 : 0;

    __syncthreads();

    for (int t = 0; t < TT; t++) {
        int tr = (dir & 1) ? (TT - 1 - t) : t;
        const float* h = (t & 1) ? hb1 : hb0;
        float* hn_buf = (t & 1) ? hb0 : hb1;

        float acc[4][4];
#pragma unroll
        for (int i = 0; i < 4; i++)
#pragma unroll
            for (int j = 0; j < 4; j++) acc[i][j] = 0.f;

        for (int k0 = 0; k0 < 256; k0 += 32) {
            __syncthreads();
#pragma unroll
            for (int r = 0; r < 64; r += 8)
                As[lk * 68 + lr + r] = __ldcg(&h[(bm + lr + r) * 256 + k0 + lk]);
            __syncthreads();
#pragma unroll
            for (int k = 0; k < 32; k++) {
                float4 av = *(const float4*)&As[k * 68 + ty * 4];
                float4 bv = *(const float4*)&Ws[(k0 + k) * 68 + tx * 4];
                float a[4] = {av.x, av.y, av.z, av.w};
                float b[4] = {bv.x, bv.y, bv.z, bv.w};
#pragma unroll
                for (int i = 0; i < 4; i++)
#pragma unroll
                    for (int j = 0; j < 4; j++) acc[i][j] = fmaf(a[i], b[j], acc[i][j]);
            }
        }

        const float* xrow = xp + (size_t)tr * BB * 1024;
#pragma unroll
        for (int i = 0; i < 4; i++) {
            int b = bm + ty * 4 + i;
            float4 x = __ldg((const float4*)&xrow[b * 1024 + nb * 64 + tx * 4]);
            float gi = acc[i][0] + x.x;
            float gf = acc[i][1] + x.y;
            float gc = acc[i][2] + x.z;
            float go = acc[i][3] + x.w;
            float cn = sg_(gf) * creg[i] + sg_(gi) * tanhf(gc);
            float hv = sg_(go) * tanhf(cn);
            bool valid = tr < lenv[i];
            if (valid) { creg[i] = cn; hreg[i] = hv; }
            outp[((size_t)b * TT + tr) * 512 + half + u] = valid ? hv : 0.f;
            hn_buf[b * 256 + u] = hreg[i];
        }

        grid_bar((unsigned)(t + 1));
    }
}

// ---------------- CRF: real path score ----------------
__global__ void k_crf_real(const float* __restrict__ logits, const int* __restrict__ tags,
                           const int* __restrict__ lens, const float* __restrict__ trans,
                           float* __restrict__ rl) {
    int b = threadIdx.x;
    int len = lens[b];
    float s = 0.f;
    int prev = 10;
    for (int t = 0; t < len; t++) {
        int tg = tags[b * TT + t];
        s += logits[((size_t)b * TT + t) * 12 + tg] + trans[prev * 12 + tg];
        prev = tg;
    }
    s += trans[prev * 12 + 11];
    rl[b] = s;
}

// ---------------- CRF forward: one warp per batch ----------------
__global__ void k_crf_fwd(const float* __restrict__ logits, const int* __restrict__ lens,
                          const float* __restrict__ trans, float* __restrict__ tot) {
    __shared__ float st[144];
    int tid = threadIdx.x;
    if (tid < 144) st[tid] = trans[tid];
    __syncthreads();
    int warp = tid >> 5, lane = tid & 31;
    int b = blockIdx.x * 8 + warp;
    int len = lens[b];
    float alpha = 0.f;
    for (int t = 0; t < TT; t++) {
        float lt = (lane < 12) ? logits[((size_t)b * TT + t) * 12 + lane] : 0.f;
        float sc[12];
        float mx = -1e30f;
#pragma unroll
        for (int i = 0; i < 12; i++) {
            float ai = __shfl_sync(0xffffffffu, alpha, i);
            float s = ai + ((lane < 12) ? st[i * 12 + lane] : 0.f);
            sc[i] = s;
            mx = fmaxf(mx, s);
        }
        float sm = 0.f;
#pragma unroll
        for (int i = 0; i < 12; i++) sm += expf(sc[i] - mx);
        float an = mx + logf(sm) + lt;
        if (t < len) alpha = an;
    }
    float v = (lane < 12) ? alpha + st[lane * 12 + 11] : -1e30f;
    float mx = v;
#pragma unroll
    for (int o = 16; o > 0; o >>= 1) mx = fmaxf(mx, __shfl_xor_sync(0xffffffffu, mx, o));
    float e = expf(v - mx);
#pragma unroll
    for (int o = 16; o > 0; o >>= 1) e += __shfl_xor_sync(0xffffffffu, e, o);
    if (lane == 0) tot[b] = mx + logf(e);
}

__global__ void k_crf_reduce(const float* __restrict__ crf, float* __restrict__ out) {
    __shared__ float s[256];
    int t = threadIdx.x;
    s[t] = crf[t] - crf[256 + t];
    __syncthreads();
    for (int o = 128; o > 0; o >>= 1) {
        if (t < o) s[t] += s[t + o];
        __syncthreads();
    }
    if (t == 0) out[0] = s[0];
}

// ---------------- launch ----------------
extern "C" void kernel_launch(void* const* d_in, const int* in_sizes, int n_in,
                              void* d_out, int out_size) {
    const int*   characters = (const int*)d_in[0];
    const float* words      = (const float*)d_in[1];
    const int*   tags       = (const int*)d_in[2];
    const int*   len_char   = (const int*)d_in[3];
    const int*   len_word   = (const int*)d_in[4];
    const float* char_emb   = (const float*)d_in[5];
    const float* cWihf = (const float*)d_in[6];
    const float* cWhhf = (const float*)d_in[7];
    const float* cbf   = (const float*)d_in[8];
    const float* cWihb = (const float*)d_in[9];
    const float* cWhhb = (const float*)d_in[10];
    const float* cbb   = (const float*)d_in[11];
    const float* clinW = (const float*)d_in[12];
    const float* clinb = (const float*)d_in[13];
    const float* wWihf = (const float*)d_in[14];
    const float* wWhhf = (const float*)d_in[15];
    const float* wbf   = (const float*)d_in[16];
    const float* wWihb = (const float*)d_in[17];
    const float* wWhhb = (const float*)d_in[18];
    const float* wbb   = (const float*)d_in[19];
    const float* wlinW = (const float*)d_in[20];
    const float* wlinb = (const float*)d_in[21];
    const float* l1W   = (const float*)d_in[22];
    const float* l1b   = (const float*)d_in[23];
    const float* l2W   = (const float*)d_in[24];
    const float* l2b   = (const float*)d_in[25];
    const float* tW    = (const float*)d_in[26];
    const float* tb    = (const float*)d_in[27];
    const float* trans = (const float*)d_in[28];
    float* out = (float*)d_out;

    float *char_x, *word_x, *xpre, *whhp, *cihp, *wihp, *bp, *hbuf;
    float *char_h, *word_h, *xcat, *buf1, *buf2, *logits, *crfb;
    cudaGetSymbolAddress((void**)&char_x, d_char_x);
    cudaGetSymbolAddress((void**)&word_x, d_word_x);
    cudaGetSymbolAddress((void**)&xpre,   d_xpre);
    cudaGetSymbolAddress((void**)&whhp,   d_whhp);
    cudaGetSymbolAddress((void**)&cihp,   d_cihp);
    cudaGetSymbolAddress((void**)&wihp,   d_wihp);
    cudaGetSymbolAddress((void**)&bp,     d_bp);
    cudaGetSymbolAddress((void**)&hbuf,   d_hbuf);
    cudaGetSymbolAddress((void**)&char_h, d_char_h);
    cudaGetSymbolAddress((void**)&word_h, d_word_h);
    cudaGetSymbolAddress((void**)&xcat,   d_xcat);
    cudaGetSymbolAddress((void**)&buf1,   d_buf1);
    cudaGetSymbolAddress((void**)&buf2,   d_buf2);
    cudaGetSymbolAddress((void**)&logits, d_logits);
    cudaGetSymbolAddress((void**)&crfb,   d_crf);

    // allow large dynamic smem for the persistent kernel (idempotent host call)
    const int REC_SMEM = (256 * 68 + 32 * 68) * 4;  // 78336 B
    cudaFuncSetAttribute(k_rec_persist, cudaFuncAttributeMaxDynamicSharedMemorySize, REC_SMEM);

    // init barrier + h buffers
    k_init<<<(4 * 2 * BB * 256 + 255) / 256, 256>>>(hbuf);

    // permute weights to unit-interleaved gate order
    k_perm_w<<<(1024 * 256 + 255) / 256, 256>>>(cWhhf, whhp + 0 * 1024 * 256, 256);
    k_perm_w<<<(1024 * 256 + 255) / 256, 256>>>(cWhhb, whhp + 1 * 1024 * 256, 256);
    k_perm_w<<<(1024 * 256 + 255) / 256, 256>>>(wWhhf, whhp + 2 * 1024 * 256, 256);
    k_perm_w<<<(1024 * 256 + 255) / 256, 256>>>(wWhhb, whhp + 3 * 1024 * 256, 256);
    k_perm_w<<<(1024 * 30 + 255) / 256, 256>>>(cWihf, cihp + 0 * 1024 * 30, 30);
    k_perm_w<<<(1024 * 30 + 255) / 256, 256>>>(cWihb, cihp + 1 * 1024 * 30, 30);
    k_perm_w<<<(1024 * 128 + 255) / 256, 256>>>(wWihf, wihp + 0 * 1024 * 128, 128);
    k_perm_w<<<(1024 * 128 + 255) / 256, 256>>>(wWihb, wihp + 1 * 1024 * 128, 128);
    k_perm_b<<<4, 256>>>(cbf, bp + 0 * 1024);
    k_perm_b<<<4, 256>>>(cbb, bp + 1 * 1024);
    k_perm_b<<<4, 256>>>(wbf, bp + 2 * 1024);
    k_perm_b<<<4, 256>>>(wbb, bp + 3 * 1024);

    // stage inputs
    k_gather_char<<<(TT * BB * 30 + 255) / 256, 256>>>(characters, char_emb, char_x);
    k_transpose_word<<<(TT * BB * 128 + 255) / 256, 256>>>(words, word_x);

    int Mbt = BB * TT;  // 51200
    auto grid = [](int M, int N) { return dim3((unsigned)((N + 63) / 64), (unsigned)((M + 63) / 64)); };

    // input projections (time-parallel) with permuted weights -> interleaved xpre
    k_gemm<<<grid(Mbt, 1024), 256>>>(char_x, cihp + 0 * 1024 * 30,  bp + 0 * 1024, xpre + 0 * (size_t)XPD, Mbt, 1024, 30, 1024, 0);
    k_gemm<<<grid(Mbt, 1024), 256>>>(char_x, cihp + 1 * 1024 * 30,  bp + 1 * 1024, xpre + 1 * (size_t)XPD, Mbt, 1024, 30, 1024, 0);
    k_gemm<<<grid(Mbt, 1024), 256>>>(word_x, wihp + 0 * 1024 * 128, bp + 2 * 1024, xpre + 2 * (size_t)XPD, Mbt, 1024, 128, 1024, 0);
    k_gemm<<<grid(Mbt, 1024), 256>>>(word_x, wihp + 1 * 1024 * 128, bp + 3 * 1024, xpre + 3 * (size_t)XPD, Mbt, 1024, 128, 1024, 0);

    // persistent recurrence: 4 dirs x 200 steps, one launch
    RP rp;
    rp.whhp = whhp;
    rp.xpre = xpre;
    rp.hbuf = hbuf;
    rp.len_char = len_char;
    rp.len_word = len_word;
    rp.outc = char_h;
    rp.outw = word_h;
    k_rec_persist<<<NBLK, 256, REC_SMEM>>>(rp);

    // dense stack (softplus fused); word_map reshape is a contiguous identity
    k_gemm<<<grid(Mbt, 512), 256>>>(char_h, clinW, clinb, xcat,       Mbt, 512, 512, 712, 1);
    k_gemm<<<grid(Mbt, 200), 256>>>(word_h, wlinW, wlinb, xcat + 512, Mbt, 200, 512, 712, 1);
    k_gemm<<<grid(Mbt, 512), 256>>>(xcat, l1W, l1b, buf1,   Mbt, 512, 712, 512, 1);
    k_gemm<<<grid(Mbt, 256), 256>>>(buf1, l2W, l2b, buf2,   Mbt, 256, 512, 256, 1);
    k_gemm<<<grid(Mbt, 12),  256>>>(buf2, tW,  tb,  logits, Mbt, 12,  256, 12,  1);

    // CRF
    k_crf_real<<<1, 256>>>(logits, tags, len_char, trans, crfb + BB);
    k_crf_fwd<<<32, 256>>>(logits, len_char, trans, crfb);
    k_crf_reduce<<<1, 256>>>(crfb, out);
}

// round 3
// speedup vs baseline: 1.9401x; 1.6270x over previous
#include <cuda_runtime.h>

#define TT 200
#define BB 256
#define XPD (TT*BB*1024)
#define NBLK 256

// ---------------- scratch (device globals: allocation-free) ----------------
__device__ float d_char_x[TT*BB*30];        // [t][b][30]
__device__ float d_word_x[TT*BB*128];       // [w][b][128]
__device__ float d_xpre[4][TT*BB*1024];     // per-dir input preact, gate-interleaved cols
__device__ float d_whhp[4][1024*256];       // permuted (unit-interleaved) Whh
__device__ float d_cihp[2][1024*30];        // permuted char Wih
__device__ float d_wihp[2][1024*128];       // permuted word Wih
__device__ float d_bp[4][1024];             // permuted biases
__device__ float d_hbuf[4*2*BB*256];        // ping-pong h per dir
__device__ float d_char_h[BB*TT*512];       // [b][t][512]
__device__ float d_word_h[BB*TT*512];       // [b][w][512]
__device__ float d_xcat[BB*TT*712];         // concat(char_map, word_map)
__device__ float d_buf1[BB*TT*512];
__device__ float d_buf2[BB*TT*256];
__device__ float d_logits[BB*TT*12];
__device__ float d_crf[2*BB];

__device__ unsigned g_arr;
__device__ volatile unsigned g_gen;

__device__ __forceinline__ float sp_(float x) { return fmaxf(x, 0.f) + log1pf(expf(-fabsf(x))); }
__device__ __forceinline__ float sg_(float x) { return 1.f / (1.f + expf(-x)); }

__device__ __forceinline__ unsigned f2tf(float f) {
    unsigned u;
    asm("cvt.rna.tf32.f32 %0, %1;" : "=r"(u) : "f"(f));
    return u;
}

__device__ __forceinline__ void mma_tf32(float* d, const unsigned* a, const unsigned* b) {
    asm volatile(
        "mma.sync.aligned.m16n8k8.row.col.f32.tf32.tf32.f32 "
        "{%0,%1,%2,%3}, {%4,%5,%6,%7}, {%8,%9}, {%0,%1,%2,%3};\n"
        : "+f"(d[0]), "+f"(d[1]), "+f"(d[2]), "+f"(d[3])
        : "r"(a[0]), "r"(a[1]), "r"(a[2]), "r"(a[3]), "r"(b[0]), "r"(b[1]));
}

// ---------------- small utility kernels ----------------
__global__ void k_init(float* hbuf) {
    int i = blockIdx.x * blockDim.x + threadIdx.x;
    if (i == 0) { g_arr = 0; g_gen = 0; }
    if (i < 4 * 2 * BB * 256) hbuf[i] = 0.f;
}

__global__ void k_gather_char(const int* __restrict__ chars, const float* __restrict__ emb,
                              float* __restrict__ out) {
    int i = blockIdx.x * blockDim.x + threadIdx.x;
    if (i >= TT * BB * 30) return;
    int k = i % 30, tb = i / 30;
    int b = tb % BB, t = tb / BB;
    out[i] = emb[chars[b * TT + t] * 30 + k];
}

__global__ void k_transpose_word(const float* __restrict__ words, float* __restrict__ out) {
    int i = blockIdx.x * blockDim.x + threadIdx.x;
    if (i >= TT * BB * 128) return;
    int k = i & 127, wb = i >> 7;
    int b = wb % BB, w = wb / BB;
    out[i] = words[((size_t)b * TT + w) * 128 + k];
}

// permute gate-major rows (g*256+u) -> unit-interleaved rows (u*4+g)
__global__ void k_perm_w(const float* __restrict__ src, float* __restrict__ dst, int K) {
    int i = blockIdx.x * blockDim.x + threadIdx.x;
    if (i >= 1024 * K) return;
    int k = i % K, r = i / K;
    int u = r >> 2, g = r & 3;
    dst[(size_t)r * K + k] = src[(size_t)(g * 256 + u) * K + k];
}

__global__ void k_perm_b(const float* __restrict__ src, float* __restrict__ dst) {
    int r = blockIdx.x * blockDim.x + threadIdx.x;
    if (r >= 1024) return;
    int u = r >> 2, g = r & 3;
    dst[r] = src[g * 256 + u];
}

// ---------------- TF32 tensor-core GEMM: C = act(A[M,K] @ W[N,K]^T + bias) ----------------
// block tile 128(M) x 64(N), K-chunk 32; 8 warps each 32x32 via m16n8k8 mma.
__global__ void __launch_bounds__(256) k_gemm_tc(
        const float* __restrict__ A, const float* __restrict__ W,
        const float* __restrict__ bias, float* __restrict__ C,
        int M, int N, int K, int ldc, int act) {
    __shared__ unsigned As[128][36];
    __shared__ unsigned Bs[64][36];

    int tid = threadIdx.x;
    int bm = blockIdx.y * 128, bn = blockIdx.x * 64;
    int wid = tid >> 5, lane = tid & 31;
    int wm = (wid & 3) * 32, wn = (wid >> 2) * 32;
    int gid = lane >> 2, tig = lane & 3;
    bool k4 = (K & 3) == 0;

    float acc[2][4][4];
#pragma unroll
    for (int i = 0; i < 2; i++)
#pragma unroll
        for (int j = 0; j < 4; j++)
#pragma unroll
            for (int v = 0; v < 4; v++) acc[i][j][v] = 0.f;

    float ra[16], rb[8];

    auto load_stage = [&](int k0) {
#pragma unroll
        for (int j = 0; j < 4; j++) {
            int q = tid + 256 * j;
            int r = q >> 3, c = (q & 7) * 4;
            const float* src = A + (size_t)(bm + r) * K + k0 + c;
            float4 v;
            if (k4 && k0 + c + 3 < K) v = *(const float4*)src;
            else {
                v.x = (k0 + c + 0 < K) ? src[0] : 0.f;
                v.y = (k0 + c + 1 < K) ? src[1] : 0.f;
                v.z = (k0 + c + 2 < K) ? src[2] : 0.f;
                v.w = (k0 + c + 3 < K) ? src[3] : 0.f;
            }
            ra[j * 4 + 0] = v.x; ra[j * 4 + 1] = v.y; ra[j * 4 + 2] = v.z; ra[j * 4 + 3] = v.w;
        }
#pragma unroll
        for (int j = 0; j < 2; j++) {
            int q = tid + 256 * j;
            int r = q >> 3, c = (q & 7) * 4;
            float4 v = make_float4(0.f, 0.f, 0.f, 0.f);
            if (bn + r < N) {
                const float* src = W + (size_t)(bn + r) * K + k0 + c;
                if (k4 && k0 + c + 3 < K) v = *(const float4*)src;
                else {
                    v.x = (k0 + c + 0 < K) ? src[0] : 0.f;
                    v.y = (k0 + c + 1 < K) ? src[1] : 0.f;
                    v.z = (k0 + c + 2 < K) ? src[2] : 0.f;
                    v.w = (k0 + c + 3 < K) ? src[3] : 0.f;
                }
            }
            rb[j * 4 + 0] = v.x; rb[j * 4 + 1] = v.y; rb[j * 4 + 2] = v.z; rb[j * 4 + 3] = v.w;
        }
    };

    load_stage(0);
    for (int k0 = 0; k0 < K; k0 += 32) {
        __syncthreads();
#pragma unroll
        for (int j = 0; j < 4; j++) {
            int q = tid + 256 * j;
            int r = q >> 3, c = (q & 7) * 4;
            *(uint4*)&As[r][c] = make_uint4(f2tf(ra[j*4+0]), f2tf(ra[j*4+1]), f2tf(ra[j*4+2]), f2tf(ra[j*4+3]));
        }
#pragma unroll
        for (int j = 0; j < 2; j++) {
            int q = tid + 256 * j;
            int r = q >> 3, c = (q & 7) * 4;
            *(uint4*)&Bs[r][c] = make_uint4(f2tf(rb[j*4+0]), f2tf(rb[j*4+1]), f2tf(rb[j*4+2]), f2tf(rb[j*4+3]));
        }
        __syncthreads();
        if (k0 + 32 < K) load_stage(k0 + 32);

#pragma unroll
        for (int ks = 0; ks < 4; ks++) {
            int kk = ks * 8;
            unsigned af[2][4], bf[4][2];
#pragma unroll
            for (int im = 0; im < 2; im++) {
                int rm = wm + im * 16;
                af[im][0] = As[rm + gid][kk + tig];
                af[im][1] = As[rm + gid + 8][kk + tig];
                af[im][2] = As[rm + gid][kk + tig + 4];
                af[im][3] = As[rm + gid + 8][kk + tig + 4];
            }
#pragma unroll
            for (int jn = 0; jn < 4; jn++) {
                int cn = wn + jn * 8;
                bf[jn][0] = Bs[cn + gid][kk + tig];
                bf[jn][1] = Bs[cn + gid][kk + tig + 4];
            }
#pragma unroll
            for (int im = 0; im < 2; im++)
#pragma unroll
                for (int jn = 0; jn < 4; jn++)
                    mma_tf32(acc[im][jn], af[im], bf[jn]);
        }
    }

    // epilogue
#pragma unroll
    for (int im = 0; im < 2; im++) {
#pragma unroll
        for (int jn = 0; jn < 4; jn++) {
            int row0 = bm + wm + im * 16 + gid;
            int col0 = bn + wn + jn * 8 + tig * 2;
#pragma unroll
            for (int half = 0; half < 2; half++) {
                int row = row0 + half * 8;
#pragma unroll
                for (int cc = 0; cc < 2; cc++) {
                    int col = col0 + cc;
                    if (col >= N) continue;
                    float v = acc[im][jn][half * 2 + cc];
                    if (bias) v += bias[col];
                    if (act) v = sp_(v);
                    C[(size_t)row * ldc + col] = v;
                }
            }
        }
    }
}

// ---------------- persistent recurrence ----------------
struct RP {
    const float* whhp;      // [4][1024*256] interleaved rows
    const float* xpre;      // [4][XPD] interleaved cols
    float* hbuf;            // [4][2][256*256]
    const int* len_char;
    const int* len_word;
    float* outc;
    float* outw;
};

__device__ __forceinline__ void grid_bar(unsigned target) {
    __threadfence();
    __syncthreads();
    if (threadIdx.x == 0) {
        if (atomicAdd(&g_arr, 1u) == NBLK - 1) {
            g_arr = 0;
            __threadfence();
            g_gen = target;
        } else {
            while (g_gen < target) __nanosleep(64);
        }
    }
    __syncthreads();
}

__global__ void __launch_bounds__(256, 2) k_rec_persist(RP p) {
    extern __shared__ float sm[];
    float* Ws = sm;                 // [256][68]
    float* As = sm + 256 * 68;      // [32][68]

    int bx = blockIdx.x;
    int dir = bx >> 6, mb = (bx >> 4) & 3, nb = bx & 15;
    int tid = threadIdx.x;
    int tx = tid & 15, ty = tid >> 4;
    unsigned lk = tid & 31, lr = tid >> 5;

    const float* W = p.whhp + (size_t)dir * 1024 * 256;
    for (int idx = tid; idx < 64 * 256; idx += 256) {
        int k = idx & 255, n = idx >> 8;
        Ws[k * 68 + n] = W[(size_t)(nb * 64 + n) * 256 + k];
    }

    float hreg[4], creg[4];
#pragma unroll
    for (int i = 0; i < 4; i++) { hreg[i] = 0.f; creg[i] = 0.f; }

    int u = nb * 16 + tx;
    int bm = mb * 64;
    const int* lens = (dir < 2) ? p.len_char : p.len_word;
    int lenv[4];
#pragma unroll
    for (int i = 0; i < 4; i++) lenv[i] = lens[bm + ty * 4 + i];

    float* hb0 = p.hbuf + (size_t)dir * 2 * 65536;
    float* hb1 = hb0 + 65536;
    const float* xp = p.xpre + (size_t)dir * XPD;
    float* outp = (dir < 2) ? p.outc : p.outw;
    int half = (dir & 1) ? 256 : 0;

    __syncthreads();

    for (int t = 0; t < TT; t++) {
        int tr = (dir & 1) ? (TT - 1 - t) : t;
        const float* h = (t & 1) ? hb1 : hb0;
        float* hn_buf = (t & 1) ? hb0 : hb1;

        float acc[4][4];
#pragma unroll
        for (int i = 0; i < 4; i++)
#pragma unroll
            for (int j = 0; j < 4; j++) acc[i][j] = 0.f;

        for (int k0 = 0; k0 < 256; k0 += 32) {
            __syncthreads();
#pragma unroll
            for (int r = 0; r < 64; r += 8)
                As[lk * 68 + lr + r] = __ldcg(&h[(bm + lr + r) * 256 + k0 + lk]);
            __syncthreads();
#pragma unroll
            for (int k = 0; k < 32; k++) {
                float4 av = *(const float4*)&As[k * 68 + ty * 4];
                float4 bv = *(const float4*)&Ws[(k0 + k) * 68 + tx * 4];
                float a[4] = {av.x, av.y, av.z, av.w};
                float b[4] = {bv.x, bv.y, bv.z, bv.w};
#pragma unroll
                for (int i = 0; i < 4; i++)
#pragma unroll
                    for (int j = 0; j < 4; j++) acc[i][j] = fmaf(a[i], b[j], acc[i][j]);
            }
        }

        const float* xrow = xp + (size_t)tr * BB * 1024;
#pragma unroll
        for (int i = 0; i < 4; i++) {
            int b = bm + ty * 4 + i;
            float4 x = __ldg((const float4*)&xrow[b * 1024 + nb * 64 + tx * 4]);
            float gi = acc[i][0] + x.x;
            float gf = acc[i][1] + x.y;
            float gc = acc[i][2] + x.z;
            float go = acc[i][3] + x.w;
            float cn = sg_(gf) * creg[i] + sg_(gi) * tanhf(gc);
            float hv = sg_(go) * tanhf(cn);
            bool valid = tr < lenv[i];
            if (valid) { creg[i] = cn; hreg[i] = hv; }
            outp[((size_t)b * TT + tr) * 512 + half + u] = valid ? hv : 0.f;
            hn_buf[b * 256 + u] = hreg[i];
        }

        grid_bar((unsigned)(t + 1));
    }
}

// ---------------- CRF: real path score ----------------
__global__ void k_crf_real(const float* __restrict__ logits, const int* __restrict__ tags,
                           const int* __restrict__ lens, const float* __restrict__ trans,
                           float* __restrict__ rl) {
    int b = threadIdx.x;
    int len = lens[b];
    float s = 0.f;
    int prev = 10;
    for (int t = 0; t < len; t++) {
        int tg = tags[b * TT + t];
        s += logits[((size_t)b * TT + t) * 12 + tg] + trans[prev * 12 + tg];
        prev = tg;
    }
    s += trans[prev * 12 + 11];
    rl[b] = s;
}

// ---------------- CRF forward: one warp per batch ----------------
__global__ void k_crf_fwd(const float* __restrict__ logits, const int* __restrict__ lens,
                          const float* __restrict__ trans, float* __restrict__ tot) {
    __shared__ float st[144];
    int tid = threadIdx.x;
    if (tid < 144) st[tid] = trans[tid];
    __syncthreads();
    int warp = tid >> 5, lane = tid & 31;
    int b = blockIdx.x * 8 + warp;
    int len = lens[b];
    float alpha = 0.f;
    for (int t = 0; t < TT; t++) {
        float lt = (lane < 12) ? logits[((size_t)b * TT + t) * 12 + lane] : 0.f;
        float sc[12];
        float mx = -1e30f;
#pragma unroll
        for (int i = 0; i < 12; i++) {
            float ai = __shfl_sync(0xffffffffu, alpha, i);
            float s = ai + ((lane < 12) ? st[i * 12 + lane] : 0.f);
            sc[i] = s;
            mx = fmaxf(mx, s);
        }
        float sm = 0.f;
#pragma unroll
        for (int i = 0; i < 12; i++) sm += expf(sc[i] - mx);
        float an = mx + logf(sm) + lt;
        if (t < len) alpha = an;
    }
    float v = (lane < 12) ? alpha + st[lane * 12 + 11] : -1e30f;
    float mx = v;
#pragma unroll
    for (int o = 16; o > 0; o >>= 1) mx = fmaxf(mx, __shfl_xor_sync(0xffffffffu, mx, o));
    float e = expf(v - mx);
#pragma unroll
    for (int o = 16; o > 0; o >>= 1) e += __shfl_xor_sync(0xffffffffu, e, o);
    if (lane == 0) tot[b] = mx + logf(e);
}

__global__ void k_crf_reduce(const float* __restrict__ crf, float* __restrict__ out) {
    __shared__ float s[256];
    int t = threadIdx.x;
    s[t] = crf[t] - crf[256 + t];
    __syncthreads();
    for (int o = 128; o > 0; o >>= 1) {
        if (t < o) s[t] += s[t + o];
        __syncthreads();
    }
    if (t == 0) out[0] = s[0];
}

// ---------------- launch ----------------
extern "C" void kernel_launch(void* const* d_in, const int* in_sizes, int n_in,
                              void* d_out, int out_size) {
    const int*   characters = (const int*)d_in[0];
    const float* words      = (const float*)d_in[1];
    const int*   tags       = (const int*)d_in[2];
    const int*   len_char   = (const int*)d_in[3];
    const int*   len_word   = (const int*)d_in[4];
    const float* char_emb   = (const float*)d_in[5];
    const float* cWihf = (const float*)d_in[6];
    const float* cWhhf = (const float*)d_in[7];
    const float* cbf   = (const float*)d_in[8];
    const float* cWihb = (const float*)d_in[9];
    const float* cWhhb = (const float*)d_in[10];
    const float* cbb   = (const float*)d_in[11];
    const float* clinW = (const float*)d_in[12];
    const float* clinb = (const float*)d_in[13];
    const float* wWihf = (const float*)d_in[14];
    const float* wWhhf = (const float*)d_in[15];
    const float* wbf   = (const float*)d_in[16];
    const float* wWihb = (const float*)d_in[17];
    const float* wWhhb = (const float*)d_in[18];
    const float* wbb   = (const float*)d_in[19];
    const float* wlinW = (const float*)d_in[20];
    const float* wlinb = (const float*)d_in[21];
    const float* l1W   = (const float*)d_in[22];
    const float* l1b   = (const float*)d_in[23];
    const float* l2W   = (const float*)d_in[24];
    const float* l2b   = (const float*)d_in[25];
    const float* tW    = (const float*)d_in[26];
    const float* tb    = (const float*)d_in[27];
    const float* trans = (const float*)d_in[28];
    float* out = (float*)d_out;

    float *char_x, *word_x, *xpre, *whhp, *cihp, *wihp, *bp, *hbuf;
    float *char_h, *word_h, *xcat, *buf1, *buf2, *logits, *crfb;
    cudaGetSymbolAddress((void**)&char_x, d_char_x);
    cudaGetSymbolAddress((void**)&word_x, d_word_x);
    cudaGetSymbolAddress((void**)&xpre,   d_xpre);
    cudaGetSymbolAddress((void**)&whhp,   d_whhp);
    cudaGetSymbolAddress((void**)&cihp,   d_cihp);
    cudaGetSymbolAddress((void**)&wihp,   d_wihp);
    cudaGetSymbolAddress((void**)&bp,     d_bp);
    cudaGetSymbolAddress((void**)&hbuf,   d_hbuf);
    cudaGetSymbolAddress((void**)&char_h, d_char_h);
    cudaGetSymbolAddress((void**)&word_h, d_word_h);
    cudaGetSymbolAddress((void**)&xcat,   d_xcat);
    cudaGetSymbolAddress((void**)&buf1,   d_buf1);
    cudaGetSymbolAddress((void**)&buf2,   d_buf2);
    cudaGetSymbolAddress((void**)&logits, d_logits);
    cudaGetSymbolAddress((void**)&crfb,   d_crf);

    const int REC_SMEM = (256 * 68 + 32 * 68) * 4;  // 78336 B
    cudaFuncSetAttribute(k_rec_persist, cudaFuncAttributeMaxDynamicSharedMemorySize, REC_SMEM);

    k_init<<<(4 * 2 * BB * 256 + 255) / 256, 256>>>(hbuf);

    k_perm_w<<<(1024 * 256 + 255) / 256, 256>>>(cWhhf, whhp + 0 * 1024 * 256, 256);
    k_perm_w<<<(1024 * 256 + 255) / 256, 256>>>(cWhhb, whhp + 1 * 1024 * 256, 256);
    k_perm_w<<<(1024 * 256 + 255) / 256, 256>>>(wWhhf, whhp + 2 * 1024 * 256, 256);
    k_perm_w<<<(1024 * 256 + 255) / 256, 256>>>(wWhhb, whhp + 3 * 1024 * 256, 256);
    k_perm_w<<<(1024 * 30 + 255) / 256, 256>>>(cWihf, cihp + 0 * 1024 * 30, 30);
    k_perm_w<<<(1024 * 30 + 255) / 256, 256>>>(cWihb, cihp + 1 * 1024 * 30, 30);
    k_perm_w<<<(1024 * 128 + 255) / 256, 256>>>(wWihf, wihp + 0 * 1024 * 128, 128);
    k_perm_w<<<(1024 * 128 + 255) / 256, 256>>>(wWihb, wihp + 1 * 1024 * 128, 128);
    k_perm_b<<<4, 256>>>(cbf, bp + 0 * 1024);
    k_perm_b<<<4, 256>>>(cbb, bp + 1 * 1024);
    k_perm_b<<<4, 256>>>(wbf, bp + 2 * 1024);
    k_perm_b<<<4, 256>>>(wbb, bp + 3 * 1024);

    k_gather_char<<<(TT * BB * 30 + 255) / 256, 256>>>(characters, char_emb, char_x);
    k_transpose_word<<<(TT * BB * 128 + 255) / 256, 256>>>(words, word_x);

    int Mbt = BB * TT;  // 51200
    auto grid = [](int M, int N) { return dim3((unsigned)((N + 63) / 64), (unsigned)((M + 127) / 128)); };

    // input projections (tf32 tensor cores) with permuted weights -> interleaved xpre
    k_gemm_tc<<<grid(Mbt, 1024), 256>>>(char_x, cihp + 0 * 1024 * 30,  bp + 0 * 1024, xpre + 0 * (size_t)XPD, Mbt, 1024, 30, 1024, 0);
    k_gemm_tc<<<grid(Mbt, 1024), 256>>>(char_x, cihp + 1 * 1024 * 30,  bp + 1 * 1024, xpre + 1 * (size_t)XPD, Mbt, 1024, 30, 1024, 0);
    k_gemm_tc<<<grid(Mbt, 1024), 256>>>(word_x, wihp + 0 * 1024 * 128, bp + 2 * 1024, xpre + 2 * (size_t)XPD, Mbt, 1024, 128, 1024, 0);
    k_gemm_tc<<<grid(Mbt, 1024), 256>>>(word_x, wihp + 1 * 1024 * 128, bp + 3 * 1024, xpre + 3 * (size_t)XPD, Mbt, 1024, 128, 1024, 0);

    // persistent recurrence: 4 dirs x 200 steps, one launch
    RP rp;
    rp.whhp = whhp;
    rp.xpre = xpre;
    rp.hbuf = hbuf;
    rp.len_char = len_char;
    rp.len_word = len_word;
    rp.outc = char_h;
    rp.outw = word_h;
    k_rec_persist<<<NBLK, 256, REC_SMEM>>>(rp);

    // dense stack (tf32 tensor cores, softplus fused)
    k_gemm_tc<<<grid(Mbt, 512), 256>>>(char_h, clinW, clinb, xcat,       Mbt, 512, 512, 712, 1);
    k_gemm_tc<<<grid(Mbt, 200), 256>>>(word_h, wlinW, wlinb, xcat + 512, Mbt, 200, 512, 712, 1);
    k_gemm_tc<<<grid(Mbt, 512), 256>>>(xcat, l1W, l1b, buf1,   Mbt, 512, 712, 512, 1);
    k_gemm_tc<<<grid(Mbt, 256), 256>>>(buf1, l2W, l2b, buf2,   Mbt, 256, 512, 256, 1);
    k_gemm_tc<<<grid(Mbt, 12),  256>>>(buf2, tW,  tb,  logits, Mbt, 12,  256, 12,  1);

    // CRF
    k_crf_real<<<1, 256>>>(logits, tags, len_char, trans, crfb + BB);
    k_crf_fwd<<<32, 256>>>(logits, len_char, trans, crfb);
    k_crf_reduce<<<1, 256>>>(crfb, out);
}

// round 4
// speedup vs baseline: 3.1152x; 1.6057x over previous
#include <cuda_runtime.h>

#define TT 200
#define BB 256
#define XPD (TT*BB*1024)
#define NBLK 256

// ---------------- scratch (device globals: allocation-free) ----------------
__device__ float d_char_x[TT*BB*30];        // [t][b][30]
__device__ float d_word_x[TT*BB*128];       // [w][b][128]
__device__ float d_xpre[4][TT*BB*1024];     // per-dir input preact, mma-permuted cols
__device__ float d_whhp[4][1024*256];       // permuted Whh
__device__ float d_cihp[2][1024*30];        // permuted char Wih
__device__ float d_wihp[2][1024*128];       // permuted word Wih
__device__ float d_bp[4][1024];             // permuted biases
__device__ float d_hbuf[4*2*BB*256];        // ping-pong h per dir
__device__ float d_char_h[BB*TT*512];       // [b][t][512]
__device__ float d_word_h[BB*TT*512];       // [b][w][512]
__device__ float d_xcat[BB*TT*712];         // concat(char_map, word_map)
__device__ float d_buf1[BB*TT*512];
__device__ float d_buf2[BB*TT*256];
__device__ float d_logits[BB*TT*12];
__device__ float d_crf[2*BB];

__device__ unsigned g_arr;
__device__ volatile unsigned g_gen;

__device__ __forceinline__ float sp_(float x) { return fmaxf(x, 0.f) + log1pf(expf(-fabsf(x))); }
__device__ __forceinline__ float sg_(float x) { return 1.f / (1.f + expf(-x)); }

__device__ __forceinline__ unsigned f2tf(float f) {
    unsigned u;
    asm("cvt.rna.tf32.f32 %0, %1;" : "=r"(u) : "f"(f));
    return u;
}

__device__ __forceinline__ void mma_tf32(float* d, const unsigned* a, const unsigned* b) {
    asm volatile(
        "mma.sync.aligned.m16n8k8.row.col.f32.tf32.tf32.f32 "
        "{%0,%1,%2,%3}, {%4,%5,%6,%7}, {%8,%9}, {%0,%1,%2,%3};\n"
        : "+f"(d[0]), "+f"(d[1]), "+f"(d[2]), "+f"(d[3])
        : "r"(a[0]), "r"(a[1]), "r"(a[2]), "r"(a[3]), "r"(b[0]), "r"(b[1]));
}

// mma-friendly gate-column permutation: (g,u) -> permuted row index
__device__ __forceinline__ int perm_gu(int g, int u) {
    int nb = u >> 4, w16 = u & 15;
    int h = w16 >> 3, v = w16 & 7;
    int p = v >> 2, t = v & 3;
    return nb * 64 + h * 32 + p * 16 + ((g >> 1) << 3) + t * 2 + (g & 1);
}

// ---------------- small utility kernels ----------------
__global__ void k_init(float* hbuf) {
    int i = blockIdx.x * blockDim.x + threadIdx.x;
    if (i == 0) { g_arr = 0; g_gen = 0; }
    if (i < 4 * 2 * BB * 256) hbuf[i] = 0.f;
}

__global__ void k_gather_char(const int* __restrict__ chars, const float* __restrict__ emb,
                              float* __restrict__ out) {
    int i = blockIdx.x * blockDim.x + threadIdx.x;
    if (i >= TT * BB * 30) return;
    int k = i % 30, tb = i / 30;
    int b = tb % BB, t = tb / BB;
    out[i] = emb[chars[b * TT + t] * 30 + k];
}

__global__ void k_transpose_word(const float* __restrict__ words, float* __restrict__ out) {
    int i = blockIdx.x * blockDim.x + threadIdx.x;
    if (i >= TT * BB * 128) return;
    int k = i & 127, wb = i >> 7;
    int b = wb % BB, w = wb / BB;
    out[i] = words[((size_t)b * TT + w) * 128 + k];
}

// permute gate-major rows (g*256+u) -> mma-fragment order
__global__ void k_perm_w(const float* __restrict__ src, float* __restrict__ dst, int K) {
    int i = blockIdx.x * blockDim.x + threadIdx.x;
    if (i >= 1024 * K) return;
    int k = i % K, s = i / K;
    int g = s >> 8, u = s & 255;
    dst[(size_t)perm_gu(g, u) * K + k] = src[(size_t)s * K + k];
}

__global__ void k_perm_b(const float* __restrict__ src, float* __restrict__ dst) {
    int s = blockIdx.x * blockDim.x + threadIdx.x;
    if (s >= 1024) return;
    int g = s >> 8, u = s & 255;
    dst[perm_gu(g, u)] = src[s];
}

// ---------------- TF32 tensor-core GEMM: C = act(A[M,K] @ W[N,K]^T + bias) ----------------
__global__ void __launch_bounds__(256) k_gemm_tc(
        const float* __restrict__ A, const float* __restrict__ W,
        const float* __restrict__ bias, float* __restrict__ C,
        int M, int N, int K, int ldc, int act) {
    __shared__ unsigned As[128][36];
    __shared__ unsigned Bs[64][36];

    int tid = threadIdx.x;
    int bm = blockIdx.y * 128, bn = blockIdx.x * 64;
    int wid = tid >> 5, lane = tid & 31;
    int wm = (wid & 3) * 32, wn = (wid >> 2) * 32;
    int gid = lane >> 2, tig = lane & 3;
    bool k4 = (K & 3) == 0;

    float acc[2][4][4];
#pragma unroll
    for (int i = 0; i < 2; i++)
#pragma unroll
        for (int j = 0; j < 4; j++)
#pragma unroll
            for (int v = 0; v < 4; v++) acc[i][j][v] = 0.f;

    float ra[16], rb[8];

    auto load_stage = [&](int k0) {
#pragma unroll
        for (int j = 0; j < 4; j++) {
            int q = tid + 256 * j;
            int r = q >> 3, c = (q & 7) * 4;
            const float* src = A + (size_t)(bm + r) * K + k0 + c;
            float4 v;
            if (k4 && k0 + c + 3 < K) v = *(const float4*)src;
            else {
                v.x = (k0 + c + 0 < K) ? src[0] : 0.f;
                v.y = (k0 + c + 1 < K) ? src[1] : 0.f;
                v.z = (k0 + c + 2 < K) ? src[2] : 0.f;
                v.w = (k0 + c + 3 < K) ? src[3] : 0.f;
            }
            ra[j * 4 + 0] = v.x; ra[j * 4 + 1] = v.y; ra[j * 4 + 2] = v.z; ra[j * 4 + 3] = v.w;
        }
#pragma unroll
        for (int j = 0; j < 2; j++) {
            int q = tid + 256 * j;
            int r = q >> 3, c = (q & 7) * 4;
            float4 v = make_float4(0.f, 0.f, 0.f, 0.f);
            if (bn + r < N) {
                const float* src = W + (size_t)(bn + r) * K + k0 + c;
                if (k4 && k0 + c + 3 < K) v = *(const float4*)src;
                else {
                    v.x = (k0 + c + 0 < K) ? src[0] : 0.f;
                    v.y = (k0 + c + 1 < K) ? src[1] : 0.f;
                    v.z = (k0 + c + 2 < K) ? src[2] : 0.f;
                    v.w = (k0 + c + 3 < K) ? src[3] : 0.f;
                }
            }
            rb[j * 4 + 0] = v.x; rb[j * 4 + 1] = v.y; rb[j * 4 + 2] = v.z; rb[j * 4 + 3] = v.w;
        }
    };

    load_stage(0);
    for (int k0 = 0; k0 < K; k0 += 32) {
        __syncthreads();
#pragma unroll
        for (int j = 0; j < 4; j++) {
            int q = tid + 256 * j;
            int r = q >> 3, c = (q & 7) * 4;
            *(uint4*)&As[r][c] = make_uint4(f2tf(ra[j*4+0]), f2tf(ra[j*4+1]), f2tf(ra[j*4+2]), f2tf(ra[j*4+3]));
        }
#pragma unroll
        for (int j = 0; j < 2; j++) {
            int q = tid + 256 * j;
            int r = q >> 3, c = (q & 7) * 4;
            *(uint4*)&Bs[r][c] = make_uint4(f2tf(rb[j*4+0]), f2tf(rb[j*4+1]), f2tf(rb[j*4+2]), f2tf(rb[j*4+3]));
        }
        __syncthreads();
        if (k0 + 32 < K) load_stage(k0 + 32);

#pragma unroll
        for (int ks = 0; ks < 4; ks++) {
            int kk = ks * 8;
            unsigned af[2][4], bf[4][2];
#pragma unroll
            for (int im = 0; im < 2; im++) {
                int rm = wm + im * 16;
                af[im][0] = As[rm + gid][kk + tig];
                af[im][1] = As[rm + gid + 8][kk + tig];
                af[im][2] = As[rm + gid][kk + tig + 4];
                af[im][3] = As[rm + gid + 8][kk + tig + 4];
            }
#pragma unroll
            for (int jn = 0; jn < 4; jn++) {
                int cn = wn + jn * 8;
                bf[jn][0] = Bs[cn + gid][kk + tig];
                bf[jn][1] = Bs[cn + gid][kk + tig + 4];
            }
#pragma unroll
            for (int im = 0; im < 2; im++)
#pragma unroll
                for (int jn = 0; jn < 4; jn++)
                    mma_tf32(acc[im][jn], af[im], bf[jn]);
        }
    }

#pragma unroll
    for (int im = 0; im < 2; im++) {
#pragma unroll
        for (int jn = 0; jn < 4; jn++) {
            int row0 = bm + wm + im * 16 + gid;
            int col0 = bn + wn + jn * 8 + tig * 2;
#pragma unroll
            for (int half = 0; half < 2; half++) {
                int row = row0 + half * 8;
#pragma unroll
                for (int cc = 0; cc < 2; cc++) {
                    int col = col0 + cc;
                    if (col >= N) continue;
                    float v = acc[im][jn][half * 2 + cc];
                    if (bias) v += bias[col];
                    if (act) v = sp_(v);
                    C[(size_t)row * ldc + col] = v;
                }
            }
        }
    }
}

// ---------------- persistent recurrence (tensor cores) ----------------
struct RP {
    const float* whhp;
    const float* xpre;
    float* hbuf;
    const int* len_char;
    const int* len_word;
    float* outc;
    float* outw;
};

__device__ __forceinline__ void grid_bar(unsigned target) {
    __threadfence();
    __syncthreads();
    if (threadIdx.x == 0) {
        if (atomicAdd(&g_arr, 1u) == NBLK - 1) {
            g_arr = 0;
            __threadfence();
            g_gen = target;
        } else {
            while (g_gen < target) __nanosleep(64);
        }
    }
    __syncthreads();
}

// smem: Ws [64][260] tf32 + As [64][132] tf32
#define REC_SMEM ((64*260 + 64*132) * 4)

__global__ void __launch_bounds__(256, 2) k_rec_persist(RP p) {
    extern __shared__ unsigned smu[];
    unsigned* Ws = smu;                 // [64][260]
    unsigned* As = smu + 64 * 260;      // [64][132]

    int bx = blockIdx.x;
    int dir = bx >> 6, mb = (bx >> 4) & 3, nb = bx & 15;
    int tid = threadIdx.x;
    int wid = tid >> 5, lane = tid & 31;
    int gid = lane >> 2, tig = lane & 3;
    int wm = (wid & 3) * 16;      // warp m offset
    int wnh = wid >> 2;           // warp n half (0/1)
    int bm = mb * 64;

    // load + convert Whh tile for this block's 64 gate-columns
    const float* W = p.whhp + (size_t)dir * 1024 * 256;
    for (int idx = tid; idx < 64 * 256; idx += 256) {
        int n = idx >> 8, k = idx & 255;
        Ws[n * 260 + k] = f2tf(W[(size_t)(nb * 64 + n) * 256 + k]);
    }

    float hreg[2][2], creg[2][2];
#pragma unroll
    for (int i = 0; i < 2; i++)
#pragma unroll
        for (int j = 0; j < 2; j++) { hreg[i][j] = 0.f; creg[i][j] = 0.f; }

    const int* lens = (dir < 2) ? p.len_char : p.len_word;
    int lenv[2];
    lenv[0] = lens[bm + wm + gid];
    lenv[1] = lens[bm + wm + gid + 8];

    float* hb0 = p.hbuf + (size_t)dir * 2 * 65536;
    float* hb1 = hb0 + 65536;
    const float* xp = p.xpre + (size_t)dir * XPD;
    float* outp = (dir < 2) ? p.outc : p.outw;
    int half = (dir & 1) ? 256 : 0;
    int cn0 = nb * 64 + wnh * 32;       // warp's global column base in xpre

    __syncthreads();

    for (int t = 0; t < TT; t++) {
        int tr = (dir & 1) ? (TT - 1 - t) : t;
        const float* h = (t & 1) ? hb1 : hb0;
        float* hn_buf = (t & 1) ? hb0 : hb1;

        float acc[4][4];
#pragma unroll
        for (int j = 0; j < 4; j++)
#pragma unroll
            for (int v = 0; v < 4; v++) acc[j][v] = 0.f;

#pragma unroll
        for (int k0 = 0; k0 < 256; k0 += 128) {
            __syncthreads();
            // stage h chunk [64 rows][128 k] as tf32
#pragma unroll
            for (int j = 0; j < 8; j++) {
                int q = tid + 256 * j;          // 0..2047 float4 slots
                int r = q >> 5, c4 = q & 31;
                float4 v = __ldcg((const float4*)&h[(bm + r) * 256 + k0 + c4 * 4]);
                *(uint4*)&As[r * 132 + c4 * 4] =
                    make_uint4(f2tf(v.x), f2tf(v.y), f2tf(v.z), f2tf(v.w));
            }
            __syncthreads();
#pragma unroll
            for (int ks = 0; ks < 16; ks++) {
                int kk = ks * 8;
                unsigned af[4], bf[4][2];
                af[0] = As[(wm + gid) * 132 + kk + tig];
                af[1] = As[(wm + gid + 8) * 132 + kk + tig];
                af[2] = As[(wm + gid) * 132 + kk + tig + 4];
                af[3] = As[(wm + gid + 8) * 132 + kk + tig + 4];
#pragma unroll
                for (int jn = 0; jn < 4; jn++) {
                    int n0 = wnh * 32 + jn * 8;
                    bf[jn][0] = Ws[(n0 + gid) * 260 + k0 + kk + tig];
                    bf[jn][1] = Ws[(n0 + gid) * 260 + k0 + kk + tig + 4];
                }
#pragma unroll
                for (int jn = 0; jn < 4; jn++)
                    mma_tf32(acc[jn], af, bf[jn]);
            }
        }

        // fused LSTM cell epilogue: each thread owns 2 rows x 2 units (all 4 gates)
        const float* xrow = xp + (size_t)tr * BB * 1024;
#pragma unroll
        for (int rh = 0; rh < 2; rh++) {
            int b = bm + wm + gid + rh * 8;
            bool valid = tr < lenv[rh];
#pragma unroll
            for (int pp = 0; pp < 2; pp++) {
                float2 x01 = *(const float2*)&xrow[(size_t)b * 1024 + cn0 + pp * 16 + tig * 2];
                float2 x23 = *(const float2*)&xrow[(size_t)b * 1024 + cn0 + pp * 16 + 8 + tig * 2];
                float gi = acc[2 * pp + 0][rh * 2 + 0] + x01.x;
                float gf = acc[2 * pp + 0][rh * 2 + 1] + x01.y;
                float gc = acc[2 * pp + 1][rh * 2 + 0] + x23.x;
                float go = acc[2 * pp + 1][rh * 2 + 1] + x23.y;
                float cn = sg_(gf) * creg[rh][pp] + sg_(gi) * tanhf(gc);
                float hv = sg_(go) * tanhf(cn);
                if (valid) { creg[rh][pp] = cn; hreg[rh][pp] = hv; }
                int u = nb * 16 + wnh * 8 + pp * 4 + tig;
                outp[((size_t)b * TT + tr) * 512 + half + u] = valid ? hv : 0.f;
                hn_buf[b * 256 + u] = hreg[rh][pp];
            }
        }

        grid_bar((unsigned)(t + 1));
    }
}

// ---------------- CRF ----------------
__global__ void k_crf_real(const float* __restrict__ logits, const int* __restrict__ tags,
                           const int* __restrict__ lens, const float* __restrict__ trans,
                           float* __restrict__ rl) {
    int b = threadIdx.x;
    int len = lens[b];
    float s = 0.f;
    int prev = 10;
    for (int t = 0; t < len; t++) {
        int tg = tags[b * TT + t];
        s += logits[((size_t)b * TT + t) * 12 + tg] + trans[prev * 12 + tg];
        prev = tg;
    }
    s += trans[prev * 12 + 11];
    rl[b] = s;
}

__global__ void k_crf_fwd(const float* __restrict__ logits, const int* __restrict__ lens,
                          const float* __restrict__ trans, float* __restrict__ tot) {
    __shared__ float st[144];
    int tid = threadIdx.x;
    if (tid < 144) st[tid] = trans[tid];
    __syncthreads();
    int warp = tid >> 5, lane = tid & 31;
    int b = blockIdx.x * 8 + warp;
    int len = lens[b];
    float alpha = 0.f;
    for (int t = 0; t < TT; t++) {
        float lt = (lane < 12) ? logits[((size_t)b * TT + t) * 12 + lane] : 0.f;
        float sc[12];
        float mx = -1e30f;
#pragma unroll
        for (int i = 0; i < 12; i++) {
            float ai = __shfl_sync(0xffffffffu, alpha, i);
            float s = ai + ((lane < 12) ? st[i * 12 + lane] : 0.f);
            sc[i] = s;
            mx = fmaxf(mx, s);
        }
        float sm = 0.f;
#pragma unroll
        for (int i = 0; i < 12; i++) sm += expf(sc[i] - mx);
        float an = mx + logf(sm) + lt;
        if (t < len) alpha = an;
    }
    float v = (lane < 12) ? alpha + st[lane * 12 + 11] : -1e30f;
    float mx = v;
#pragma unroll
    for (int o = 16; o > 0; o >>= 1) mx = fmaxf(mx, __shfl_xor_sync(0xffffffffu, mx, o));
    float e = expf(v - mx);
#pragma unroll
    for (int o = 16; o > 0; o >>= 1) e += __shfl_xor_sync(0xffffffffu, e, o);
    if (lane == 0) tot[b] = mx + logf(e);
}

__global__ void k_crf_reduce(const float* __restrict__ crf, float* __restrict__ out) {
    __shared__ float s[256];
    int t = threadIdx.x;
    s[t] = crf[t] - crf[256 + t];
    __syncthreads();
    for (int o = 128; o > 0; o >>= 1) {
        if (t < o) s[t] += s[t + o];
        __syncthreads();
    }
    if (t == 0) out[0] = s[0];
}

// ---------------- launch ----------------
extern "C" void kernel_launch(void* const* d_in, const int* in_sizes, int n_in,
                              void* d_out, int out_size) {
    const int*   characters = (const int*)d_in[0];
    const float* words      = (const float*)d_in[1];
    const int*   tags       = (const int*)d_in[2];
    const int*   len_char   = (const int*)d_in[3];
    const int*   len_word   = (const int*)d_in[4];
    const float* char_emb   = (const float*)d_in[5];
    const float* cWihf = (const float*)d_in[6];
    const float* cWhhf = (const float*)d_in[7];
    const float* cbf   = (const float*)d_in[8];
    const float* cWihb = (const float*)d_in[9];
    const float* cWhhb = (const float*)d_in[10];
    const float* cbb   = (const float*)d_in[11];
    const float* clinW = (const float*)d_in[12];
    const float* clinb = (const float*)d_in[13];
    const float* wWihf = (const float*)d_in[14];
    const float* wWhhf = (const float*)d_in[15];
    const float* wbf   = (const float*)d_in[16];
    const float* wWihb = (const float*)d_in[17];
    const float* wWhhb = (const float*)d_in[18];
    const float* wbb   = (const float*)d_in[19];
    const float* wlinW = (const float*)d_in[20];
    const float* wlinb = (const float*)d_in[21];
    const float* l1W   = (const float*)d_in[22];
    const float* l1b   = (const float*)d_in[23];
    const float* l2W   = (const float*)d_in[24];
    const float* l2b   = (const float*)d_in[25];
    const float* tW    = (const float*)d_in[26];
    const float* tb    = (const float*)d_in[27];
    const float* trans = (const float*)d_in[28];
    float* out = (float*)d_out;

    float *char_x, *word_x, *xpre, *whhp, *cihp, *wihp, *bp, *hbuf;
    float *char_h, *word_h, *xcat, *buf1, *buf2, *logits, *crfb;
    cudaGetSymbolAddress((void**)&char_x, d_char_x);
    cudaGetSymbolAddress((void**)&word_x, d_word_x);
    cudaGetSymbolAddress((void**)&xpre,   d_xpre);
    cudaGetSymbolAddress((void**)&whhp,   d_whhp);
    cudaGetSymbolAddress((void**)&cihp,   d_cihp);
    cudaGetSymbolAddress((void**)&wihp,   d_wihp);
    cudaGetSymbolAddress((void**)&bp,     d_bp);
    cudaGetSymbolAddress((void**)&hbuf,   d_hbuf);
    cudaGetSymbolAddress((void**)&char_h, d_char_h);
    cudaGetSymbolAddress((void**)&word_h, d_word_h);
    cudaGetSymbolAddress((void**)&xcat,   d_xcat);
    cudaGetSymbolAddress((void**)&buf1,   d_buf1);
    cudaGetSymbolAddress((void**)&buf2,   d_buf2);
    cudaGetSymbolAddress((void**)&logits, d_logits);
    cudaGetSymbolAddress((void**)&crfb,   d_crf);

    cudaFuncSetAttribute(k_rec_persist, cudaFuncAttributeMaxDynamicSharedMemorySize, REC_SMEM);

    k_init<<<(4 * 2 * BB * 256 + 255) / 256, 256>>>(hbuf);

    k_perm_w<<<(1024 * 256 + 255) / 256, 256>>>(cWhhf, whhp + 0 * 1024 * 256, 256);
    k_perm_w<<<(1024 * 256 + 255) / 256, 256>>>(cWhhb, whhp + 1 * 1024 * 256, 256);
    k_perm_w<<<(1024 * 256 + 255) / 256, 256>>>(wWhhf, whhp + 2 * 1024 * 256, 256);
    k_perm_w<<<(1024 * 256 + 255) / 256, 256>>>(wWhhb, whhp + 3 * 1024 * 256, 256);
    k_perm_w<<<(1024 * 30 + 255) / 256, 256>>>(cWihf, cihp + 0 * 1024 * 30, 30);
    k_perm_w<<<(1024 * 30 + 255) / 256, 256>>>(cWihb, cihp + 1 * 1024 * 30, 30);
    k_perm_w<<<(1024 * 128 + 255) / 256, 256>>>(wWihf, wihp + 0 * 1024 * 128, 128);
    k_perm_w<<<(1024 * 128 + 255) / 256, 256>>>(wWihb, wihp + 1 * 1024 * 128, 128);
    k_perm_b<<<4, 256>>>(cbf, bp + 0 * 1024);
    k_perm_b<<<4, 256>>>(cbb, bp + 1 * 1024);
    k_perm_b<<<4, 256>>>(wbf, bp + 2 * 1024);
    k_perm_b<<<4, 256>>>(wbb, bp + 3 * 1024);

    k_gather_char<<<(TT * BB * 30 + 255) / 256, 256>>>(characters, char_emb, char_x);
    k_transpose_word<<<(TT * BB * 128 + 255) / 256, 256>>>(words, word_x);

    int Mbt = BB * TT;  // 51200
    auto grid = [](int M, int N) { return dim3((unsigned)((N + 63) / 64), (unsigned)((M + 127) / 128)); };

    k_gemm_tc<<<grid(Mbt, 1024), 256>>>(char_x, cihp + 0 * 1024 * 30,  bp + 0 * 1024, xpre + 0 * (size_t)XPD, Mbt, 1024, 30, 1024, 0);
    k_gemm_tc<<<grid(Mbt, 1024), 256>>>(char_x, cihp + 1 * 1024 * 30,  bp + 1 * 1024, xpre + 1 * (size_t)XPD, Mbt, 1024, 30, 1024, 0);
    k_gemm_tc<<<grid(Mbt, 1024), 256>>>(word_x, wihp + 0 * 1024 * 128, bp + 2 * 1024, xpre + 2 * (size_t)XPD, Mbt, 1024, 128, 1024, 0);
    k_gemm_tc<<<grid(Mbt, 1024), 256>>>(word_x, wihp + 1 * 1024 * 128, bp + 3 * 1024, xpre + 3 * (size_t)XPD, Mbt, 1024, 128, 1024, 0);

    RP rp;
    rp.whhp = whhp;
    rp.xpre = xpre;
    rp.hbuf = hbuf;
    rp.len_char = len_char;
    rp.len_word = len_word;
    rp.outc = char_h;
    rp.outw = word_h;
    k_rec_persist<<<NBLK, 256, REC_SMEM>>>(rp);

    k_gemm_tc<<<grid(Mbt, 512), 256>>>(char_h, clinW, clinb, xcat,       Mbt, 512, 512, 712, 1);
    k_gemm_tc<<<grid(Mbt, 200), 256>>>(word_h, wlinW, wlinb, xcat + 512, Mbt, 200, 512, 712, 1);
    k_gemm_tc<<<grid(Mbt, 512), 256>>>(xcat, l1W, l1b, buf1,   Mbt, 512, 712, 512, 1);
    k_gemm_tc<<<grid(Mbt, 256), 256>>>(buf1, l2W, l2b, buf2,   Mbt, 256, 512, 256, 1);
    k_gemm_tc<<<grid(Mbt, 12),  256>>>(buf2, tW,  tb,  logits, Mbt, 12,  256, 12,  1);

    k_crf_real<<<1, 256>>>(logits, tags, len_char, trans, crfb + BB);
    k_crf_fwd<<<32, 256>>>(logits, len_char, trans, crfb);
    k_crf_reduce<<<1, 256>>>(crfb, out);
}

// round 6
// speedup vs baseline: 4.0172x; 1.2896x over previous
#include <cuda_runtime.h>
#include <cuda_bf16.h>

#define TT 200
#define BB 256
#define XPD (TT*BB*1024)
#define NBLK 256

// ---------------- scratch (device globals: allocation-free) ----------------
__device__ float d_char_x[TT*BB*30];            // [t][b][30]
__device__ float d_word_x[TT*BB*128];           // [w][b][128]
__device__ __nv_bfloat16 d_xpre[4][XPD];        // per-dir input preact, mma-permuted cols (bf16)
__device__ float d_whhp[4][1024*256];           // permuted Whh
__device__ float d_cihp[2][1024*30];            // permuted char Wih
__device__ float d_wihp[2][1024*128];           // permuted word Wih
__device__ float d_bp[4][1024];                 // permuted biases
__device__ float d_hbuf[4*2*BB*256];            // ping-pong h per dir
__device__ float d_char_h[BB*TT*512];           // [b][t][512]
__device__ float d_word_h[BB*TT*512];           // [b][w][512]
__device__ float d_xcat[BB*TT*712];             // concat(char_map, word_map)
__device__ float d_buf1[BB*TT*512];
__device__ float d_buf2[BB*TT*256];
__device__ float d_logits[BB*TT*12];
__device__ float d_crf[2*BB];

__device__ unsigned g_arr;
__device__ volatile unsigned g_gen;

__device__ __forceinline__ float sp_(float x) { return fmaxf(x, 0.f) + log1pf(expf(-fabsf(x))); }
__device__ __forceinline__ float sg_(float x) { return 1.f / (1.f + expf(-x)); }

// pack two fp32 -> bf16x2 word (lo = first k, hi = second k)
__device__ __forceinline__ unsigned pk2(float lo, float hi) {
    unsigned r;
    asm("cvt.rn.bf16x2.f32 %0, %1, %2;" : "=r"(r) : "f"(hi), "f"(lo));
    return r;
}

__device__ __forceinline__ void mma_bf16(float* d, const unsigned* a, const unsigned* b) {
    asm volatile(
        "mma.sync.aligned.m16n8k16.row.col.f32.bf16.bf16.f32 "
        "{%0,%1,%2,%3}, {%4,%5,%6,%7}, {%8,%9}, {%0,%1,%2,%3};\n"
        : "+f"(d[0]), "+f"(d[1]), "+f"(d[2]), "+f"(d[3])
        : "r"(a[0]), "r"(a[1]), "r"(a[2]), "r"(a[3]), "r"(b[0]), "r"(b[1]));
}

// mma-friendly gate-column permutation: (g,u) -> permuted row index
__device__ __forceinline__ int perm_gu(int g, int u) {
    int nb = u >> 4, w16 = u & 15;
    int h = w16 >> 3, v = w16 & 7;
    int p = v >> 2, t = v & 3;
    return nb * 64 + h * 32 + p * 16 + ((g >> 1) << 3) + t * 2 + (g & 1);
}

// ---------------- small utility kernels ----------------
__global__ void k_init(float* hbuf) {
    int i = blockIdx.x * blockDim.x + threadIdx.x;
    if (i == 0) { g_arr = 0; g_gen = 0; }
    if (i < 4 * 2 * BB * 256) hbuf[i] = 0.f;
}

__global__ void k_gather_char(const int* __restrict__ chars, const float* __restrict__ emb,
                              float* __restrict__ out) {
    int i = blockIdx.x * blockDim.x + threadIdx.x;
    if (i >= TT * BB * 30) return;
    int k = i % 30, tb = i / 30;
    int b = tb % BB, t = tb / BB;
    out[i] = emb[chars[b * TT + t] * 30 + k];
}

__global__ void k_transpose_word(const float* __restrict__ words, float* __restrict__ out) {
    int i = blockIdx.x * blockDim.x + threadIdx.x;
    if (i >= TT * BB * 128) return;
    int k = i & 127, wb = i >> 7;
    int b = wb % BB, w = wb / BB;
    out[i] = words[((size_t)b * TT + w) * 128 + k];
}

__global__ void k_perm_w(const float* __restrict__ src, float* __restrict__ dst, int K) {
    int i = blockIdx.x * blockDim.x + threadIdx.x;
    if (i >= 1024 * K) return;
    int k = i % K, s = i / K;
    int g = s >> 8, u = s & 255;
    dst[(size_t)perm_gu(g, u) * K + k] = src[(size_t)s * K + k];
}

__global__ void k_perm_b(const float* __restrict__ src, float* __restrict__ dst) {
    int s = blockIdx.x * blockDim.x + threadIdx.x;
    if (s >= 1024) return;
    int g = s >> 8, u = s & 255;
    dst[perm_gu(g, u)] = src[s];
}

// ---------------- BF16 tensor-core GEMM: C = act(A[M,K] @ W[N,K]^T + bias) ----------------
// block 128(M) x 64(N), K-chunk 32; 8 warps each 32x32 via m16n8k16 bf16 mma, fp32 accum.
// obf=1 -> write bf16 output (C cast), else fp32.
__global__ void __launch_bounds__(256) k_gemm_tc(
        const float* __restrict__ A, const float* __restrict__ W,
        const float* __restrict__ bias, float* __restrict__ C,
        int M, int N, int K, int ldc, int act, int obf) {
    __shared__ unsigned As[128][20];   // 16 k-words (32 k) + pad
    __shared__ unsigned Bs[64][20];

    int tid = threadIdx.x;
    int bm = blockIdx.y * 128, bn = blockIdx.x * 64;
    int wid = tid >> 5, lane = tid & 31;
    int wm = (wid & 3) * 32, wn = (wid >> 2) * 32;
    int gid = lane >> 2, tig = lane & 3;
    bool k4 = (K & 3) == 0;

    float acc[2][4][4];
#pragma unroll
    for (int i = 0; i < 2; i++)
#pragma unroll
        for (int j = 0; j < 4; j++)
#pragma unroll
            for (int v = 0; v < 4; v++) acc[i][j][v] = 0.f;

    float ra[16], rb[8];

    auto load_stage = [&](int k0) {
#pragma unroll
        for (int j = 0; j < 4; j++) {
            int q = tid + 256 * j;
            int r = q >> 3, c = (q & 7) * 4;
            const float* src = A + (size_t)(bm + r) * K + k0 + c;
            float4 v;
            if (k4 && k0 + c + 3 < K) v = *(const float4*)src;
            else {
                v.x = (k0 + c + 0 < K) ? src[0] : 0.f;
                v.y = (k0 + c + 1 < K) ? src[1] : 0.f;
                v.z = (k0 + c + 2 < K) ? src[2] : 0.f;
                v.w = (k0 + c + 3 < K) ? src[3] : 0.f;
            }
            ra[j * 4 + 0] = v.x; ra[j * 4 + 1] = v.y; ra[j * 4 + 2] = v.z; ra[j * 4 + 3] = v.w;
        }
#pragma unroll
        for (int j = 0; j < 2; j++) {
            int q = tid + 256 * j;
            int r = q >> 3, c = (q & 7) * 4;
            float4 v = make_float4(0.f, 0.f, 0.f, 0.f);
            if (bn + r < N) {
                const float* src = W + (size_t)(bn + r) * K + k0 + c;
                if (k4 && k0 + c + 3 < K) v = *(const float4*)src;
                else {
                    v.x = (k0 + c + 0 < K) ? src[0] : 0.f;
                    v.y = (k0 + c + 1 < K) ? src[1] : 0.f;
                    v.z = (k0 + c + 2 < K) ? src[2] : 0.f;
                    v.w = (k0 + c + 3 < K) ? src[3] : 0.f;
                }
            }
            rb[j * 4 + 0] = v.x; rb[j * 4 + 1] = v.y; rb[j * 4 + 2] = v.z; rb[j * 4 + 3] = v.w;
        }
    };

    load_stage(0);
    for (int k0 = 0; k0 < K; k0 += 32) {
        __syncthreads();
#pragma unroll
        for (int j = 0; j < 4; j++) {
            int q = tid + 256 * j;
            int r = q >> 3, cw = (q & 7) * 2;   // word col 0,2,..,14
            *(uint2*)&As[r][cw] = make_uint2(pk2(ra[j*4+0], ra[j*4+1]), pk2(ra[j*4+2], ra[j*4+3]));
        }
#pragma unroll
        for (int j = 0; j < 2; j++) {
            int q = tid + 256 * j;
            int r = q >> 3, cw = (q & 7) * 2;
            *(uint2*)&Bs[r][cw] = make_uint2(pk2(rb[j*4+0], rb[j*4+1]), pk2(rb[j*4+2], rb[j*4+3]));
        }
        __syncthreads();
        if (k0 + 32 < K) load_stage(k0 + 32);

#pragma unroll
        for (int ks = 0; ks < 2; ks++) {
            int kw = ks * 8;
            unsigned af[2][4], bf[4][2];
#pragma unroll
            for (int im = 0; im < 2; im++) {
                int rm = wm + im * 16;
                af[im][0] = As[rm + gid][kw + tig];
                af[im][1] = As[rm + gid + 8][kw + tig];
                af[im][2] = As[rm + gid][kw + tig + 4];
                af[im][3] = As[rm + gid + 8][kw + tig + 4];
            }
#pragma unroll
            for (int jn = 0; jn < 4; jn++) {
                int cn = wn + jn * 8;
                bf[jn][0] = Bs[cn + gid][kw + tig];
                bf[jn][1] = Bs[cn + gid][kw + tig + 4];
            }
#pragma unroll
            for (int im = 0; im < 2; im++)
#pragma unroll
                for (int jn = 0; jn < 4; jn++)
                    mma_bf16(acc[im][jn], af[im], bf[jn]);
        }
    }

#pragma unroll
    for (int im = 0; im < 2; im++) {
#pragma unroll
        for (int jn = 0; jn < 4; jn++) {
            int row0 = bm + wm + im * 16 + gid;
            int col0 = bn + wn + jn * 8 + tig * 2;
#pragma unroll
            for (int half = 0; half < 2; half++) {
                int row = row0 + half * 8;
#pragma unroll
                for (int cc = 0; cc < 2; cc++) {
                    int col = col0 + cc;
                    if (col >= N) continue;
                    float v = acc[im][jn][half * 2 + cc];
                    if (bias) v += bias[col];
                    if (act) v = sp_(v);
                    if (obf) ((__nv_bfloat16*)C)[(size_t)row * ldc + col] = __float2bfloat16(v);
                    else C[(size_t)row * ldc + col] = v;
                }
            }
        }
    }
}

// ---------------- persistent recurrence (bf16 tensor cores) ----------------
struct RP {
    const float* whhp;
    const __nv_bfloat16* xpre;
    float* hbuf;
    const int* len_char;
    const int* len_word;
    float* outc;
    float* outw;
};

__device__ __forceinline__ void grid_bar(unsigned target) {
    __threadfence();
    __syncthreads();
    if (threadIdx.x == 0) {
        if (atomicAdd(&g_arr, 1u) == NBLK - 1) {
            g_arr = 0;
            __threadfence();
            g_gen = target;
        } else {
            while (g_gen < target) __nanosleep(64);
        }
    }
    __syncthreads();
}

// smem: Ws [64][132] words + As [64][132] words
#define REC_SMEM ((64*132 + 64*132) * 4)

__global__ void __launch_bounds__(256, 2) k_rec_persist(RP p) {
    extern __shared__ unsigned smu[];
    unsigned* Ws = smu;                 // [64][132] bf16x2 words (256 k = 128 words)
    unsigned* As = smu + 64 * 132;      // [64][132]

    int bx = blockIdx.x;
    int dir = bx >> 6, mb = (bx >> 4) & 3, nb = bx & 15;
    int tid = threadIdx.x;
    int wid = tid >> 5, lane = tid & 31;
    int gid = lane >> 2, tig = lane & 3;
    int wm = (wid & 3) * 16;
    int wnh = wid >> 2;
    int bm = mb * 64;

    // load + pack Whh tile for this block's 64 gate-columns
    const float* W = p.whhp + (size_t)dir * 1024 * 256;
    for (int idx = tid; idx < 64 * 128; idx += 256) {
        int n = idx >> 7, kw = idx & 127;
        float2 v = *(const float2*)&W[(size_t)(nb * 64 + n) * 256 + kw * 2];
        Ws[n * 132 + kw] = pk2(v.x, v.y);
    }

    float hreg[2][2], creg[2][2];
#pragma unroll
    for (int i = 0; i < 2; i++)
#pragma unroll
        for (int j = 0; j < 2; j++) { hreg[i][j] = 0.f; creg[i][j] = 0.f; }

    const int* lens = (dir < 2) ? p.len_char : p.len_word;
    int lenv[2];
    lenv[0] = lens[bm + wm + gid];
    lenv[1] = lens[bm + wm + gid + 8];

    float* hb0 = p.hbuf + (size_t)dir * 2 * 65536;
    float* hb1 = hb0 + 65536;
    const __nv_bfloat16* xp = p.xpre + (size_t)dir * XPD;
    float* outp = (dir < 2) ? p.outc : p.outw;
    int half = (dir & 1) ? 256 : 0;
    int cn0 = nb * 64 + wnh * 32;

    __syncthreads();

    for (int t = 0; t < TT; t++) {
        int tr = (dir & 1) ? (TT - 1 - t) : t;
        const float* h = (t & 1) ? hb1 : hb0;
        float* hn_buf = (t & 1) ? hb0 : hb1;

        // stage full h tile [64 rows][256 k] as packed bf16
        // 64 rows x 64 float4-slots = 4096 slots; 16 per thread
#pragma unroll
        for (int j = 0; j < 16; j++) {
            int q = tid + 256 * j;
            int r = q >> 6, c4 = q & 63;
            float4 v = __ldcg((const float4*)&h[(bm + r) * 256 + c4 * 4]);
            *(uint2*)&As[r * 132 + c4 * 2] = make_uint2(pk2(v.x, v.y), pk2(v.z, v.w));
        }
        __syncthreads();

        float acc[4][4];
#pragma unroll
        for (int j = 0; j < 4; j++)
#pragma unroll
            for (int v = 0; v < 4; v++) acc[j][v] = 0.f;

#pragma unroll
        for (int ks = 0; ks < 16; ks++) {
            int kw = ks * 8;
            unsigned af[4], bf[4][2];
            af[0] = As[(wm + gid) * 132 + kw + tig];
            af[1] = As[(wm + gid + 8) * 132 + kw + tig];
            af[2] = As[(wm + gid) * 132 + kw + tig + 4];
            af[3] = As[(wm + gid + 8) * 132 + kw + tig + 4];
#pragma unroll
            for (int jn = 0; jn < 4; jn++) {
                int n0 = wnh * 32 + jn * 8;
                bf[jn][0] = Ws[(n0 + gid) * 132 + kw + tig];
                bf[jn][1] = Ws[(n0 + gid) * 132 + kw + tig + 4];
            }
#pragma unroll
            for (int jn = 0; jn < 4; jn++)
                mma_bf16(acc[jn], af, bf[jn]);
        }

        // fused LSTM cell epilogue
        const __nv_bfloat16* xrow = xp + (size_t)tr * BB * 1024;
#pragma unroll
        for (int rh = 0; rh < 2; rh++) {
            int b = bm + wm + gid + rh * 8;
            bool valid = tr < lenv[rh];
#pragma unroll
            for (int pp = 0; pp < 2; pp++) {
                float2 x01 = __bfloat1622float2(
                    *(const __nv_bfloat162*)&xrow[(size_t)b * 1024 + cn0 + pp * 16 + tig * 2]);
                float2 x23 = __bfloat1622float2(
                    *(const __nv_bfloat162*)&xrow[(size_t)b * 1024 + cn0 + pp * 16 + 8 + tig * 2]);
                float gi = acc[2 * pp + 0][rh * 2 + 0] + x01.x;
                float gf = acc[2 * pp + 0][rh * 2 + 1] + x01.y;
                float gc = acc[2 * pp + 1][rh * 2 + 0] + x23.x;
                float go = acc[2 * pp + 1][rh * 2 + 1] + x23.y;
                float cn = sg_(gf) * creg[rh][pp] + sg_(gi) * tanhf(gc);
                float hv = sg_(go) * tanhf(cn);
                if (valid) { creg[rh][pp] = cn; hreg[rh][pp] = hv; }
                int u = nb * 16 + wnh * 8 + pp * 4 + tig;
                outp[((size_t)b * TT + tr) * 512 + half + u] = valid ? hv : 0.f;
                hn_buf[b * 256 + u] = hreg[rh][pp];
            }
        }

        grid_bar((unsigned)(t + 1));
    }
}

// ---------------- CRF: real path score (one warp per batch, deterministic) ----------------
__global__ void k_crf_real(const float* __restrict__ logits, const int* __restrict__ tags,
                           const int* __restrict__ lens, const float* __restrict__ trans,
                           float* __restrict__ rl) {
    __shared__ float st[144];
    int tid = threadIdx.x;
    if (tid < 144) st[tid] = trans[tid];
    __syncthreads();
    int warp = tid >> 5, lane = tid & 31;
    int b = blockIdx.x * 8 + warp;
    int len = lens[b];
    float s = 0.f;
    for (int t = lane; t < len; t += 32) {
        int tg = tags[b * TT + t];
        int prev = (t == 0) ? 10 : tags[b * TT + t - 1];
        s += logits[((size_t)b * TT + t) * 12 + tg] + st[prev * 12 + tg];
    }
#pragma unroll
    for (int o = 16; o > 0; o >>= 1) s += __shfl_xor_sync(0xffffffffu, s, o);
    if (lane == 0) {
        int last = tags[b * TT + len - 1];
        rl[b] = s + st[last * 12 + 11];
    }
}

// ---------------- CRF forward: one warp per batch ----------------
__global__ void k_crf_fwd(const float* __restrict__ logits, const int* __restrict__ lens,
                          const float* __restrict__ trans, float* __restrict__ tot) {
    __shared__ float st[144];
    int tid = threadIdx.x;
    if (tid < 144) st[tid] = trans[tid];
    __syncthreads();
    int warp = tid >> 5, lane = tid & 31;
    int b = blockIdx.x * 8 + warp;
    int len = lens[b];
    float alpha = 0.f;
    for (int t = 0; t < TT; t++) {
        float lt = (lane < 12) ? logits[((size_t)b * TT + t) * 12 + lane] : 0.f;
        float sc[12];
        float mx = -1e30f;
#pragma unroll
        for (int i = 0; i < 12; i++) {
            float ai = __shfl_sync(0xffffffffu, alpha, i);
            float s = ai + ((lane < 12) ? st[i * 12 + lane] : 0.f);
            sc[i] = s;
            mx = fmaxf(mx, s);
        }
        float sm = 0.f;
#pragma unroll
        for (int i = 0; i < 12; i++) sm += expf(sc[i] - mx);
        float an = mx + logf(sm) + lt;
        if (t < len) alpha = an;
    }
    float v = (lane < 12) ? alpha + st[lane * 12 + 11] : -1e30f;
    float mx = v;
#pragma unroll
    for (int o = 16; o > 0; o >>= 1) mx = fmaxf(mx, __shfl_xor_sync(0xffffffffu, mx, o));
    float e = expf(v - mx);
#pragma unroll
    for (int o = 16; o > 0; o >>= 1) e += __shfl_xor_sync(0xffffffffu, e, o);
    if (lane == 0) tot[b] = mx + logf(e);
}

__global__ void k_crf_reduce(const float* __restrict__ crf, float* __restrict__ out) {
    __shared__ float s[256];
    int t = threadIdx.x;
    s[t] = crf[t] - crf[256 + t];
    __syncthreads();
    for (int o = 128; o > 0; o >>= 1) {
        if (t < o) s[t] += s[t + o];
        __syncthreads();
    }
    if (t == 0) out[0] = s[0];
}

// ---------------- launch ----------------
extern "C" void kernel_launch(void* const* d_in, const int* in_sizes, int n_in,
                              void* d_out, int out_size) {
    const int*   characters = (const int*)d_in[0];
    const float* words      = (const float*)d_in[1];
    const int*   tags       = (const int*)d_in[2];
    const int*   len_char   = (const int*)d_in[3];
    const int*   len_word   = (const int*)d_in[4];
    const float* char_emb   = (const float*)d_in[5];
    const float* cWihf = (const float*)d_in[6];
    const float* cWhhf = (const float*)d_in[7];
    const float* cbf   = (const float*)d_in[8];
    const float* cWihb = (const float*)d_in[9];
    const float* cWhhb = (const float*)d_in[10];
    const float* cbb   = (const float*)d_in[11];
    const float* clinW = (const float*)d_in[12];
    const float* clinb = (const float*)d_in[13];
    const float* wWihf = (const float*)d_in[14];
    const float* wWhhf = (const float*)d_in[15];
    const float* wbf   = (const float*)d_in[16];
    const float* wWihb = (const float*)d_in[17];
    const float* wWhhb = (const float*)d_in[18];
    const float* wbb   = (const float*)d_in[19];
    const float* wlinW = (const float*)d_in[20];
    const float* wlinb = (const float*)d_in[21];
    const float* l1W   = (const float*)d_in[22];
    const float* l1b   = (const float*)d_in[23];
    const float* l2W   = (const float*)d_in[24];
    const float* l2b   = (const float*)d_in[25];
    const float* tW    = (const float*)d_in[26];
    const float* tb    = (const float*)d_in[27];
    const float* trans = (const float*)d_in[28];
    float* out = (float*)d_out;

    float *char_x, *word_x, *whhp, *cihp, *wihp, *bp, *hbuf;
    float *char_h, *word_h, *xcat, *buf1, *buf2, *logits, *crfb;
    __nv_bfloat16* xpre;
    cudaGetSymbolAddress((void**)&char_x, d_char_x);
    cudaGetSymbolAddress((void**)&word_x, d_word_x);
    cudaGetSymbolAddress((void**)&xpre,   d_xpre);
    cudaGetSymbolAddress((void**)&whhp,   d_whhp);
    cudaGetSymbolAddress((void**)&cihp,   d_cihp);
    cudaGetSymbolAddress((void**)&wihp,   d_wihp);
    cudaGetSymbolAddress((void**)&bp,     d_bp);
    cudaGetSymbolAddress((void**)&hbuf,   d_hbuf);
    cudaGetSymbolAddress((void**)&char_h, d_char_h);
    cudaGetSymbolAddress((void**)&word_h, d_word_h);
    cudaGetSymbolAddress((void**)&xcat,   d_xcat);
    cudaGetSymbolAddress((void**)&buf1,   d_buf1);
    cudaGetSymbolAddress((void**)&buf2,   d_buf2);
    cudaGetSymbolAddress((void**)&logits, d_logits);
    cudaGetSymbolAddress((void**)&crfb,   d_crf);

    cudaFuncSetAttribute(k_rec_persist, cudaFuncAttributeMaxDynamicSharedMemorySize, REC_SMEM);

    k_init<<<(4 * 2 * BB * 256 + 255) / 256, 256>>>(hbuf);

    k_perm_w<<<(1024 * 256 + 255) / 256, 256>>>(cWhhf, whhp + 0 * 1024 * 256, 256);
    k_perm_w<<<(1024 * 256 + 255) / 256, 256>>>(cWhhb, whhp + 1 * 1024 * 256, 256);
    k_perm_w<<<(1024 * 256 + 255) / 256, 256>>>(wWhhf, whhp + 2 * 1024 * 256, 256);
    k_perm_w<<<(1024 * 256 + 255) / 256, 256>>>(wWhhb, whhp + 3 * 1024 * 256, 256);
    k_perm_w<<<(1024 * 30 + 255) / 256, 256>>>(cWihf, cihp + 0 * 1024 * 30, 30);
    k_perm_w<<<(1024 * 30 + 255) / 256, 256>>>(cWihb, cihp + 1 * 1024 * 30, 30);
    k_perm_w<<<(1024 * 128 + 255) / 256, 256>>>(wWihf, wihp + 0 * 1024 * 128, 128);
    k_perm_w<<<(1024 * 128 + 255) / 256, 256>>>(wWihb, wihp + 1 * 1024 * 128, 128);
    k_perm_b<<<4, 256>>>(cbf, bp + 0 * 1024);
    k_perm_b<<<4, 256>>>(cbb, bp + 1 * 1024);
    k_perm_b<<<4, 256>>>(wbf, bp + 2 * 1024);
    k_perm_b<<<4, 256>>>(wbb, bp + 3 * 1024);

    k_gather_char<<<(TT * BB * 30 + 255) / 256, 256>>>(characters, char_emb, char_x);
    k_transpose_word<<<(TT * BB * 128 + 255) / 256, 256>>>(words, word_x);

    int Mbt = BB * TT;  // 51200
    auto grid = [](int M, int N) { return dim3((unsigned)((N + 63) / 64), (unsigned)((M + 127) / 128)); };

    // input projections -> bf16 xpre (mma-permuted columns)
    k_gemm_tc<<<grid(Mbt, 1024), 256>>>(char_x, cihp + 0 * 1024 * 30,  bp + 0 * 1024, (float*)(xpre + 0 * (size_t)XPD), Mbt, 1024, 30, 1024, 0, 1);
    k_gemm_tc<<<grid(Mbt, 1024), 256>>>(char_x, cihp + 1 * 1024 * 30,  bp + 1 * 1024, (float*)(xpre + 1 * (size_t)XPD), Mbt, 1024, 30, 1024, 0, 1);
    k_gemm_tc<<<grid(Mbt, 1024), 256>>>(word_x, wihp + 0 * 1024 * 128, bp + 2 * 1024, (float*)(xpre + 2 * (size_t)XPD), Mbt, 1024, 128, 1024, 0, 1);
    k_gemm_tc<<<grid(Mbt, 1024), 256>>>(word_x, wihp + 1 * 1024 * 128, bp + 3 * 1024, (float*)(xpre + 3 * (size_t)XPD), Mbt, 1024, 128, 1024, 0, 1);

    RP rp;
    rp.whhp = whhp;
    rp.xpre = xpre;
    rp.hbuf = hbuf;
    rp.len_char = len_char;
    rp.len_word = len_word;
    rp.outc = char_h;
    rp.outw = word_h;
    k_rec_persist<<<NBLK, 256, REC_SMEM>>>(rp);

    // dense stack (bf16 mma, softplus fused, fp32 buffers)
    k_gemm_tc<<<grid(Mbt, 512), 256>>>(char_h, clinW, clinb, xcat,       Mbt, 512, 512, 712, 1, 0);
    k_gemm_tc<<<grid(Mbt, 200), 256>>>(word_h, wlinW, wlinb, xcat + 512, Mbt, 200, 512, 712, 1, 0);
    k_gemm_tc<<<grid(Mbt, 512), 256>>>(xcat, l1W, l1b, buf1,   Mbt, 512, 712, 512, 1, 0);
    k_gemm_tc<<<grid(Mbt, 256), 256>>>(buf1, l2W, l2b, buf2,   Mbt, 256, 512, 256, 1, 0);
    k_gemm_tc<<<grid(Mbt, 12),  256>>>(buf2, tW,  tb,  logits, Mbt, 12,  256, 12,  1, 0);

    // CRF
    k_crf_real<<<32, 256>>>(logits, tags, len_char, trans, crfb + BB);
    k_crf_fwd<<<32, 256>>>(logits, len_char, trans, crfb);
    k_crf_reduce<<<1, 256>>>(crfb, out);
}

// round 9
// speedup vs baseline: 4.3834x; 1.0911x over previous
#include <cuda_runtime.h>
#include <cuda_bf16.h>

#define TT 200
#define BB 256
#define XPD (TT*BB*1024)

// ---------------- scratch (device globals: allocation-free) ----------------
__device__ float d_char_x[TT*BB*30];            // [t][b][30]
__device__ float d_word_x[TT*BB*128];           // [w][b][128]
__device__ __nv_bfloat16 d_xpre[4][XPD];        // per-dir input preact, mma-permuted cols (bf16)
__device__ float d_whhp[4][1024*256];           // permuted Whh
__device__ float d_cihp[2][1024*30];            // permuted char Wih
__device__ float d_wihp[2][1024*128];           // permuted word Wih
__device__ float d_bp[4][1024];                 // permuted biases
__device__ float d_hbuf[4*2*BB*256];            // ping-pong h per dir (fp32)
__device__ __nv_bfloat16 d_char_h[BB*TT*512];   // [b][t][512] bf16
__device__ __nv_bfloat16 d_word_h[BB*TT*512];   // [b][w][512] bf16
__device__ __nv_bfloat16 d_xcat[BB*TT*712];     // concat bf16
__device__ __nv_bfloat16 d_buf1[BB*TT*512];
__device__ __nv_bfloat16 d_buf2[BB*TT*256];
__device__ float d_logits[BB*TT*12];
__device__ float d_crf[2*BB];

__device__ unsigned g_arrs[4];
__device__ volatile unsigned g_gens[4];

__device__ __forceinline__ float sp_(float x) { return fmaxf(x, 0.f) + log1pf(expf(-fabsf(x))); }
__device__ __forceinline__ float sg_(float x) { return 1.f / (1.f + expf(-x)); }

// pack two fp32 -> bf16x2 word (lo = first element)
__device__ __forceinline__ unsigned pk2(float lo, float hi) {
    unsigned r;
    asm("cvt.rn.bf16x2.f32 %0, %1, %2;" : "=r"(r) : "f"(hi), "f"(lo));
    return r;
}

__device__ __forceinline__ void mma_bf16(float* d, const unsigned* a, const unsigned* b) {
    asm volatile(
        "mma.sync.aligned.m16n8k16.row.col.f32.bf16.bf16.f32 "
        "{%0,%1,%2,%3}, {%4,%5,%6,%7}, {%8,%9}, {%0,%1,%2,%3};\n"
        : "+f"(d[0]), "+f"(d[1]), "+f"(d[2]), "+f"(d[3])
        : "r"(a[0]), "r"(a[1]), "r"(a[2]), "r"(a[3]), "r"(b[0]), "r"(b[1]));
}

// mma-friendly gate-column permutation: (g,u) -> permuted row index
__device__ __forceinline__ int perm_gu(int g, int u) {
    int nb = u >> 4, w16 = u & 15;
    int h = w16 >> 3, v = w16 & 7;
    int p = v >> 2, t = v & 3;
    return nb * 64 + h * 32 + p * 16 + ((g >> 1) << 3) + t * 2 + (g & 1);
}

// ---------------- small utility kernels ----------------
__global__ void k_init(float* hbuf) {
    int i = blockIdx.x * blockDim.x + threadIdx.x;
    if (i < 4) { g_arrs[i] = 0; g_gens[i] = 0; }
    if (i < 4 * 2 * BB * 256) hbuf[i] = 0.f;
}

__global__ void k_gather_char(const int* __restrict__ chars, const float* __restrict__ emb,
                              float* __restrict__ out) {
    int i = blockIdx.x * blockDim.x + threadIdx.x;
    if (i >= TT * BB * 30) return;
    int k = i % 30, tb = i / 30;
    int b = tb % BB, t = tb / BB;
    out[i] = emb[chars[b * TT + t] * 30 + k];
}

__global__ void k_transpose_word(const float* __restrict__ words, float* __restrict__ out) {
    int i = blockIdx.x * blockDim.x + threadIdx.x;
    if (i >= TT * BB * 128) return;
    int k = i & 127, wb = i >> 7;
    int b = wb % BB, w = wb / BB;
    out[i] = words[((size_t)b * TT + w) * 128 + k];
}

__global__ void k_perm_w(const float* __restrict__ src, float* __restrict__ dst, int K) {
    int i = blockIdx.x * blockDim.x + threadIdx.x;
    if (i >= 1024 * K) return;
    int k = i % K, s = i / K;
    int g = s >> 8, u = s & 255;
    dst[(size_t)perm_gu(g, u) * K + k] = src[(size_t)s * K + k];
}

__global__ void k_perm_b(const float* __restrict__ src, float* __restrict__ dst) {
    int s = blockIdx.x * blockDim.x + threadIdx.x;
    if (s >= 1024) return;
    int g = s >> 8, u = s & 255;
    dst[perm_gu(g, u)] = src[s];
}

// ---------------- BF16 tensor-core GEMM: C = act(A[M,K] @ W[N,K]^T + bias) ----------------
// block 128(M) x 64(N); 8 warps each 32x32 via m16n8k16 bf16 mma, fp32 accum.
// abf: A is bf16 (else fp32).  obf: write bf16 output (else fp32).
// M must be a multiple of 128 (callers use M=51200).
__global__ void __launch_bounds__(256) k_gemm_tc(
        const void* __restrict__ Av, const float* __restrict__ W,
        const float* __restrict__ bias, float* __restrict__ C,
        int M, int N, int K, int ldc, int act, int abf, int obf) {
    __shared__ unsigned As[128][20];   // 16 k-words (32 k) + pad
    __shared__ unsigned Bs[64][20];

    int tid = threadIdx.x;
    int bm = blockIdx.y * 128, bn = blockIdx.x * 64;
    int wid = tid >> 5, lane = tid & 31;
    int wm = (wid & 3) * 32, wn = (wid >> 2) * 32;
    int gid = lane >> 2, tig = lane & 3;
    bool k4 = (K & 3) == 0;

    float acc[2][4][4];
#pragma unroll
    for (int i = 0; i < 2; i++)
#pragma unroll
        for (int j = 0; j < 4; j++)
#pragma unroll
            for (int v = 0; v < 4; v++) acc[i][j][v] = 0.f;

    float ra[16];      // fp32 A staging
    uint4 rau[2];      // bf16 A staging
    float rb[8];

    auto load_stage = [&](int k0) {
        if (abf) {
            const __nv_bfloat16* Ab = (const __nv_bfloat16*)Av;
#pragma unroll
            for (int j = 0; j < 2; j++) {
                int q = tid + 256 * j;
                int r = q >> 2, cw4 = (q & 3) * 4;      // 4 words = 8 bf16
                int ke = k0 + cw4 * 2;
                const __nv_bfloat16* src = Ab + (size_t)(bm + r) * K + ke;
                if (ke + 8 <= K) rau[j] = *(const uint4*)src;
                else {
                    unsigned w[4] = {0u, 0u, 0u, 0u};
#pragma unroll
                    for (int e = 0; e < 8; e++)
                        if (ke + e < K) ((__nv_bfloat16*)w)[e] = src[e];
                    rau[j] = make_uint4(w[0], w[1], w[2], w[3]);
                }
            }
        } else {
            const float* A = (const float*)Av;
#pragma unroll
            for (int j = 0; j < 4; j++) {
                int q = tid + 256 * j;
                int r = q >> 3, c = (q & 7) * 4;
                const float* src = A + (size_t)(bm + r) * K + k0 + c;
                float4 v;
                if (k4 && k0 + c + 3 < K) v = *(const float4*)src;
                else {
                    v.x = (k0 + c + 0 < K) ? src[0] : 0.f;
                    v.y = (k0 + c + 1 < K) ? src[1] : 0.f;
                    v.z = (k0 + c + 2 < K) ? src[2] : 0.f;
                    v.w = (k0 + c + 3 < K) ? src[3] : 0.f;
                }
                ra[j * 4 + 0] = v.x; ra[j * 4 + 1] = v.y; ra[j * 4 + 2] = v.z; ra[j * 4 + 3] = v.w;
            }
        }
#pragma unroll
        for (int j = 0; j < 2; j++) {
            int q = tid + 256 * j;
            int r = q >> 3, c = (q & 7) * 4;
            float4 v = make_float4(0.f, 0.f, 0.f, 0.f);
            if (bn + r < N) {
                const float* src = W + (size_t)(bn + r) * K + k0 + c;
                if (k4 && k0 + c + 3 < K) v = *(const float4*)src;
                else {
                    v.x = (k0 + c + 0 < K) ? src[0] : 0.f;
                    v.y = (k0 + c + 1 < K) ? src[1] : 0.f;
                    v.z = (k0 + c + 2 < K) ? src[2] : 0.f;
                    v.w = (k0 + c + 3 < K) ? src[3] : 0.f;
                }
            }
            rb[j * 4 + 0] = v.x; rb[j * 4 + 1] = v.y; rb[j * 4 + 2] = v.z; rb[j * 4 + 3] = v.w;
        }
    };

    load_stage(0);
    for (int k0 = 0; k0 < K; k0 += 32) {
        __syncthreads();
        if (abf) {
#pragma unroll
            for (int j = 0; j < 2; j++) {
                int q = tid + 256 * j;
                int r = q >> 2, cw4 = (q & 3) * 4;
                *(uint4*)&As[r][cw4] = rau[j];
            }
        } else {
#pragma unroll
            for (int j = 0; j < 4; j++) {
                int q = tid + 256 * j;
                int r = q >> 3, cw = (q & 7) * 2;
                *(uint2*)&As[r][cw] = make_uint2(pk2(ra[j*4+0], ra[j*4+1]), pk2(ra[j*4+2], ra[j*4+3]));
            }
        }
#pragma unroll
        for (int j = 0; j < 2; j++) {
            int q = tid + 256 * j;
            int r = q >> 3, cw = (q & 7) * 2;
            *(uint2*)&Bs[r][cw] = make_uint2(pk2(rb[j*4+0], rb[j*4+1]), pk2(rb[j*4+2], rb[j*4+3]));
        }
        __syncthreads();
        if (k0 + 32 < K) load_stage(k0 + 32);

#pragma unroll
        for (int ks = 0; ks < 2; ks++) {
            int kw = ks * 8;
            unsigned af[2][4], bf[4][2];
#pragma unroll
            for (int im = 0; im < 2; im++) {
                int rm = wm + im * 16;
                af[im][0] = As[rm + gid][kw + tig];
                af[im][1] = As[rm + gid + 8][kw + tig];
                af[im][2] = As[rm + gid][kw + tig + 4];
                af[im][3] = As[rm + gid + 8][kw + tig + 4];
            }
#pragma unroll
            for (int jn = 0; jn < 4; jn++) {
                int cn = wn + jn * 8;
                bf[jn][0] = Bs[cn + gid][kw + tig];
                bf[jn][1] = Bs[cn + gid][kw + tig + 4];
            }
#pragma unroll
            for (int im = 0; im < 2; im++)
#pragma unroll
                for (int jn = 0; jn < 4; jn++)
                    mma_bf16(acc[im][jn], af[im], bf[jn]);
        }
    }

#pragma unroll
    for (int im = 0; im < 2; im++) {
#pragma unroll
        for (int jn = 0; jn < 4; jn++) {
            int row0 = bm + wm + im * 16 + gid;
            int col0 = bn + wn + jn * 8 + tig * 2;
#pragma unroll
            for (int half = 0; half < 2; half++) {
                int row = row0 + half * 8;
                if (obf) {
                    if (col0 < N) {   // N even, col0 even -> pair fully in-bounds
                        float v0 = acc[im][jn][half * 2 + 0];
                        float v1 = acc[im][jn][half * 2 + 1];
                        if (bias) { v0 += bias[col0]; v1 += bias[col0 + 1]; }
                        if (act) { v0 = sp_(v0); v1 = sp_(v1); }
                        *(unsigned*)(((__nv_bfloat16*)C) + (size_t)row * ldc + col0) = pk2(v0, v1);
                    }
                } else {
#pragma unroll
                    for (int cc = 0; cc < 2; cc++) {
                        int col = col0 + cc;
                        if (col >= N) continue;
                        float v = acc[im][jn][half * 2 + cc];
                        if (bias) v += bias[col];
                        if (act) v = sp_(v);
                        C[(size_t)row * ldc + col] = v;
                    }
                }
            }
        }
    }
}

// ---------------- persistent recurrence (bf16 tensor cores) ----------------
struct RP {
    const float* whhp;
    const __nv_bfloat16* xpre;
    float* hbuf;
    const int* len_char;
    const int* len_word;
    __nv_bfloat16* outc;
    __nv_bfloat16* outw;
};

// per-direction barrier over 64 blocks
__device__ __forceinline__ void grid_bar(int dir, unsigned target) {
    __threadfence();
    __syncthreads();
    if (threadIdx.x == 0) {
        if (atomicAdd(&g_arrs[dir], 1u) == 63u) {
            g_arrs[dir] = 0;
            __threadfence();
            g_gens[dir] = target;
        } else {
            while (g_gens[dir] < target) __nanosleep(32);
        }
    }
    __syncthreads();
}

// smem: Ws [64][132] words + As [64][132] words
#define REC_SMEM ((64*132 + 64*132) * 4)

__global__ void __launch_bounds__(256, 2) k_rec_persist(RP p) {
    extern __shared__ unsigned smu[];
    unsigned* Ws = smu;                 // [64][132] bf16x2 words (256 k = 128 words)
    unsigned* As = smu + 64 * 132;      // [64][132]

    int bx = blockIdx.x;
    int dir = bx >> 6, mb = (bx >> 4) & 3, nb = bx & 15;
    int tid = threadIdx.x;
    int wid = tid >> 5, lane = tid & 31;
    int gid = lane >> 2, tig = lane & 3;
    int wm = (wid & 3) * 16;
    int wnh = wid >> 2;
    int bm = mb * 64;

    // load + pack Whh tile for this block's 64 gate-columns
    const float* W = p.whhp + (size_t)dir * 1024 * 256;
    for (int idx = tid; idx < 64 * 128; idx += 256) {
        int n = idx >> 7, kw = idx & 127;
        float2 v = *(const float2*)&W[(size_t)(nb * 64 + n) * 256 + kw * 2];
        Ws[n * 132 + kw] = pk2(v.x, v.y);
    }

    float hreg[2][2], creg[2][2];
#pragma unroll
    for (int i = 0; i < 2; i++)
#pragma unroll
        for (int j = 0; j < 2; j++) { hreg[i][j] = 0.f; creg[i][j] = 0.f; }

    const int* lens = (dir < 2) ? p.len_char : p.len_word;
    int lenv[2];
    lenv[0] = lens[bm + wm + gid];
    lenv[1] = lens[bm + wm + gid + 8];

    float* hb0 = p.hbuf + (size_t)dir * 2 * 65536;
    float* hb1 = hb0 + 65536;
    const __nv_bfloat16* xp = p.xpre + (size_t)dir * XPD;
    __nv_bfloat16* outp = (dir < 2) ? p.outc : p.outw;
    int half = (dir & 1) ? 256 : 0;
    int cn0 = nb * 64 + wnh * 32;

    __syncthreads();

    for (int t = 0; t < TT; t++) {
        int tr = (dir & 1) ? (TT - 1 - t) : t;
        const float* h = (t & 1) ? hb1 : hb0;
        float* hn_buf = (t & 1) ? hb0 : hb1;

        // stage full h tile [64 rows][256 k] as packed bf16: 4096 float4 slots, 16/thread
#pragma unroll
        for (int j = 0; j < 16; j++) {
            int q = tid + 256 * j;
            int r = q >> 6, c4 = q & 63;
            float4 v = __ldcg((const float4*)&h[(bm + r) * 256 + c4 * 4]);
            *(uint2*)&As[r * 132 + c4 * 2] = make_uint2(pk2(v.x, v.y), pk2(v.z, v.w));
        }
        __syncthreads();

        float acc[4][4];
#pragma unroll
        for (int j = 0; j < 4; j++)
#pragma unroll
            for (int v = 0; v < 4; v++) acc[j][v] = 0.f;

#pragma unroll
        for (int ks = 0; ks < 16; ks++) {
            int kw = ks * 8;
            unsigned af[4], bf[4][2];
            af[0] = As[(wm + gid) * 132 + kw + tig];
            af[1] = As[(wm + gid + 8) * 132 + kw + tig];
            af[2] = As[(wm + gid) * 132 + kw + tig + 4];
            af[3] = As[(wm + gid + 8) * 132 + kw + tig + 4];
#pragma unroll
            for (int jn = 0; jn < 4; jn++) {
                int n0 = wnh * 32 + jn * 8;
                bf[jn][0] = Ws[(n0 + gid) * 132 + kw + tig];
                bf[jn][1] = Ws[(n0 + gid) * 132 + kw + tig + 4];
            }
#pragma unroll
            for (int jn = 0; jn < 4; jn++)
                mma_bf16(acc[jn], af, bf[jn]);
        }

        // fused LSTM cell epilogue
        const __nv_bfloat16* xrow = xp + (size_t)tr * BB * 1024;
#pragma unroll
        for (int rh = 0; rh < 2; rh++) {
            int b = bm + wm + gid + rh * 8;
            bool valid = tr < lenv[rh];
#pragma unroll
            for (int pp = 0; pp < 2; pp++) {
                float2 x01 = __bfloat1622float2(
                    *(const __nv_bfloat162*)&xrow[(size_t)b * 1024 + cn0 + pp * 16 + tig * 2]);
                float2 x23 = __bfloat1622float2(
                    *(const __nv_bfloat162*)&xrow[(size_t)b * 1024 + cn0 + pp * 16 + 8 + tig * 2]);
                float gi = acc[2 * pp + 0][rh * 2 + 0] + x01.x;
                float gf = acc[2 * pp + 0][rh * 2 + 1] + x01.y;
                float gc = acc[2 * pp + 1][rh * 2 + 0] + x23.x;
                float go = acc[2 * pp + 1][rh * 2 + 1] + x23.y;
                float cn = sg_(gf) * creg[rh][pp] + sg_(gi) * tanhf(gc);
                float hv = sg_(go) * tanhf(cn);
                if (valid) { creg[rh][pp] = cn; hreg[rh][pp] = hv; }
                int u = nb * 16 + wnh * 8 + pp * 4 + tig;
                outp[((size_t)b * TT + tr) * 512 + half + u] = __float2bfloat16(valid ? hv : 0.f);
                hn_buf[b * 256 + u] = hreg[rh][pp];
            }
        }

        if (t + 1 < TT) grid_bar(dir, (unsigned)(t + 1));
    }
}

// ---------------- CRF: real path score (one warp per batch, deterministic) ----------------
__global__ void k_crf_real(const float* __restrict__ logits, const int* __restrict__ tags,
                           const int* __restrict__ lens, const float* __restrict__ trans,
                           float* __restrict__ rl) {
    __shared__ float st[144];
    int tid = threadIdx.x;
    if (tid < 144) st[tid] = trans[tid];
    __syncthreads();
    int warp = tid >> 5, lane = tid & 31;
    int b = blockIdx.x * 8 + warp;
    int len = lens[b];
    float s = 0.f;
    for (int t = lane; t < len; t += 32) {
        int tg = tags[b * TT + t];
        int prev = (t == 0) ? 10 : tags[b * TT + t - 1];
        s += logits[((size_t)b * TT + t) * 12 + tg] + st[prev * 12 + tg];
    }
#pragma unroll
    for (int o = 16; o > 0; o >>= 1) s += __shfl_xor_sync(0xffffffffu, s, o);
    if (lane == 0) {
        int last = tags[b * TT + len - 1];
        rl[b] = s + st[last * 12 + 11];
    }
}

// ---------------- CRF forward: one warp per batch ----------------
__global__ void k_crf_fwd(const float* __restrict__ logits, const int* __restrict__ lens,
                          const float* __restrict__ trans, float* __restrict__ tot) {
    __shared__ float st[144];
    int tid = threadIdx.x;
    if (tid < 144) st[tid] = trans[tid];
    __syncthreads();
    int warp = tid >> 5, lane = tid & 31;
    int b = blockIdx.x * 8 + warp;
    int len = lens[b];
    float alpha = 0.f;
    for (int t = 0; t < TT; t++) {
        float lt = (lane < 12) ? logits[((size_t)b * TT + t) * 12 + lane] : 0.f;
        float sc[12];
        float mx = -1e30f;
#pragma unroll
        for (int i = 0; i < 12; i++) {
            float ai = __shfl_sync(0xffffffffu, alpha, i);
            float s = ai + ((lane < 12) ? st[i * 12 + lane] : 0.f);
            sc[i] = s;
            mx = fmaxf(mx, s);
        }
        float sm = 0.f;
#pragma unroll
        for (int i = 0; i < 12; i++) sm += expf(sc[i] - mx);
        float an = mx + logf(sm) + lt;
        if (t < len) alpha = an;
    }
    float v = (lane < 12) ? alpha + st[lane * 12 + 11] : -1e30f;
    float mx = v;
#pragma unroll
    for (int o = 16; o > 0; o >>= 1) mx = fmaxf(mx, __shfl_xor_sync(0xffffffffu, mx, o));
    float e = expf(v - mx);
#pragma unroll
    for (int o = 16; o > 0; o >>= 1) e += __shfl_xor_sync(0xffffffffu, e, o);
    if (lane == 0) tot[b] = mx + logf(e);
}

__global__ void k_crf_reduce(const float* __restrict__ crf, float* __restrict__ out) {
    __shared__ float s[256];
    int t = threadIdx.x;
    s[t] = crf[t] - crf[256 + t];
    __syncthreads();
    for (int o = 128; o > 0; o >>= 1) {
        if (t < o) s[t] += s[t + o];
        __syncthreads();
    }
    if (t == 0) out[0] = s[0];
}

// ---------------- launch ----------------
extern "C" void kernel_launch(void* const* d_in, const int* in_sizes, int n_in,
                              void* d_out, int out_size) {
    const int*   characters = (const int*)d_in[0];
    const float* words      = (const float*)d_in[1];
    const int*   tags       = (const int*)d_in[2];
    const int*   len_char   = (const int*)d_in[3];
    const int*   len_word   = (const int*)d_in[4];
    const float* char_emb   = (const float*)d_in[5];
    const float* cWihf = (const float*)d_in[6];
    const float* cWhhf = (const float*)d_in[7];
    const float* cbf   = (const float*)d_in[8];
    const float* cWihb = (const float*)d_in[9];
    const float* cWhhb = (const float*)d_in[10];
    const float* cbb   = (const float*)d_in[11];
    const float* clinW = (const float*)d_in[12];
    const float* clinb = (const float*)d_in[13];
    const float* wWihf = (const float*)d_in[14];
    const float* wWhhf = (const float*)d_in[15];
    const float* wbf   = (const float*)d_in[16];
    const float* wWihb = (const float*)d_in[17];
    const float* wWhhb = (const float*)d_in[18];
    const float* wbb   = (const float*)d_in[19];
    const float* wlinW = (const float*)d_in[20];
    const float* wlinb = (const float*)d_in[21];
    const float* l1W   = (const float*)d_in[22];
    const float* l1b   = (const float*)d_in[23];
    const float* l2W   = (const float*)d_in[24];
    const float* l2b   = (const float*)d_in[25];
    const float* tW    = (const float*)d_in[26];
    const float* tb    = (const float*)d_in[27];
    const float* trans = (const float*)d_in[28];
    float* out = (float*)d_out;

    float *char_x, *word_x, *whhp, *cihp, *wihp, *bp, *hbuf, *logits, *crfb;
    __nv_bfloat16 *xpre, *char_h, *word_h, *xcat, *buf1, *buf2;
    cudaGetSymbolAddress((void**)&char_x, d_char_x);
    cudaGetSymbolAddress((void**)&word_x, d_word_x);
    cudaGetSymbolAddress((void**)&xpre,   d_xpre);
    cudaGetSymbolAddress((void**)&whhp,   d_whhp);
    cudaGetSymbolAddress((void**)&cihp,   d_cihp);
    cudaGetSymbolAddress((void**)&wihp,   d_wihp);
    cudaGetSymbolAddress((void**)&bp,     d_bp);
    cudaGetSymbolAddress((void**)&hbuf,   d_hbuf);
    cudaGetSymbolAddress((void**)&char_h, d_char_h);
    cudaGetSymbolAddress((void**)&word_h, d_word_h);
    cudaGetSymbolAddress((void**)&xcat,   d_xcat);
    cudaGetSymbolAddress((void**)&buf1,   d_buf1);
    cudaGetSymbolAddress((void**)&buf2,   d_buf2);
    cudaGetSymbolAddress((void**)&logits, d_logits);
    cudaGetSymbolAddress((void**)&crfb,   d_crf);

    cudaFuncSetAttribute(k_rec_persist, cudaFuncAttributeMaxDynamicSharedMemorySize, REC_SMEM);

    k_init<<<(4 * 2 * BB * 256 + 255) / 256, 256>>>(hbuf);

    k_perm_w<<<(1024 * 256 + 255) / 256, 256>>>(cWhhf, whhp + 0 * 1024 * 256, 256);
    k_perm_w<<<(1024 * 256 + 255) / 256, 256>>>(cWhhb, whhp + 1 * 1024 * 256, 256);
    k_perm_w<<<(1024 * 256 + 255) / 256, 256>>>(wWhhf, whhp + 2 * 1024 * 256, 256);
    k_perm_w<<<(1024 * 256 + 255) / 256, 256>>>(wWhhb, whhp + 3 * 1024 * 256, 256);
    k_perm_w<<<(1024 * 30 + 255) / 256, 256>>>(cWihf, cihp + 0 * 1024 * 30, 30);
    k_perm_w<<<(1024 * 30 + 255) / 256, 256>>>(cWihb, cihp + 1 * 1024 * 30, 30);
    k_perm_w<<<(1024 * 128 + 255) / 256, 256>>>(wWihf, wihp + 0 * 1024 * 128, 128);
    k_perm_w<<<(1024 * 128 + 255) / 256, 256>>>(wWihb, wihp + 1 * 1024 * 128, 128);
    k_perm_b<<<4, 256>>>(cbf, bp + 0 * 1024);
    k_perm_b<<<4, 256>>>(cbb, bp + 1 * 1024);
    k_perm_b<<<4, 256>>>(wbf, bp + 2 * 1024);
    k_perm_b<<<4, 256>>>(wbb, bp + 3 * 1024);

    k_gather_char<<<(TT * BB * 30 + 255) / 256, 256>>>(characters, char_emb, char_x);
    k_transpose_word<<<(TT * BB * 128 + 255) / 256, 256>>>(words, word_x);

    int Mbt = BB * TT;  // 51200
    auto grid = [](int M, int N) { return dim3((unsigned)((N + 63) / 64), (unsigned)((M + 127) / 128)); };

    // input projections (fp32 A) -> bf16 xpre (mma-permuted columns)
    k_gemm_tc<<<grid(Mbt, 1024), 256>>>(char_x, cihp + 0 * 1024 * 30,  bp + 0 * 1024, (float*)(xpre + 0 * (size_t)XPD), Mbt, 1024, 30, 1024, 0, 0, 1);
    k_gemm_tc<<<grid(Mbt, 1024), 256>>>(char_x, cihp + 1 * 1024 * 30,  bp + 1 * 1024, (float*)(xpre + 1 * (size_t)XPD), Mbt, 1024, 30, 1024, 0, 0, 1);
    k_gemm_tc<<<grid(Mbt, 1024), 256>>>(word_x, wihp + 0 * 1024 * 128, bp + 2 * 1024, (float*)(xpre + 2 * (size_t)XPD), Mbt, 1024, 128, 1024, 0, 0, 1);
    k_gemm_tc<<<grid(Mbt, 1024), 256>>>(word_x, wihp + 1 * 1024 * 128, bp + 3 * 1024, (float*)(xpre + 3 * (size_t)XPD), Mbt, 1024, 128, 1024, 0, 0, 1);

    RP rp;
    rp.whhp = whhp;
    rp.xpre = xpre;
    rp.hbuf = hbuf;
    rp.len_char = len_char;
    rp.len_word = len_word;
    rp.outc = char_h;
    rp.outw = word_h;
    k_rec_persist<<<256, 256, REC_SMEM>>>(rp);

    // dense stack (bf16 A operands, bf16 intermediates, softplus fused)
    k_gemm_tc<<<grid(Mbt, 512), 256>>>(char_h, clinW, clinb, (float*)xcat,         Mbt, 512, 512, 712, 1, 1, 1);
    k_gemm_tc<<<grid(Mbt, 200), 256>>>(word_h, wlinW, wlinb, (float*)(xcat + 512), Mbt, 200, 512, 712, 1, 1, 1);
    k_gemm_tc<<<grid(Mbt, 512), 256>>>(xcat, l1W, l1b, (float*)buf1, Mbt, 512, 712, 512, 1, 1, 1);
    k_gemm_tc<<<grid(Mbt, 256), 256>>>(buf1, l2W, l2b, (float*)buf2, Mbt, 256, 512, 256, 1, 1, 1);
    k_gemm_tc<<<grid(Mbt, 12),  256>>>(buf2, tW,  tb,  logits,       Mbt, 12,  256, 12,  1, 1, 0);

    // CRF
    k_crf_real<<<32, 256>>>(logits, tags, len_char, trans, crfb + BB);
    k_crf_fwd<<<32, 256>>>(logits, len_char, trans, crfb);
    k_crf_reduce<<<1, 256>>>(crfb, out);
}

// round 10
// speedup vs baseline: 5.0903x; 1.1613x over previous
#include <cuda_runtime.h>
#include <cuda_bf16.h>

#define TT 200
#define BB 256

// ---------------- scratch (device globals: allocation-free) ----------------
__device__ float d_char_x[TT*BB*30];            // [t][b][30]
__device__ float d_word_x[TT*BB*128];           // [w][b][128]
__device__ float d_whhp[4][1024*256];           // permuted Whh
__device__ float d_cihp[2][1024*30];            // permuted char Wih
__device__ float d_wihp[2][1024*128];           // permuted word Wih
__device__ float d_bp[4][1024];                 // permuted biases
__device__ float d_hbuf[4*2*BB*256];            // ping-pong h per dir (fp32)
__device__ __nv_bfloat16 d_char_h[BB*TT*512];   // [b][t][512] bf16
__device__ __nv_bfloat16 d_word_h[BB*TT*512];   // [b][w][512] bf16
__device__ __nv_bfloat16 d_xcat[BB*TT*712];     // concat bf16
__device__ __nv_bfloat16 d_buf1[BB*TT*512];
__device__ __nv_bfloat16 d_buf2[BB*TT*256];
__device__ float d_logits[BB*TT*12];
__device__ float d_crf[2*BB];

__device__ unsigned g_arrs[4];
__device__ volatile unsigned g_gens[4];

__device__ __forceinline__ float sp_(float x) { return fmaxf(x, 0.f) + log1pf(expf(-fabsf(x))); }
__device__ __forceinline__ float sg_(float x) { return 1.f / (1.f + expf(-x)); }

// pack two fp32 -> bf16x2 word (lo = first element)
__device__ __forceinline__ unsigned pk2(float lo, float hi) {
    unsigned r;
    asm("cvt.rn.bf16x2.f32 %0, %1, %2;" : "=r"(r) : "f"(hi), "f"(lo));
    return r;
}

__device__ __forceinline__ void mma_bf16(float* d, const unsigned* a, const unsigned* b) {
    asm volatile(
        "mma.sync.aligned.m16n8k16.row.col.f32.bf16.bf16.f32 "
        "{%0,%1,%2,%3}, {%4,%5,%6,%7}, {%8,%9}, {%0,%1,%2,%3};\n"
        : "+f"(d[0]), "+f"(d[1]), "+f"(d[2]), "+f"(d[3])
        : "r"(a[0]), "r"(a[1]), "r"(a[2]), "r"(a[3]), "r"(b[0]), "r"(b[1]));
}

// mma-friendly gate-column permutation: (g,u) -> permuted row index
__device__ __forceinline__ int perm_gu(int g, int u) {
    int nb = u >> 4, w16 = u & 15;
    int h = w16 >> 3, v = w16 & 7;
    int p = v >> 2, t = v & 3;
    return nb * 64 + h * 32 + p * 16 + ((g >> 1) << 3) + t * 2 + (g & 1);
}

// ---------------- small utility kernels ----------------
__global__ void k_init(float* hbuf) {
    int i = blockIdx.x * blockDim.x + threadIdx.x;
    if (i < 4) { g_arrs[i] = 0; g_gens[i] = 0; }
    if (i < 4 * 2 * BB * 256) hbuf[i] = 0.f;
}

__global__ void k_gather_char(const int* __restrict__ chars, const float* __restrict__ emb,
                              float* __restrict__ out) {
    int i = blockIdx.x * blockDim.x + threadIdx.x;
    if (i >= TT * BB * 30) return;
    int k = i % 30, tb = i / 30;
    int b = tb % BB, t = tb / BB;
    out[i] = emb[chars[b * TT + t] * 30 + k];
}

__global__ void k_transpose_word(const float* __restrict__ words, float* __restrict__ out) {
    int i = blockIdx.x * blockDim.x + threadIdx.x;
    if (i >= TT * BB * 128) return;
    int k = i & 127, wb = i >> 7;
    int b = wb % BB, w = wb / BB;
    out[i] = words[((size_t)b * TT + w) * 128 + k];
}

__global__ void k_perm_w(const float* __restrict__ src, float* __restrict__ dst, int K) {
    int i = blockIdx.x * blockDim.x + threadIdx.x;
    if (i >= 1024 * K) return;
    int k = i % K, s = i / K;
    int g = s >> 8, u = s & 255;
    dst[(size_t)perm_gu(g, u) * K + k] = src[(size_t)s * K + k];
}

__global__ void k_perm_b(const float* __restrict__ src, float* __restrict__ dst) {
    int s = blockIdx.x * blockDim.x + threadIdx.x;
    if (s >= 1024) return;
    int g = s >> 8, u = s & 255;
    dst[perm_gu(g, u)] = src[s];
}

// ---------------- BF16 tensor-core GEMM: C = act(A[M,K] @ W[N,K]^T + bias) ----------------
// block 128(M) x 64(N); 8 warps each 32x32 via m16n8k16 bf16 mma, fp32 accum.
// A is bf16.  obf: write bf16 output (else fp32).  M multiple of 128.
__global__ void __launch_bounds__(256) k_gemm_tc(
        const __nv_bfloat16* __restrict__ Ab, const float* __restrict__ W,
        const float* __restrict__ bias, float* __restrict__ C,
        int M, int N, int K, int ldc, int act, int obf) {
    __shared__ unsigned As[128][20];   // 16 k-words (32 k) + pad
    __shared__ unsigned Bs[64][20];

    int tid = threadIdx.x;
    int bm = blockIdx.y * 128, bn = blockIdx.x * 64;
    int wid = tid >> 5, lane = tid & 31;
    int wm = (wid & 3) * 32, wn = (wid >> 2) * 32;
    int gid = lane >> 2, tig = lane & 3;
    bool k4 = (K & 3) == 0;

    float acc[2][4][4];
#pragma unroll
    for (int i = 0; i < 2; i++)
#pragma unroll
        for (int j = 0; j < 4; j++)
#pragma unroll
            for (int v = 0; v < 4; v++) acc[i][j][v] = 0.f;

    uint4 rau[2];
    float rb[8];

    auto load_stage = [&](int k0) {
#pragma unroll
        for (int j = 0; j < 2; j++) {
            int q = tid + 256 * j;
            int r = q >> 2, cw4 = (q & 3) * 4;      // 4 words = 8 bf16
            int ke = k0 + cw4 * 2;
            const __nv_bfloat16* src = Ab + (size_t)(bm + r) * K + ke;
            if (ke + 8 <= K) rau[j] = *(const uint4*)src;
            else {
                unsigned w[4] = {0u, 0u, 0u, 0u};
#pragma unroll
                for (int e = 0; e < 8; e++)
                    if (ke + e < K) ((__nv_bfloat16*)w)[e] = src[e];
                rau[j] = make_uint4(w[0], w[1], w[2], w[3]);
            }
        }
#pragma unroll
        for (int j = 0; j < 2; j++) {
            int q = tid + 256 * j;
            int r = q >> 3, c = (q & 7) * 4;
            float4 v = make_float4(0.f, 0.f, 0.f, 0.f);
            if (bn + r < N) {
                const float* src = W + (size_t)(bn + r) * K + k0 + c;
                if (k4 && k0 + c + 3 < K) v = *(const float4*)src;
                else {
                    v.x = (k0 + c + 0 < K) ? src[0] : 0.f;
                    v.y = (k0 + c + 1 < K) ? src[1] : 0.f;
                    v.z = (k0 + c + 2 < K) ? src[2] : 0.f;
                    v.w = (k0 + c + 3 < K) ? src[3] : 0.f;
                }
            }
            rb[j * 4 + 0] = v.x; rb[j * 4 + 1] = v.y; rb[j * 4 + 2] = v.z; rb[j * 4 + 3] = v.w;
        }
    };

    load_stage(0);
    for (int k0 = 0; k0 < K; k0 += 32) {
        __syncthreads();
#pragma unroll
        for (int j = 0; j < 2; j++) {
            int q = tid + 256 * j;
            int r = q >> 2, cw4 = (q & 3) * 4;
            *(uint4*)&As[r][cw4] = rau[j];
        }
#pragma unroll
        for (int j = 0; j < 2; j++) {
            int q = tid + 256 * j;
            int r = q >> 3, cw = (q & 7) * 2;
            *(uint2*)&Bs[r][cw] = make_uint2(pk2(rb[j*4+0], rb[j*4+1]), pk2(rb[j*4+2], rb[j*4+3]));
        }
        __syncthreads();
        if (k0 + 32 < K) load_stage(k0 + 32);

#pragma unroll
        for (int ks = 0; ks < 2; ks++) {
            int kw = ks * 8;
            unsigned af[2][4], bf[4][2];
#pragma unroll
            for (int im = 0; im < 2; im++) {
                int rm = wm + im * 16;
                af[im][0] = As[rm + gid][kw + tig];
                af[im][1] = As[rm + gid + 8][kw + tig];
                af[im][2] = As[rm + gid][kw + tig + 4];
                af[im][3] = As[rm + gid + 8][kw + tig + 4];
            }
#pragma unroll
            for (int jn = 0; jn < 4; jn++) {
                int cn = wn + jn * 8;
                bf[jn][0] = Bs[cn + gid][kw + tig];
                bf[jn][1] = Bs[cn + gid][kw + tig + 4];
            }
#pragma unroll
            for (int im = 0; im < 2; im++)
#pragma unroll
                for (int jn = 0; jn < 4; jn++)
                    mma_bf16(acc[im][jn], af[im], bf[jn]);
        }
    }

#pragma unroll
    for (int im = 0; im < 2; im++) {
#pragma unroll
        for (int jn = 0; jn < 4; jn++) {
            int row0 = bm + wm + im * 16 + gid;
            int col0 = bn + wn + jn * 8 + tig * 2;
#pragma unroll
            for (int half = 0; half < 2; half++) {
                int row = row0 + half * 8;
                if (obf) {
                    if (col0 < N) {   // N even, col0 even -> pair fully in-bounds
                        float v0 = acc[im][jn][half * 2 + 0];
                        float v1 = acc[im][jn][half * 2 + 1];
                        if (bias) { v0 += bias[col0]; v1 += bias[col0 + 1]; }
                        if (act) { v0 = sp_(v0); v1 = sp_(v1); }
                        *(unsigned*)(((__nv_bfloat16*)C) + (size_t)row * ldc + col0) = pk2(v0, v1);
                    }
                } else {
#pragma unroll
                    for (int cc = 0; cc < 2; cc++) {
                        int col = col0 + cc;
                        if (col >= N) continue;
                        float v = acc[im][jn][half * 2 + cc];
                        if (bias) v += bias[col];
                        if (act) v = sp_(v);
                        C[(size_t)row * ldc + col] = v;
                    }
                }
            }
        }
    }
}

// ---------------- persistent recurrence (bf16 tensor cores, fused input proj) ----------------
struct RP {
    const float* whhp;      // [4][1024*256] permuted
    const float* cihp;      // [2][1024*30]  permuted
    const float* wihp;      // [2][1024*128] permuted
    const float* bp;        // [4][1024]     permuted
    const float* char_x;    // [t][b][30]
    const float* word_x;    // [t][b][128]
    float* hbuf;
    const int* len_char;
    const int* len_word;
    __nv_bfloat16* outc;
    __nv_bfloat16* outw;
};

// per-direction barrier over 64 blocks
__device__ __forceinline__ void grid_bar(int dir, unsigned target) {
    __threadfence();
    __syncthreads();
    if (threadIdx.x == 0) {
        if (atomicAdd(&g_arrs[dir], 1u) == 63u) {
            g_arrs[dir] = 0;
            __threadfence();
            g_gens[dir] = target;
        } else {
            while (g_gens[dir] < target) __nanosleep(32);
        }
    }
    __syncthreads();
}

// smem: Ws [64][132] + As [64][132] + Wxs [64][68] + Xs [64][68] (words)
#define REC_SMEM ((64*132*2 + 64*68*2) * 4)   // 102400 B

__global__ void __launch_bounds__(256, 2) k_rec_persist(RP p) {
    extern __shared__ unsigned smu[];
    unsigned* Ws  = smu;                       // [64][132] Whh tile
    unsigned* As  = Ws  + 64 * 132;            // [64][132] h tile
    unsigned* Wxs = As  + 64 * 132;            // [64][68]  Wih tile
    unsigned* Xs  = Wxs + 64 * 68;             // [64][68]  x tile

    int bx = blockIdx.x;
    int dir = bx >> 6, mb = (bx >> 4) & 3, nb = bx & 15;
    int tid = threadIdx.x;
    int wid = tid >> 5, lane = tid & 31;
    int gid = lane >> 2, tig = lane & 3;
    int wm = (wid & 3) * 16;
    int wnh = wid >> 2;
    int bm = mb * 64;

    int Kx  = (dir < 2) ? 30 : 128;            // x feature dim
    int Kxw = (dir < 2) ? 16 : 64;             // padded word count
    const float* Wx = (dir < 2) ? (p.cihp + (size_t)dir * 1024 * 30)
                                : (p.wihp + (size_t)(dir - 2) * 1024 * 128);
    const float* xsrc = (dir < 2) ? p.char_x : p.word_x;

    // load + pack Whh tile [64 cols][256 k]
    const float* W = p.whhp + (size_t)dir * 1024 * 256;
    for (int idx = tid; idx < 64 * 128; idx += 256) {
        int n = idx >> 7, kw = idx & 127;
        float2 v = *(const float2*)&W[(size_t)(nb * 64 + n) * 256 + kw * 2];
        Ws[n * 132 + kw] = pk2(v.x, v.y);
    }
    // load + pack Wih tile [64 cols][Kx k] (zero-padded to Kxw words)
    for (int idx = tid; idx < 64 * Kxw; idx += 256) {
        int n = idx / Kxw, kw = idx % Kxw;
        const float* wr = Wx + (size_t)(nb * 64 + n) * Kx;
        float lo = (kw * 2     < Kx) ? wr[kw * 2]     : 0.f;
        float hi = (kw * 2 + 1 < Kx) ? wr[kw * 2 + 1] : 0.f;
        Wxs[n * 68 + kw] = pk2(lo, hi);
    }

    // bias fragment: col = nb*64 + wnh*32 + jn*8 + tig*2 + c
    const float* bpd = p.bp + dir * 1024 + nb * 64 + wnh * 32;
    float bias_r[4][2];
#pragma unroll
    for (int jn = 0; jn < 4; jn++) {
        bias_r[jn][0] = bpd[jn * 8 + tig * 2];
        bias_r[jn][1] = bpd[jn * 8 + tig * 2 + 1];
    }

    float hreg[2][2], creg[2][2];
#pragma unroll
    for (int i = 0; i < 2; i++)
#pragma unroll
        for (int j = 0; j < 2; j++) { hreg[i][j] = 0.f; creg[i][j] = 0.f; }

    const int* lens = (dir < 2) ? p.len_char : p.len_word;
    int lenv[2];
    lenv[0] = lens[bm + wm + gid];
    lenv[1] = lens[bm + wm + gid + 8];

    float* hb0 = p.hbuf + (size_t)dir * 2 * 65536;
    float* hb1 = hb0 + 65536;
    __nv_bfloat16* outp = (dir < 2) ? p.outc : p.outw;
    int half = (dir & 1) ? 256 : 0;

    __syncthreads();

    for (int t = 0; t < TT; t++) {
        int tr = (dir & 1) ? (TT - 1 - t) : t;
        const float* h = (t & 1) ? hb1 : hb0;
        float* hn_buf = (t & 1) ? hb0 : hb1;

        // stage h tile [64 rows][256 k] as packed bf16: 4096 float4 slots, 16/thread
#pragma unroll
        for (int j = 0; j < 16; j++) {
            int q = tid + 256 * j;
            int r = q >> 6, c4 = q & 63;
            float4 v = __ldcg((const float4*)&h[(bm + r) * 256 + c4 * 4]);
            *(uint2*)&As[r * 132 + c4 * 2] = make_uint2(pk2(v.x, v.y), pk2(v.z, v.w));
        }
        // stage x tile [64 rows][Kx]
        if (Kxw == 64) {
            // word: 64 rows x 32 float4 slots = 2048, 8/thread
#pragma unroll
            for (int j = 0; j < 8; j++) {
                int q = tid + 256 * j;
                int r = q >> 5, c4 = q & 31;
                float4 v = __ldcg((const float4*)&xsrc[((size_t)tr * BB + bm + r) * 128 + c4 * 4]);
                *(uint2*)&Xs[r * 68 + c4 * 2] = make_uint2(pk2(v.x, v.y), pk2(v.z, v.w));
            }
        } else {
            // char: 64 rows x 16 words, guarded scalar loads (Kx=30)
#pragma unroll
            for (int j = 0; j < 4; j++) {
                int q = tid + 256 * j;
                int r = q >> 4, kw = q & 15;
                const float* xr = xsrc + ((size_t)tr * BB + bm + r) * 30;
                float lo = (kw * 2     < 30) ? xr[kw * 2]     : 0.f;
                float hi = (kw * 2 + 1 < 30) ? xr[kw * 2 + 1] : 0.f;
                Xs[r * 68 + kw] = pk2(lo, hi);
            }
        }
        __syncthreads();

        float acc[4][4];
#pragma unroll
        for (int j = 0; j < 4; j++)
#pragma unroll
            for (int v = 0; v < 4; v++) acc[j][v] = 0.f;

        // h @ Whh^T
#pragma unroll
        for (int ks = 0; ks < 16; ks++) {
            int kw = ks * 8;
            unsigned af[4], bf[4][2];
            af[0] = As[(wm + gid) * 132 + kw + tig];
            af[1] = As[(wm + gid + 8) * 132 + kw + tig];
            af[2] = As[(wm + gid) * 132 + kw + tig + 4];
            af[3] = As[(wm + gid + 8) * 132 + kw + tig + 4];
#pragma unroll
            for (int jn = 0; jn < 4; jn++) {
                int n0 = wnh * 32 + jn * 8;
                bf[jn][0] = Ws[(n0 + gid) * 132 + kw + tig];
                bf[jn][1] = Ws[(n0 + gid) * 132 + kw + tig + 4];
            }
#pragma unroll
            for (int jn = 0; jn < 4; jn++)
                mma_bf16(acc[jn], af, bf[jn]);
        }
        // x @ Wih^T (fused input projection)
        int nksx = Kxw >> 3;
#pragma unroll 2
        for (int ks = 0; ks < nksx; ks++) {
            int kw = ks * 8;
            unsigned af[4], bf[4][2];
            af[0] = Xs[(wm + gid) * 68 + kw + tig];
            af[1] = Xs[(wm + gid + 8) * 68 + kw + tig];
            af[2] = Xs[(wm + gid) * 68 + kw + tig + 4];
            af[3] = Xs[(wm + gid + 8) * 68 + kw + tig + 4];
#pragma unroll
            for (int jn = 0; jn < 4; jn++) {
                int n0 = wnh * 32 + jn * 8;
                bf[jn][0] = Wxs[(n0 + gid) * 68 + kw + tig];
                bf[jn][1] = Wxs[(n0 + gid) * 68 + kw + tig + 4];
            }
#pragma unroll
            for (int jn = 0; jn < 4; jn++)
                mma_bf16(acc[jn], af, bf[jn]);
        }

        // fused LSTM cell epilogue (bias folded)
#pragma unroll
        for (int rh = 0; rh < 2; rh++) {
            int b = bm + wm + gid + rh * 8;
            bool valid = tr < lenv[rh];
#pragma unroll
            for (int pp = 0; pp < 2; pp++) {
                float gi = acc[2 * pp + 0][rh * 2 + 0] + bias_r[2 * pp + 0][0];
                float gf = acc[2 * pp + 0][rh * 2 + 1] + bias_r[2 * pp + 0][1];
                float gc = acc[2 * pp + 1][rh * 2 + 0] + bias_r[2 * pp + 1][0];
                float go = acc[2 * pp + 1][rh * 2 + 1] + bias_r[2 * pp + 1][1];
                float cn = sg_(gf) * creg[rh][pp] + sg_(gi) * tanhf(gc);
                float hv = sg_(go) * tanhf(cn);
                if (valid) { creg[rh][pp] = cn; hreg[rh][pp] = hv; }
                int u = nb * 16 + wnh * 8 + pp * 4 + tig;
                outp[((size_t)b * TT + tr) * 512 + half + u] = __float2bfloat16(valid ? hv : 0.f);
                hn_buf[b * 256 + u] = hreg[rh][pp];
            }
        }

        if (t + 1 < TT) grid_bar(dir, (unsigned)(t + 1));
    }
}

// ---------------- CRF: real path score (one warp per batch, deterministic) ----------------
__global__ void k_crf_real(const float* __restrict__ logits, const int* __restrict__ tags,
                           const int* __restrict__ lens, const float* __restrict__ trans,
                           float* __restrict__ rl) {
    __shared__ float st[144];
    int tid = threadIdx.x;
    if (tid < 144) st[tid] = trans[tid];
    __syncthreads();
    int warp = tid >> 5, lane = tid & 31;
    int b = blockIdx.x * 8 + warp;
    int len = lens[b];
    float s = 0.f;
    for (int t = lane; t < len; t += 32) {
        int tg = tags[b * TT + t];
        int prev = (t == 0) ? 10 : tags[b * TT + t - 1];
        s += logits[((size_t)b * TT + t) * 12 + tg] + st[prev * 12 + tg];
    }
#pragma unroll
    for (int o = 16; o > 0; o >>= 1) s += __shfl_xor_sync(0xffffffffu, s, o);
    if (lane == 0) {
        int last = tags[b * TT + len - 1];
        rl[b] = s + st[last * 12 + 11];
    }
}

// ---------------- CRF forward: one warp per batch ----------------
__global__ void k_crf_fwd(const float* __restrict__ logits, const int* __restrict__ lens,
                          const float* __restrict__ trans, float* __restrict__ tot) {
    __shared__ float st[144];
    int tid = threadIdx.x;
    if (tid < 144) st[tid] = trans[tid];
    __syncthreads();
    int warp = tid >> 5, lane = tid & 31;
    int b = blockIdx.x * 8 + warp;
    int len = lens[b];
    float alpha = 0.f;
    for (int t = 0; t < TT; t++) {
        float lt = (lane < 12) ? logits[((size_t)b * TT + t) * 12 + lane] : 0.f;
        float sc[12];
        float mx = -1e30f;
#pragma unroll
        for (int i = 0; i < 12; i++) {
            float ai = __shfl_sync(0xffffffffu, alpha, i);
            float s = ai + ((lane < 12) ? st[i * 12 + lane] : 0.f);
            sc[i] = s;
            mx = fmaxf(mx, s);
        }
        float sm = 0.f;
#pragma unroll
        for (int i = 0; i < 12; i++) sm += expf(sc[i] - mx);
        float an = mx + logf(sm) + lt;
        if (t < len) alpha = an;
    }
    float v = (lane < 12) ? alpha + st[lane * 12 + 11] : -1e30f;
    float mx = v;
#pragma unroll
    for (int o = 16; o > 0; o >>= 1) mx = fmaxf(mx, __shfl_xor_sync(0xffffffffu, mx, o));
    float e = expf(v - mx);
#pragma unroll
    for (int o = 16; o > 0; o >>= 1) e += __shfl_xor_sync(0xffffffffu, e, o);
    if (lane == 0) tot[b] = mx + logf(e);
}

__global__ void k_crf_reduce(const float* __restrict__ crf, float* __restrict__ out) {
    __shared__ float s[256];
    int t = threadIdx.x;
    s[t] = crf[t] - crf[256 + t];
    __syncthreads();
    for (int o = 128; o > 0; o >>= 1) {
        if (t < o) s[t] += s[t + o];
        __syncthreads();
    }
    if (t == 0) out[0] = s[0];
}

// ---------------- launch ----------------
extern "C" void kernel_launch(void* const* d_in, const int* in_sizes, int n_in,
                              void* d_out, int out_size) {
    const int*   characters = (const int*)d_in[0];
    const float* words      = (const float*)d_in[1];
    const int*   tags       = (const int*)d_in[2];
    const int*   len_char   = (const int*)d_in[3];
    const int*   len_word   = (const int*)d_in[4];
    const float* char_emb   = (const float*)d_in[5];
    const float* cWihf = (const float*)d_in[6];
    const float* cWhhf = (const float*)d_in[7];
    const float* cbf   = (const float*)d_in[8];
    const float* cWihb = (const float*)d_in[9];
    const float* cWhhb = (const float*)d_in[10];
    const float* cbb   = (const float*)d_in[11];
    const float* clinW = (const float*)d_in[12];
    const float* clinb = (const float*)d_in[13];
    const float* wWihf = (const float*)d_in[14];
    const float* wWhhf = (const float*)d_in[15];
    const float* wbf   = (const float*)d_in[16];
    const float* wWihb = (const float*)d_in[17];
    const float* wWhhb = (const float*)d_in[18];
    const float* wbb   = (const float*)d_in[19];
    const float* wlinW = (const float*)d_in[20];
    const float* wlinb = (const float*)d_in[21];
    const float* l1W   = (const float*)d_in[22];
    const float* l1b   = (const float*)d_in[23];
    const float* l2W   = (const float*)d_in[24];
    const float* l2b   = (const float*)d_in[25];
    const float* tW    = (const float*)d_in[26];
    const float* tb    = (const float*)d_in[27];
    const float* trans = (const float*)d_in[28];
    float* out = (float*)d_out;

    float *char_x, *word_x, *whhp, *cihp, *wihp, *bp, *hbuf, *logits, *crfb;
    __nv_bfloat16 *char_h, *word_h, *xcat, *buf1, *buf2;
    cudaGetSymbolAddress((void**)&char_x, d_char_x);
    cudaGetSymbolAddress((void**)&word_x, d_word_x);
    cudaGetSymbolAddress((void**)&whhp,   d_whhp);
    cudaGetSymbolAddress((void**)&cihp,   d_cihp);
    cudaGetSymbolAddress((void**)&wihp,   d_wihp);
    cudaGetSymbolAddress((void**)&bp,     d_bp);
    cudaGetSymbolAddress((void**)&hbuf,   d_hbuf);
    cudaGetSymbolAddress((void**)&char_h, d_char_h);
    cudaGetSymbolAddress((void**)&word_h, d_word_h);
    cudaGetSymbolAddress((void**)&xcat,   d_xcat);
    cudaGetSymbolAddress((void**)&buf1,   d_buf1);
    cudaGetSymbolAddress((void**)&buf2,   d_buf2);
    cudaGetSymbolAddress((void**)&logits, d_logits);
    cudaGetSymbolAddress((void**)&crfb,   d_crf);

    cudaFuncSetAttribute(k_rec_persist, cudaFuncAttributeMaxDynamicSharedMemorySize, REC_SMEM);

    k_init<<<(4 * 2 * BB * 256 + 255) / 256, 256>>>(hbuf);

    k_perm_w<<<(1024 * 256 + 255) / 256, 256>>>(cWhhf, whhp + 0 * 1024 * 256, 256);
    k_perm_w<<<(1024 * 256 + 255) / 256, 256>>>(cWhhb, whhp + 1 * 1024 * 256, 256);
    k_perm_w<<<(1024 * 256 + 255) / 256, 256>>>(wWhhf, whhp + 2 * 1024 * 256, 256);
    k_perm_w<<<(1024 * 256 + 255) / 256, 256>>>(wWhhb, whhp + 3 * 1024 * 256, 256);
    k_perm_w<<<(1024 * 30 + 255) / 256, 256>>>(cWihf, cihp + 0 * 1024 * 30, 30);
    k_perm_w<<<(1024 * 30 + 255) / 256, 256>>>(cWihb, cihp + 1 * 1024 * 30, 30);
    k_perm_w<<<(1024 * 128 + 255) / 256, 256>>>(wWihf, wihp + 0 * 1024 * 128, 128);
    k_perm_w<<<(1024 * 128 + 255) / 256, 256>>>(wWihb, wihp + 1 * 1024 * 128, 128);
    k_perm_b<<<4, 256>>>(cbf, bp + 0 * 1024);
    k_perm_b<<<4, 256>>>(cbb, bp + 1 * 1024);
    k_perm_b<<<4, 256>>>(wbf, bp + 2 * 1024);
    k_perm_b<<<4, 256>>>(wbb, bp + 3 * 1024);

    k_gather_char<<<(TT * BB * 30 + 255) / 256, 256>>>(characters, char_emb, char_x);
    k_transpose_word<<<(TT * BB * 128 + 255) / 256, 256>>>(words, word_x);

    // persistent recurrence with fused input projections (no xpre buffer)
    RP rp;
    rp.whhp = whhp;
    rp.cihp = cihp;
    rp.wihp = wihp;
    rp.bp   = bp;
    rp.char_x = char_x;
    rp.word_x = word_x;
    rp.hbuf = hbuf;
    rp.len_char = len_char;
    rp.len_word = len_word;
    rp.outc = char_h;
    rp.outw = word_h;
    k_rec_persist<<<256, 256, REC_SMEM>>>(rp);

    int Mbt = BB * TT;  // 51200
    auto grid = [](int M, int N) { return dim3((unsigned)((N + 63) / 64), (unsigned)((M + 127) / 128)); };

    // dense stack (bf16 operands, bf16 intermediates, softplus fused)
    k_gemm_tc<<<grid(Mbt, 512), 256>>>(char_h, clinW, clinb, (float*)xcat,         Mbt, 512, 512, 712, 1, 1);
    k_gemm_tc<<<grid(Mbt, 200), 256>>>(word_h, wlinW, wlinb, (float*)(xcat + 512), Mbt, 200, 512, 712, 1, 1);
    k_gemm_tc<<<grid(Mbt, 512), 256>>>(xcat, l1W, l1b, (float*)buf1, Mbt, 512, 712, 512, 1, 1);
    k_gemm_tc<<<grid(Mbt, 256), 256>>>(buf1, l2W, l2b, (float*)buf2, Mbt, 256, 512, 256, 1, 1);
    k_gemm_tc<<<grid(Mbt, 12),  256>>>(buf2, tW,  tb,  logits,       Mbt, 12,  256, 12,  1, 0);

    // CRF
    k_crf_real<<<32, 256>>>(logits, tags, len_char, trans, crfb + BB);
    k_crf_fwd<<<32, 256>>>(logits, len_char, trans, crfb);
    k_crf_reduce<<<1, 256>>>(crfb, out);
}

// round 12
// speedup vs baseline: 5.3638x; 1.0537x over previous
#include <cuda_runtime.h>
#include <cuda_bf16.h>

#define TT 200
#define BB 256

// ---------------- scratch (device globals: allocation-free) ----------------
__device__ float d_char_x[TT*BB*30];            // [t][b][30]
__device__ float d_word_x[TT*BB*128];           // [w][b][128]
__device__ float d_whhp[4][1024*256];           // permuted Whh
__device__ float d_cihp[2][1024*30];            // permuted char Wih
__device__ float d_wihp[2][1024*128];           // permuted word Wih
__device__ float d_bp[4][1024];                 // permuted biases
__device__ __nv_bfloat16 d_hbuf[4*2*BB*256];    // ping-pong h per dir (bf16)
__device__ __nv_bfloat16 d_char_h[BB*TT*512];   // [b][t][512] bf16
__device__ __nv_bfloat16 d_word_h[BB*TT*512];   // [b][w][512] bf16
__device__ __nv_bfloat16 d_xcat[BB*TT*712];     // concat bf16
__device__ __nv_bfloat16 d_buf1[BB*TT*512];
__device__ __nv_bfloat16 d_buf2[BB*TT*256];
__device__ float d_logits[BB*TT*12];
__device__ float d_crf[2*BB];

__device__ unsigned g_arrs[16];
__device__ volatile unsigned g_gens[16];

__device__ __forceinline__ float sp_(float x) { return fmaxf(x, 0.f) + log1pf(expf(-fabsf(x))); }
__device__ __forceinline__ float sg_(float x) { return 1.f / (1.f + expf(-x)); }

// pack two fp32 -> bf16x2 word (lo = first element)
__device__ __forceinline__ unsigned pk2(float lo, float hi) {
    unsigned r;
    asm("cvt.rn.bf16x2.f32 %0, %1, %2;" : "=r"(r) : "f"(hi), "f"(lo));
    return r;
}

__device__ __forceinline__ void mma_bf16(float* d, const unsigned* a, const unsigned* b) {
    asm volatile(
        "mma.sync.aligned.m16n8k16.row.col.f32.bf16.bf16.f32 "
        "{%0,%1,%2,%3}, {%4,%5,%6,%7}, {%8,%9}, {%0,%1,%2,%3};\n"
        : "+f"(d[0]), "+f"(d[1]), "+f"(d[2]), "+f"(d[3])
        : "r"(a[0]), "r"(a[1]), "r"(a[2]), "r"(a[3]), "r"(b[0]), "r"(b[1]));
}

// mma-friendly gate-column permutation: (g,u) -> permuted row index
__device__ __forceinline__ int perm_gu(int g, int u) {
    int nb = u >> 4, w16 = u & 15;
    int h = w16 >> 3, v = w16 & 7;
    int p = v >> 2, t = v & 3;
    return nb * 64 + h * 32 + p * 16 + ((g >> 1) << 3) + t * 2 + (g & 1);
}

// ---------------- init + fused prep ----------------
__global__ void k_init(__nv_bfloat16* hbuf) {
    int i = blockIdx.x * blockDim.x + threadIdx.x;
    if (i < 16) { g_arrs[i] = 0; g_gens[i] = 0; }
    if (i < 4 * 2 * BB * 128) ((unsigned*)hbuf)[i] = 0u;   // 524288 bf16 = 262144 words
}

struct PrepP {
    const float* whh[4];
    const float* cih[2];
    const float* wih[2];
    const float* bias[4];
    float* whhp; float* cihp; float* wihp; float* bp;
};

// y: 0-3 Whh(K=256), 4-5 char Wih(K=30), 6-7 word Wih(K=128), 8-11 bias
__global__ void k_prep(PrepP p) {
    int y = blockIdx.y;
    int i = blockIdx.x * blockDim.x + threadIdx.x;
    if (y < 4) {
        if (i >= 1024 * 256) return;
        int k = i & 255, s = i >> 8;
        int g = s >> 8, u = s & 255;
        p.whhp[(size_t)y * 262144 + perm_gu(g, u) * 256 + k] = p.whh[y][(size_t)s * 256 + k];
    } else if (y < 6) {
        if (i >= 1024 * 30) return;
        int k = i % 30, s = i / 30;
        int g = s >> 8, u = s & 255;
        p.cihp[(size_t)(y - 4) * 30720 + perm_gu(g, u) * 30 + k] = p.cih[y - 4][(size_t)s * 30 + k];
    } else if (y < 8) {
        if (i >= 1024 * 128) return;
        int k = i & 127, s = i >> 7;
        int g = s >> 8, u = s & 255;
        p.wihp[(size_t)(y - 6) * 131072 + perm_gu(g, u) * 128 + k] = p.wih[y - 6][(size_t)s * 128 + k];
    } else {
        if (i >= 1024) return;
        int g = i >> 8, u = i & 255;
        p.bp[(y - 8) * 1024 + perm_gu(g, u)] = p.bias[y - 8][i];
    }
}

__global__ void k_gather_char(const int* __restrict__ chars, const float* __restrict__ emb,
                              float* __restrict__ out) {
    int i = blockIdx.x * blockDim.x + threadIdx.x;
    if (i >= TT * BB * 30) return;
    int k = i % 30, tb = i / 30;
    int b = tb % BB, t = tb / BB;
    out[i] = emb[chars[b * TT + t] * 30 + k];
}

__global__ void k_transpose_word(const float* __restrict__ words, float* __restrict__ out) {
    int i = blockIdx.x * blockDim.x + threadIdx.x;
    if (i >= TT * BB * 128) return;
    int k = i & 127, wb = i >> 7;
    int b = wb % BB, w = wb / BB;
    out[i] = words[((size_t)b * TT + w) * 128 + k];
}

// ---------------- BF16 tensor-core GEMM: C = act(A[M,K] @ W[N,K]^T + bias) ----------------
__global__ void __launch_bounds__(256) k_gemm_tc(
        const __nv_bfloat16* __restrict__ Ab, const float* __restrict__ W,
        const float* __restrict__ bias, float* __restrict__ C,
        int M, int N, int K, int ldc, int act, int obf) {
    __shared__ unsigned As[128][20];
    __shared__ unsigned Bs[64][20];

    int tid = threadIdx.x;
    int bm = blockIdx.y * 128, bn = blockIdx.x * 64;
    int wid = tid >> 5, lane = tid & 31;
    int wm = (wid & 3) * 32, wn = (wid >> 2) * 32;
    int gid = lane >> 2, tig = lane & 3;
    bool k4 = (K & 3) == 0;

    float acc[2][4][4];
#pragma unroll
    for (int i = 0; i < 2; i++)
#pragma unroll
        for (int j = 0; j < 4; j++)
#pragma unroll
            for (int v = 0; v < 4; v++) acc[i][j][v] = 0.f;

    uint4 rau[2];
    float rb[8];

    auto load_stage = [&](int k0) {
#pragma unroll
        for (int j = 0; j < 2; j++) {
            int q = tid + 256 * j;
            int r = q >> 2, cw4 = (q & 3) * 4;
            int ke = k0 + cw4 * 2;
            const __nv_bfloat16* src = Ab + (size_t)(bm + r) * K + ke;
            if (ke + 8 <= K) rau[j] = *(const uint4*)src;
            else {
                unsigned w[4] = {0u, 0u, 0u, 0u};
#pragma unroll
                for (int e = 0; e < 8; e++)
                    if (ke + e < K) ((__nv_bfloat16*)w)[e] = src[e];
                rau[j] = make_uint4(w[0], w[1], w[2], w[3]);
            }
        }
#pragma unroll
        for (int j = 0; j < 2; j++) {
            int q = tid + 256 * j;
            int r = q >> 3, c = (q & 7) * 4;
            float4 v = make_float4(0.f, 0.f, 0.f, 0.f);
            if (bn + r < N) {
                const float* src = W + (size_t)(bn + r) * K + k0 + c;
                if (k4 && k0 + c + 3 < K) v = *(const float4*)src;
                else {
                    v.x = (k0 + c + 0 < K) ? src[0] : 0.f;
                    v.y = (k0 + c + 1 < K) ? src[1] : 0.f;
                    v.z = (k0 + c + 2 < K) ? src[2] : 0.f;
                    v.w = (k0 + c + 3 < K) ? src[3] : 0.f;
                }
            }
            rb[j * 4 + 0] = v.x; rb[j * 4 + 1] = v.y; rb[j * 4 + 2] = v.z; rb[j * 4 + 3] = v.w;
        }
    };

    load_stage(0);
    for (int k0 = 0; k0 < K; k0 += 32) {
        __syncthreads();
#pragma unroll
        for (int j = 0; j < 2; j++) {
            int q = tid + 256 * j;
            int r = q >> 2, cw4 = (q & 3) * 4;
            *(uint4*)&As[r][cw4] = rau[j];
        }
#pragma unroll
        for (int j = 0; j < 2; j++) {
            int q = tid + 256 * j;
            int r = q >> 3, cw = (q & 7) * 2;
            *(uint2*)&Bs[r][cw] = make_uint2(pk2(rb[j*4+0], rb[j*4+1]), pk2(rb[j*4+2], rb[j*4+3]));
        }
        __syncthreads();
        if (k0 + 32 < K) load_stage(k0 + 32);

#pragma unroll
        for (int ks = 0; ks < 2; ks++) {
            int kw = ks * 8;
            unsigned af[2][4], bf[4][2];
#pragma unroll
            for (int im = 0; im < 2; im++) {
                int rm = wm + im * 16;
                af[im][0] = As[rm + gid][kw + tig];
                af[im][1] = As[rm + gid + 8][kw + tig];
                af[im][2] = As[rm + gid][kw + tig + 4];
                af[im][3] = As[rm + gid + 8][kw + tig + 4];
            }
#pragma unroll
            for (int jn = 0; jn < 4; jn++) {
                int cn = wn + jn * 8;
                bf[jn][0] = Bs[cn + gid][kw + tig];
                bf[jn][1] = Bs[cn + gid][kw + tig + 4];
            }
#pragma unroll
            for (int im = 0; im < 2; im++)
#pragma unroll
                for (int jn = 0; jn < 4; jn++)
                    mma_bf16(acc[im][jn], af[im], bf[jn]);
        }
    }

#pragma unroll
    for (int im = 0; im < 2; im++) {
#pragma unroll
        for (int jn = 0; jn < 4; jn++) {
            int row0 = bm + wm + im * 16 + gid;
            int col0 = bn + wn + jn * 8 + tig * 2;
#pragma unroll
            for (int half = 0; half < 2; half++) {
                int row = row0 + half * 8;
                if (obf) {
                    if (col0 < N) {
                        float v0 = acc[im][jn][half * 2 + 0];
                        float v1 = acc[im][jn][half * 2 + 1];
                        if (bias) { v0 += bias[col0]; v1 += bias[col0 + 1]; }
                        if (act) { v0 = sp_(v0); v1 = sp_(v1); }
                        *(unsigned*)(((__nv_bfloat16*)C) + (size_t)row * ldc + col0) = pk2(v0, v1);
                    }
                } else {
#pragma unroll
                    for (int cc = 0; cc < 2; cc++) {
                        int col = col0 + cc;
                        if (col >= N) continue;
                        float v = acc[im][jn][half * 2 + cc];
                        if (bias) v += bias[col];
                        if (act) v = sp_(v);
                        C[(size_t)row * ldc + col] = v;
                    }
                }
            }
        }
    }
}

// ---------------- persistent recurrence (bf16 tensor cores, fused input proj) ----------------
struct RP {
    const float* whhp;      // [4][1024*256] permuted
    const float* cihp;      // [2][1024*30]  permuted
    const float* wihp;      // [2][1024*128] permuted
    const float* bp;        // [4][1024]     permuted
    const float* char_x;    // [t][b][30]
    const float* word_x;    // [t][b][128]
    __nv_bfloat16* hbuf;    // bf16 ping-pong
    const int* len_char;
    const int* len_word;
    __nv_bfloat16* outc;
    __nv_bfloat16* outw;
};

// per-(dir,mb) barrier over 16 blocks
__device__ __forceinline__ void grid_bar(int gi, unsigned target) {
    __threadfence();
    __syncthreads();
    if (threadIdx.x == 0) {
        if (atomicAdd(&g_arrs[gi], 1u) == 15u) {
            g_arrs[gi] = 0;
            __threadfence();
            g_gens[gi] = target;
        } else {
            while (g_gens[gi] < target) __nanosleep(32);
        }
    }
    __syncthreads();
}

// smem: Ws [64][132] + As [64][132] + Wxs [64][68] + Xs [64][68] (words)
#define REC_SMEM ((64*132*2 + 64*68*2) * 4)   // 102400 B

__global__ void __launch_bounds__(256, 2) k_rec_persist(RP p) {
    extern __shared__ unsigned smu[];
    unsigned* Ws  = smu;                       // [64][132] Whh tile
    unsigned* As  = Ws  + 64 * 132;            // [64][132] h tile
    unsigned* Wxs = As  + 64 * 132;            // [64][68]  Wih tile
    unsigned* Xs  = Wxs + 64 * 68;             // [64][68]  x tile

    int bx = blockIdx.x;
    int dir = bx >> 6, mb = (bx >> 4) & 3, nb = bx & 15;
    int gi = dir * 4 + mb;
    int tid = threadIdx.x;
    int wid = tid >> 5, lane = tid & 31;
    int gid = lane >> 2, tig = lane & 3;
    int wm = (wid & 3) * 16;
    int wnh = wid >> 2;
    int bm = mb * 64;

    int Kx  = (dir < 2) ? 30 : 128;
    int Kxw = (dir < 2) ? 16 : 64;
    const float* Wx = (dir < 2) ? (p.cihp + (size_t)dir * 1024 * 30)
                                : (p.wihp + (size_t)(dir - 2) * 1024 * 128);
    const float* xsrc = (dir < 2) ? p.char_x : p.word_x;

    // load + pack Whh tile [64 cols][256 k]
    const float* W = p.whhp + (size_t)dir * 1024 * 256;
    for (int idx = tid; idx < 64 * 128; idx += 256) {
        int n = idx >> 7, kw = idx & 127;
        float2 v = *(const float2*)&W[(size_t)(nb * 64 + n) * 256 + kw * 2];
        Ws[n * 132 + kw] = pk2(v.x, v.y);
    }
    // load + pack Wih tile [64 cols][Kx k] (zero-padded to Kxw words)
    for (int idx = tid; idx < 64 * Kxw; idx += 256) {
        int n = idx / Kxw, kw = idx % Kxw;
        const float* wr = Wx + (size_t)(nb * 64 + n) * Kx;
        float lo = (kw * 2     < Kx) ? wr[kw * 2]     : 0.f;
        float hi = (kw * 2 + 1 < Kx) ? wr[kw * 2 + 1] : 0.f;
        Wxs[n * 68 + kw] = pk2(lo, hi);
    }

    // bias fragment: col = nb*64 + wnh*32 + jn*8 + tig*2 + c
    const float* bpd = p.bp + dir * 1024 + nb * 64 + wnh * 32;
    float bias_r[4][2];
#pragma unroll
    for (int jn = 0; jn < 4; jn++) {
        bias_r[jn][0] = bpd[jn * 8 + tig * 2];
        bias_r[jn][1] = bpd[jn * 8 + tig * 2 + 1];
    }

    float hreg[2][2], creg[2][2];
#pragma unroll
    for (int i = 0; i < 2; i++)
#pragma unroll
        for (int j = 0; j < 2; j++) { hreg[i][j] = 0.f; creg[i][j] = 0.f; }

    const int* lens = (dir < 2) ? p.len_char : p.len_word;
    int lenv[2];
    lenv[0] = lens[bm + wm + gid];
    lenv[1] = lens[bm + wm + gid + 8];

    __nv_bfloat16* hb0 = p.hbuf + (size_t)dir * 2 * 65536;
    __nv_bfloat16* hb1 = hb0 + 65536;
    __nv_bfloat16* outp = (dir < 2) ? p.outc : p.outw;
    int half = (dir & 1) ? 256 : 0;

    __syncthreads();

    for (int t = 0; t < TT; t++) {
        int tr = (dir & 1) ? (TT - 1 - t) : t;
        const __nv_bfloat16* h = (t & 1) ? hb1 : hb0;
        __nv_bfloat16* hn_buf = (t & 1) ? hb0 : hb1;

        // stage h tile [64 rows][256 k] — pure uint4 copy (already bf16):
        // 64 rows x 32 uint4 slots = 2048, 8/thread
#pragma unroll
        for (int j = 0; j < 8; j++) {
            int q = tid + 256 * j;
            int r = q >> 5, c4 = q & 31;
            uint4 v = __ldcg((const uint4*)&h[(bm + r) * 256 + c4 * 8]);
            *(uint4*)&As[r * 132 + c4 * 4] = v;
        }
        // stage x tile [64 rows][Kx]
        if (Kxw == 64) {
#pragma unroll
            for (int j = 0; j < 8; j++) {
                int q = tid + 256 * j;
                int r = q >> 5, c4 = q & 31;
                float4 v = __ldcg((const float4*)&xsrc[((size_t)tr * BB + bm + r) * 128 + c4 * 4]);
                *(uint2*)&Xs[r * 68 + c4 * 2] = make_uint2(pk2(v.x, v.y), pk2(v.z, v.w));
            }
        } else {
#pragma unroll
            for (int j = 0; j < 4; j++) {
                int q = tid + 256 * j;
                int r = q >> 4, kw = q & 15;
                const float* xr = xsrc + ((size_t)tr * BB + bm + r) * 30;
                float lo = (kw * 2     < 30) ? xr[kw * 2]     : 0.f;
                float hi = (kw * 2 + 1 < 30) ? xr[kw * 2 + 1] : 0.f;
                Xs[r * 68 + kw] = pk2(lo, hi);
            }
        }
        __syncthreads();

        float acc[4][4];
#pragma unroll
        for (int j = 0; j < 4; j++)
#pragma unroll
            for (int v = 0; v < 4; v++) acc[j][v] = 0.f;

        // h @ Whh^T
#pragma unroll
        for (int ks = 0; ks < 16; ks++) {
            int kw = ks * 8;
            unsigned af[4], bf[4][2];
            af[0] = As[(wm + gid) * 132 + kw + tig];
            af[1] = As[(wm + gid + 8) * 132 + kw + tig];
            af[2] = As[(wm + gid) * 132 + kw + tig + 4];
            af[3] = As[(wm + gid + 8) * 132 + kw + tig + 4];
#pragma unroll
            for (int jn = 0; jn < 4; jn++) {
                int n0 = wnh * 32 + jn * 8;
                bf[jn][0] = Ws[(n0 + gid) * 132 + kw + tig];
                bf[jn][1] = Ws[(n0 + gid) * 132 + kw + tig + 4];
            }
#pragma unroll
            for (int jn = 0; jn < 4; jn++)
                mma_bf16(acc[jn], af, bf[jn]);
        }
        // x @ Wih^T (fused input projection)
        int nksx = Kxw >> 3;
#pragma unroll 2
        for (int ks = 0; ks < nksx; ks++) {
            int kw = ks * 8;
            unsigned af[4], bf[4][2];
            af[0] = Xs[(wm + gid) * 68 + kw + tig];
            af[1] = Xs[(wm + gid + 8) * 68 + kw + tig];
            af[2] = Xs[(wm + gid) * 68 + kw + tig + 4];
            af[3] = Xs[(wm + gid + 8) * 68 + kw + tig + 4];
#pragma unroll
            for (int jn = 0; jn < 4; jn++) {
                int n0 = wnh * 32 + jn * 8;
                bf[jn][0] = Wxs[(n0 + gid) * 68 + kw + tig];
                bf[jn][1] = Wxs[(n0 + gid) * 68 + kw + tig + 4];
            }
#pragma unroll
            for (int jn = 0; jn < 4; jn++)
                mma_bf16(acc[jn], af, bf[jn]);
        }

        // fused LSTM cell epilogue (bias folded); h stored as bf16
#pragma unroll
        for (int rh = 0; rh < 2; rh++) {
            int b = bm + wm + gid + rh * 8;
            bool valid = tr < lenv[rh];
#pragma unroll
            for (int pp = 0; pp < 2; pp++) {
                float gi_ = acc[2 * pp + 0][rh * 2 + 0] + bias_r[2 * pp + 0][0];
                float gf = acc[2 * pp + 0][rh * 2 + 1] + bias_r[2 * pp + 0][1];
                float gc = acc[2 * pp + 1][rh * 2 + 0] + bias_r[2 * pp + 1][0];
                float go = acc[2 * pp + 1][rh * 2 + 1] + bias_r[2 * pp + 1][1];
                float cn = sg_(gf) * creg[rh][pp] + sg_(gi_) * tanhf(gc);
                float hv = sg_(go) * tanhf(cn);
                if (valid) { creg[rh][pp] = cn; hreg[rh][pp] = hv; }
                int u = nb * 16 + wnh * 8 + pp * 4 + tig;
                outp[((size_t)b * TT + tr) * 512 + half + u] = __float2bfloat16(valid ? hv : 0.f);
                hn_buf[b * 256 + u] = __float2bfloat16(hreg[rh][pp]);
            }
        }

        if (t + 1 < TT) grid_bar(gi, (unsigned)(t + 1));
    }
}

// ---------------- CRF: real path score (one warp per batch, deterministic) ----------------
__global__ void k_crf_real(const float* __restrict__ logits, const int* __restrict__ tags,
                           const int* __restrict__ lens, const float* __restrict__ trans,
                           float* __restrict__ rl) {
    __shared__ float st[144];
    int tid = threadIdx.x;
    if (tid < 144) st[tid] = trans[tid];
    __syncthreads();
    int warp = tid >> 5, lane = tid & 31;
    int b = blockIdx.x * 8 + warp;
    int len = lens[b];
    float s = 0.f;
    for (int t = lane; t < len; t += 32) {
        int tg = tags[b * TT + t];
        int prev = (t == 0) ? 10 : tags[b * TT + t - 1];
        s += logits[((size_t)b * TT + t) * 12 + tg] + st[prev * 12 + tg];
    }
#pragma unroll
    for (int o = 16; o > 0; o >>= 1) s += __shfl_xor_sync(0xffffffffu, s, o);
    if (lane == 0) {
        int last = tags[b * TT + len - 1];
        rl[b] = s + st[last * 12 + 11];
    }
}

// ---------------- CRF forward: one warp per batch ----------------
__global__ void k_crf_fwd(const float* __restrict__ logits, const int* __restrict__ lens,
                          const float* __restrict__ trans, float* __restrict__ tot) {
    __shared__ float st[144];
    int tid = threadIdx.x;
    if (tid < 144) st[tid] = trans[tid];
    __syncthreads();
    int warp = tid >> 5, lane = tid & 31;
    int b = blockIdx.x * 8 + warp;
    int len = lens[b];
    float alpha = 0.f;
    for (int t = 0; t < TT; t++) {
        float lt = (lane < 12) ? logits[((size_t)b * TT + t) * 12 + lane] : 0.f;
        float sc[12];
        float mx = -1e30f;
#pragma unroll
        for (int i = 0; i < 12; i++) {
            float ai = __shfl_sync(0xffffffffu, alpha, i);
            float s = ai + ((lane < 12) ? st[i * 12 + lane] : 0.f);
            sc[i] = s;
            mx = fmaxf(mx, s);
        }
        float sm = 0.f;
#pragma unroll
        for (int i = 0; i < 12; i++) sm += expf(sc[i] - mx);
        float an = mx + logf(sm) + lt;
        if (t < len) alpha = an;
    }
    float v = (lane < 12) ? alpha + st[lane * 12 + 11] : -1e30f;
    float mx = v;
#pragma unroll
    for (int o = 16; o > 0; o >>= 1) mx = fmaxf(mx, __shfl_xor_sync(0xffffffffu, mx, o));
    float e = expf(v - mx);
#pragma unroll
    for (int o = 16; o > 0; o >>= 1) e += __shfl_xor_sync(0xffffffffu, e, o);
    if (lane == 0) tot[b] = mx + logf(e);
}

__global__ void k_crf_reduce(const float* __restrict__ crf, float* __restrict__ out) {
    __shared__ float s[256];
    int t = threadIdx.x;
    s[t] = crf[t] - crf[256 + t];
    __syncthreads();
    for (int o = 128; o > 0; o >>= 1) {
        if (t < o) s[t] += s[t + o];
        __syncthreads();
    }
    if (t == 0) out[0] = s[0];
}

// ---------------- launch ----------------
extern "C" void kernel_launch(void* const* d_in, const int* in_sizes, int n_in,
                              void* d_out, int out_size) {
    const int*   characters = (const int*)d_in[0];
    const float* words      = (const float*)d_in[1];
    const int*   tags       = (const int*)d_in[2];
    const int*   len_char   = (const int*)d_in[3];
    const int*   len_word   = (const int*)d_in[4];
    const float* char_emb   = (const float*)d_in[5];
    const float* cWihf = (const float*)d_in[6];
    const float* cWhhf = (const float*)d_in[7];
    const float* cbf   = (const float*)d_in[8];
    const float* cWihb = (const float*)d_in[9];
    const float* cWhhb = (const float*)d_in[10];
    const float* cbb   = (const float*)d_in[11];
    const float* clinW = (const float*)d_in[12];
    const float* clinb = (const float*)d_in[13];
    const float* wWihf = (const float*)d_in[14];
    const float* wWhhf = (const float*)d_in[15];
    const float* wbf   = (const float*)d_in[16];
    const float* wWihb = (const float*)d_in[17];
    const float* wWhhb = (const float*)d_in[18];
    const float* wbb   = (const float*)d_in[19];
    const float* wlinW = (const float*)d_in[20];
    const float* wlinb = (const float*)d_in[21];
    const float* l1W   = (const float*)d_in[22];
    const float* l1b   = (const float*)d_in[23];
    const float* l2W   = (const float*)d_in[24];
    const float* l2b   = (const float*)d_in[25];
    const float* tW    = (const float*)d_in[26];
    const float* tb    = (const float*)d_in[27];
    const float* trans = (const float*)d_in[28];
    float* out = (float*)d_out;

    float *char_x, *word_x, *whhp, *cihp, *wihp, *bp, *logits, *crfb;
    __nv_bfloat16 *hbuf, *char_h, *word_h, *xcat, *buf1, *buf2;
    cudaGetSymbolAddress((void**)&char_x, d_char_x);
    cudaGetSymbolAddress((void**)&word_x, d_word_x);
    cudaGetSymbolAddress((void**)&whhp,   d_whhp);
    cudaGetSymbolAddress((void**)&cihp,   d_cihp);
    cudaGetSymbolAddress((void**)&wihp,   d_wihp);
    cudaGetSymbolAddress((void**)&bp,     d_bp);
    cudaGetSymbolAddress((void**)&hbuf,   d_hbuf);
    cudaGetSymbolAddress((void**)&char_h, d_char_h);
    cudaGetSymbolAddress((void**)&word_h, d_word_h);
    cudaGetSymbolAddress((void**)&xcat,   d_xcat);
    cudaGetSymbolAddress((void**)&buf1,   d_buf1);
    cudaGetSymbolAddress((void**)&buf2,   d_buf2);
    cudaGetSymbolAddress((void**)&logits, d_logits);
    cudaGetSymbolAddress((void**)&crfb,   d_crf);

    cudaFuncSetAttribute(k_rec_persist, cudaFuncAttributeMaxDynamicSharedMemorySize, REC_SMEM);

    k_init<<<(4 * 2 * BB * 128 + 255) / 256, 256>>>(hbuf);

    // fused weight/bias permutation (12 ops in one launch)
    PrepP pp;
    pp.whh[0] = cWhhf; pp.whh[1] = cWhhb; pp.whh[2] = wWhhf; pp.whh[3] = wWhhb;
    pp.cih[0] = cWihf; pp.cih[1] = cWihb;
    pp.wih[0] = wWihf; pp.wih[1] = wWihb;
    pp.bias[0] = cbf; pp.bias[1] = cbb; pp.bias[2] = wbf; pp.bias[3] = wbb;
    pp.whhp = whhp; pp.cihp = cihp; pp.wihp = wihp; pp.bp = bp;
    k_prep<<<dim3(1024, 12), 256>>>(pp);

    k_gather_char<<<(TT * BB * 30 + 255) / 256, 256>>>(characters, char_emb, char_x);
    k_transpose_word<<<(TT * BB * 128 + 255) / 256, 256>>>(words, word_x);

    // persistent recurrence with fused input projections
    RP rp;
    rp.whhp = whhp;
    rp.cihp = cihp;
    rp.wihp = wihp;
    rp.bp   = bp;
    rp.char_x = char_x;
    rp.word_x = word_x;
    rp.hbuf = hbuf;
    rp.len_char = len_char;
    rp.len_word = len_word;
    rp.outc = char_h;
    rp.outw = word_h;
    k_rec_persist<<<256, 256, REC_SMEM>>>(rp);

    int Mbt = BB * TT;  // 51200
    auto grid = [](int M, int N) { return dim3((unsigned)((N + 63) / 64), (unsigned)((M + 127) / 128)); };

    // dense stack (bf16 operands, bf16 intermediates, softplus fused)
    k_gemm_tc<<<grid(Mbt, 512), 256>>>(char_h, clinW, clinb, (float*)xcat,         Mbt, 512, 512, 712, 1, 1);
    k_gemm_tc<<<grid(Mbt, 200), 256>>>(word_h, wlinW, wlinb, (float*)(xcat + 512), Mbt, 200, 512, 712, 1, 1);
    k_gemm_tc<<<grid(Mbt, 512), 256>>>(xcat, l1W, l1b, (float*)buf1, Mbt, 512, 712, 512, 1, 1);
    k_gemm_tc<<<grid(Mbt, 256), 256>>>(buf1, l2W, l2b, (float*)buf2, Mbt, 256, 512, 256, 1, 1);
    k_gemm_tc<<<grid(Mbt, 12),  256>>>(buf2, tW,  tb,  logits,       Mbt, 12,  256, 12,  1, 0);

    // CRF
    k_crf_real<<<32, 256>>>(logits, tags, len_char, trans, crfb + BB);
    k_crf_fwd<<<32, 256>>>(logits, len_char, trans, crfb);
    k_crf_reduce<<<1, 256>>>(crfb, out);
}